// round 8
// baseline (speedup 1.0000x reference)
#include <cuda_runtime.h>
#include <cuda_fp16.h>
#include <math.h>
#include <stdint.h>

// Problem constants
constexpr int BATCH   = 32;
constexpr int HDIM    = 56;
constexpr int C_DIM   = 384;
constexpr int NHEADS  = 12;
constexpr int HEADD   = 32;
constexpr int WS      = 7;
constexpr int SHIFT   = 3;
constexpr int NWIN    = 49;
constexpr int M_TOK   = BATCH * HDIM * HDIM;   // 100352
constexpr int MLP_HID = 4 * C_DIM;             // 1536
constexpr int NN      = NWIN * NWIN;           // 2401

constexpr int NSTAGE     = 3;
constexpr int STAGE_B    = 32768;              // A 16KB + B 16KB (fp16, k64)
constexpr int SMEM_BYTES = NSTAGE * STAGE_B;   // 96KB per CTA

// Scratch buffers (device globals: no allocation allowed)
__device__ __align__(256) __half g_ln [(size_t)M_TOK * C_DIM];
__device__ __align__(256) __half g_qkv[(size_t)M_TOK * 3 * C_DIM];
__device__ __align__(256) __half g_o  [(size_t)M_TOK * C_DIM];
__device__ __align__(256) float  g_h  [(size_t)M_TOK * C_DIM];
__device__ __align__(256) __half g_a1 [(size_t)M_TOK * MLP_HID];
// fp16 transposed weights [N][K]
__device__ __align__(256) __half g_bt_qkv [(size_t)3 * C_DIM * C_DIM];
__device__ __align__(256) __half g_bt_proj[(size_t)C_DIM * C_DIM];
__device__ __align__(256) __half g_bt_fc1 [(size_t)MLP_HID * C_DIM];
__device__ __align__(256) __half g_bt_fc2 [(size_t)C_DIM * MLP_HID];
// pre-gathered rel-bias [NHEADS][49*49] fp16
__device__ __align__(256) __half g_biasm[(size_t)NHEADS * NN];

// ---------------------------------------------------------------------------
// asm helpers (base-arch only: cp.async sm80, ldmatrix sm75, mma.sync sm80)
// ---------------------------------------------------------------------------
__device__ __forceinline__ uint32_t smem_u32(const void* p) {
    uint32_t a;
    asm("{ .reg .u64 t; cvta.to.shared.u64 t, %1; cvt.u32.u64 %0, t; }"
        : "=r"(a) : "l"(p));
    return a;
}
__device__ __forceinline__ void cp16(uint32_t dst, const void* src) {
    asm volatile("cp.async.cg.shared.global [%0], [%1], 16;"
                 :: "r"(dst), "l"(src) : "memory");
}
__device__ __forceinline__ void cp_commit() {
    asm volatile("cp.async.commit_group;" ::: "memory");
}
template <int N>
__device__ __forceinline__ void cp_wait() {
    asm volatile("cp.async.wait_group %0;" :: "n"(N) : "memory");
}
__device__ __forceinline__ void ldmx4(uint32_t& r0, uint32_t& r1,
                                      uint32_t& r2, uint32_t& r3, uint32_t addr) {
    asm volatile("ldmatrix.sync.aligned.m8n8.x4.shared.b16 {%0,%1,%2,%3}, [%4];"
                 : "=r"(r0), "=r"(r1), "=r"(r2), "=r"(r3) : "r"(addr));
}
__device__ __forceinline__ void mma16816(float* c, const uint32_t* a,
                                         const uint32_t* b) {
    asm volatile(
        "mma.sync.aligned.m16n8k16.row.col.f32.f16.f16.f32 "
        "{%0,%1,%2,%3}, {%4,%5,%6,%7}, {%8,%9}, {%0,%1,%2,%3};"
        : "+f"(c[0]), "+f"(c[1]), "+f"(c[2]), "+f"(c[3])
        : "r"(a[0]), "r"(a[1]), "r"(a[2]), "r"(a[3]), "r"(b[0]), "r"(b[1]));
}
// smem tile: [128 rows][64 fp16] = 128B rows (8x16B chunks), XOR-8 swizzle
__device__ __forceinline__ uint32_t sa_off(int row, int c4) {
    return (uint32_t)(row * 128 + ((c4 ^ (row & 7)) << 4));
}
__device__ __forceinline__ float gelu(float v) {
    return 0.5f * v * (1.0f + erff(v * 0.70710678118654752f));
}

// ---------------------------------------------------------------------------
// Weight prep: W[K][N] fp32 -> Wt[N][K] fp16, tiled transpose
// ---------------------------------------------------------------------------
__global__ __launch_bounds__(256) void prep_w(const float* __restrict__ W,
                                              __half* __restrict__ Wt,
                                              int K, int N) {
    __shared__ float t[32][33];
    int tx = threadIdx.x & 31, ty = threadIdx.x >> 5;
    int n0 = blockIdx.x * 32, k0 = blockIdx.y * 32;
    #pragma unroll
    for (int i = 0; i < 32; i += 8)
        t[ty + i][tx] = W[(size_t)(k0 + ty + i) * N + n0 + tx];
    __syncthreads();
    #pragma unroll
    for (int i = 0; i < 32; i += 8)
        Wt[(size_t)(n0 + ty + i) * K + k0 + tx] = __float2half_rn(t[tx][ty + i]);
}

// ---------------------------------------------------------------------------
// Bias prep: biasm[h][i*49+j] = table[relidx[i*49+j]*NHEADS + h] (fp16)
// ---------------------------------------------------------------------------
__global__ __launch_bounds__(256) void prep_bias(const float* __restrict__ table,
                                                 const int* __restrict__ relidx,
                                                 __half* __restrict__ bm) {
    int h = blockIdx.x;
    for (int e = threadIdx.x; e < NN; e += 256)
        bm[(size_t)h * NN + e] = __float2half_rn(table[relidx[e] * NHEADS + h]);
}

// ---------------------------------------------------------------------------
// fp16 HMMA GEMM (f32 accumulate): C[M,N] = A[M,K] @ Bt[N,K]^T (+bias/res/gelu)
// 128x128 CTA tile, 128 thr, 4 warps (2x2 -> 64x64 warp tile),
// K-chunk 64, 3-stage cp.async pipeline, 2 CTAs/SM.
// EPI: 0 = +bias -> half ; 1 = +bias+res -> float ; 2 = gelu(+bias) -> half
// ---------------------------------------------------------------------------
template <int EPI>
__global__ __launch_bounds__(128, 2)
void gemm_hmma(const __half* __restrict__ A, const __half* __restrict__ Bt,
               const float* __restrict__ bias, const float* __restrict__ R,
               void* __restrict__ out, int M, int N, int K) {
    extern __shared__ __align__(128) char smem[];
    uint32_t sbase = smem_u32(smem);

    int tid = threadIdx.x, warp = tid >> 5, lane = tid & 31;
    int wm = warp >> 1, wn = warp & 1;
    int m0 = blockIdx.y * 128, n0 = blockIdx.x * 128;
    int NC = K >> 6;

    float acc[4][8][4];
    #pragma unroll
    for (int i = 0; i < 4; i++)
        #pragma unroll
        for (int j = 0; j < 8; j++)
            #pragma unroll
            for (int e = 0; e < 4; e++) acc[i][j][e] = 0.0f;

    auto load_chunk = [&](int kc, int s) {
        uint32_t ast = sbase + s * STAGE_B;
        uint32_t bst = ast + 16384;
        #pragma unroll
        for (int t = 0; t < 8; t++) {
            int seg = tid + t * 128;
            int row = seg >> 3, q = seg & 7;
            cp16(ast + sa_off(row, q),
                 A + (size_t)(m0 + row) * K + kc * 64 + q * 8);
            cp16(bst + sa_off(row, q),
                 Bt + (size_t)(n0 + row) * K + kc * 64 + q * 8);
        }
    };

    #pragma unroll
    for (int c = 0; c < NSTAGE - 1; c++) { load_chunk(c, c); cp_commit(); }

    int s_cur = 0, s_nxt = NSTAGE - 1;
    for (int c = 0; c < NC; c++) {
        cp_wait<NSTAGE - 2>();
        __syncthreads();
        int cn = c + NSTAGE - 1;
        if (cn < NC) load_chunk(cn, s_nxt);
        cp_commit();
        if (++s_nxt == NSTAGE) s_nxt = 0;

        uint32_t ast = sbase + s_cur * STAGE_B;
        uint32_t bst = ast + 16384;
        if (++s_cur == NSTAGE) s_cur = 0;

        #pragma unroll
        for (int kk = 0; kk < 4; kk++) {
            uint32_t a[4][4], b[4][4];
            #pragma unroll
            for (int i = 0; i < 4; i++) {
                int row = wm * 64 + i * 16 + (lane & 15);
                int c4  = kk * 2 + (lane >> 4);
                ldmx4(a[i][0], a[i][1], a[i][2], a[i][3], ast + sa_off(row, c4));
            }
            #pragma unroll
            for (int jp = 0; jp < 4; jp++) {
                int row = wn * 64 + jp * 16 + (lane & 7) + ((lane >> 4) << 3);
                int c4  = kk * 2 + ((lane >> 3) & 1);
                ldmx4(b[jp][0], b[jp][1], b[jp][2], b[jp][3], bst + sa_off(row, c4));
            }
            #pragma unroll
            for (int i = 0; i < 4; i++)
                #pragma unroll
                for (int jp = 0; jp < 4; jp++) {
                    mma16816(acc[i][jp * 2 + 0], a[i], &b[jp][0]);
                    mma16816(acc[i][jp * 2 + 1], a[i], &b[jp][2]);
                }
        }
    }

    // register epilogue
    int rbase = m0 + wm * 64 + (lane >> 2);
    #pragma unroll
    for (int i = 0; i < 4; i++) {
        #pragma unroll
        for (int j = 0; j < 8; j++) {
            int col = n0 + wn * 64 + j * 8 + ((lane & 3) << 1);
            float b0 = bias[col], b1 = bias[col + 1];
            #pragma unroll
            for (int hm = 0; hm < 2; hm++) {
                int row = rbase + i * 16 + hm * 8;
                float v0 = acc[i][j][hm * 2 + 0] + b0;
                float v1 = acc[i][j][hm * 2 + 1] + b1;
                if (EPI == 1) {
                    const float2 r2 = *reinterpret_cast<const float2*>(
                        R + (size_t)row * N + col);
                    v0 += r2.x; v1 += r2.y;
                    *reinterpret_cast<float2*>((float*)out + (size_t)row * N + col)
                        = make_float2(v0, v1);
                } else {
                    if (EPI == 2) { v0 = gelu(v0); v1 = gelu(v1); }
                    *reinterpret_cast<__half2*>((__half*)out + (size_t)row * N + col)
                        = __floats2half2_rn(v0, v1);
                }
            }
        }
    }
}

// ---------------------------------------------------------------------------
// LayerNorm: one warp per token, fp32 in -> fp16 out
// ---------------------------------------------------------------------------
__global__ __launch_bounds__(256) void ln_kernel(const float* __restrict__ x,
                                                 const float* __restrict__ g,
                                                 const float* __restrict__ b,
                                                 __half* __restrict__ y) {
    int warp = threadIdx.x >> 5, lane = threadIdx.x & 31;
    int m = blockIdx.x * 8 + warp;
    const float4* xr = reinterpret_cast<const float4*>(x + (size_t)m * C_DIM);
    float4 v0 = xr[lane], v1 = xr[lane + 32], v2 = xr[lane + 64];

    float s  = v0.x + v0.y + v0.z + v0.w + v1.x + v1.y + v1.z + v1.w
             + v2.x + v2.y + v2.z + v2.w;
    float sq = v0.x*v0.x + v0.y*v0.y + v0.z*v0.z + v0.w*v0.w
             + v1.x*v1.x + v1.y*v1.y + v1.z*v1.z + v1.w*v1.w
             + v2.x*v2.x + v2.y*v2.y + v2.z*v2.z + v2.w*v2.w;
    #pragma unroll
    for (int o = 16; o; o >>= 1) {
        s  += __shfl_xor_sync(0xffffffffu, s,  o);
        sq += __shfl_xor_sync(0xffffffffu, sq, o);
    }
    float mean = s * (1.0f / 384.0f);
    float var  = sq * (1.0f / 384.0f) - mean * mean;
    float rstd = rsqrtf(var + 1e-5f);

    const float4* gr = reinterpret_cast<const float4*>(g);
    const float4* br = reinterpret_cast<const float4*>(b);
    __half2* yr = reinterpret_cast<__half2*>(y + (size_t)m * C_DIM);
    #pragma unroll
    for (int t = 0; t < 3; t++) {
        int p = lane + 32 * t;
        float4 xv = (t == 0) ? v0 : (t == 1) ? v1 : v2;
        float4 gv = gr[p], bv = br[p];
        yr[p * 2 + 0] = __floats2half2_rn((xv.x - mean) * rstd * gv.x + bv.x,
                                          (xv.y - mean) * rstd * gv.y + bv.y);
        yr[p * 2 + 1] = __floats2half2_rn((xv.z - mean) * rstd * gv.z + bv.z,
                                          (xv.w - mean) * rstd * gv.w + bv.w);
    }
}

// ---------------------------------------------------------------------------
// Windowed shifted attention: one block per (head, window); fp16 I/O.
// Q,K half2 smem (80B stride, conflict-free LDS.128), QK via HFMA2.
// Rel-bias from pre-gathered fp16 matrix (coalesced preload to smem).
// ---------------------------------------------------------------------------
__global__ __launch_bounds__(256) void attn_kernel(const __half* __restrict__ qkv,
                                                   const __half* __restrict__ biasm,
                                                   __half* __restrict__ o) {
    __shared__ __align__(16) __half2 q2[NWIN][40], k2[NWIN][40];
    __shared__ __align__(16) float vs[NWIN][36];
    __shared__ float ss[NWIN][52];
    __shared__ __align__(16) __half sb[NN + 16];
    __shared__ int   sidx[NWIN];

    int head = blockIdx.x;
    int w    = blockIdx.y;
    int tid  = threadIdx.x, warp = tid >> 5, lane = tid & 31;

    int b  = w >> 6;
    int wr = w & 63;
    int wi = wr >> 3, wj = wr & 7;

    if (tid < NWIN) {
        int i = tid / 7, j = tid - 7 * (tid / 7);
        int rr = wi * 7 + i + SHIFT; if (rr >= HDIM) rr -= HDIM;
        int cc = wj * 7 + j + SHIFT; if (cc >= HDIM) cc -= HDIM;
        sidx[tid] = b * (HDIM * HDIM) + rr * HDIM + cc;
    }
    // bias preload, coalesced
    {
        const __half* src = biasm + (size_t)head * NN;
        for (int e = tid; e < NN; e += 256) sb[e] = src[e];
    }
    __syncthreads();

    for (int idx = tid; idx < NWIN * 4; idx += 256) {
        int r = idx >> 2, c = idx & 3;
        const uint4* base = reinterpret_cast<const uint4*>(
            qkv + (size_t)sidx[r] * (3 * C_DIM) + head * HEADD);
        reinterpret_cast<uint4*>(&q2[r][0])[c] = base[c];
        reinterpret_cast<uint4*>(&k2[r][0])[c] = base[c + C_DIM / 8];
        uint4 vv = base[c + 2 * C_DIM / 8];
        const __half2* vh = reinterpret_cast<const __half2*>(&vv);
        float2 f0 = __half22float2(vh[0]), f1 = __half22float2(vh[1]);
        float2 f2 = __half22float2(vh[2]), f3 = __half22float2(vh[3]);
        float* vd = &vs[r][c * 8];
        vd[0] = f0.x; vd[1] = f0.y; vd[2] = f1.x; vd[3] = f1.y;
        vd[4] = f2.x; vd[5] = f2.y; vd[6] = f3.x; vd[7] = f3.y;
    }
    __syncthreads();

    const float scale = 0.17677669529663687f;
    for (int e = tid; e < NN; e += 256) {
        int i = e / NWIN, j = e - i * NWIN;
        const uint4* qq = reinterpret_cast<const uint4*>(&q2[i][0]);
        const uint4* kk = reinterpret_cast<const uint4*>(&k2[j][0]);
        __half2 a0 = __float2half2_rn(0.f), a1 = a0, a2 = a0, a3 = a0;
        #pragma unroll
        for (int t = 0; t < 4; t++) {
            uint4 qa = qq[t], kb = kk[t];
            const __half2* qh = reinterpret_cast<const __half2*>(&qa);
            const __half2* kh = reinterpret_cast<const __half2*>(&kb);
            a0 = __hfma2(qh[0], kh[0], a0);
            a1 = __hfma2(qh[1], kh[1], a1);
            a2 = __hfma2(qh[2], kh[2], a2);
            a3 = __hfma2(qh[3], kh[3], a3);
        }
        float2 f0 = __half22float2(a0), f1 = __half22float2(a1);
        float2 f2 = __half22float2(a2), f3 = __half22float2(a3);
        float s = (f0.x + f0.y) + (f1.x + f1.y) + (f2.x + f2.y) + (f3.x + f3.y);
        ss[i][j] = s * scale + __half2float(sb[e]);
    }
    __syncthreads();

    for (int i = warp; i < NWIN; i += 8) {
        float mx = -1e30f;
        for (int j = lane; j < NWIN; j += 32) mx = fmaxf(mx, ss[i][j]);
        #pragma unroll
        for (int off = 16; off; off >>= 1)
            mx = fmaxf(mx, __shfl_xor_sync(0xffffffffu, mx, off));
        float sum = 0.0f;
        for (int j = lane; j < NWIN; j += 32) {
            float p = __expf(ss[i][j] - mx);
            ss[i][j] = p;
            sum += p;
        }
        #pragma unroll
        for (int off = 16; off; off >>= 1)
            sum += __shfl_xor_sync(0xffffffffu, sum, off);
        float inv = 1.0f / sum;
        for (int j = lane; j < NWIN; j += 32) ss[i][j] *= inv;
    }
    __syncthreads();

    for (int e = tid; e < NWIN * 8; e += 256) {
        int i = e >> 3, dq = e & 7;
        float ax = 0.f, ay = 0.f, az = 0.f, aw = 0.f;
        #pragma unroll 7
        for (int j = 0; j < NWIN; j++) {
            float p = ss[i][j];
            float4 v = *reinterpret_cast<const float4*>(&vs[j][dq * 4]);
            ax += p * v.x; ay += p * v.y; az += p * v.z; aw += p * v.w;
        }
        __half2 h0 = __floats2half2_rn(ax, ay);
        __half2 h1 = __floats2half2_rn(az, aw);
        uint2 pk = make_uint2(*reinterpret_cast<uint32_t*>(&h0),
                              *reinterpret_cast<uint32_t*>(&h1));
        *reinterpret_cast<uint2*>(o + (size_t)sidx[i] * C_DIM + head * HEADD + dq * 4)
            = pk;
    }
}

// ---------------------------------------------------------------------------
extern "C" void kernel_launch(void* const* d_in, const int* in_sizes, int n_in,
                              void* d_out, int out_size) {
    const float* x      = (const float*)d_in[0];
    const float* n1g    = (const float*)d_in[1];
    const float* n1b    = (const float*)d_in[2];
    const float* qkvw   = (const float*)d_in[3];
    const float* qkvb   = (const float*)d_in[4];
    const float* projw  = (const float*)d_in[5];
    const float* projb  = (const float*)d_in[6];
    const float* table  = (const float*)d_in[7];
    const float* n2g    = (const float*)d_in[8];
    const float* n2b    = (const float*)d_in[9];
    const float* fc1w   = (const float*)d_in[10];
    const float* fc1b   = (const float*)d_in[11];
    const float* fc2w   = (const float*)d_in[12];
    const float* fc2b   = (const float*)d_in[13];
    const int*   relidx = (const int*)d_in[14];
    float* out = (float*)d_out;

    __half *ln, *qkv, *o, *a1, *btq, *btp, *bt1, *bt2, *bm;
    float *h;
    cudaGetSymbolAddress((void**)&ln,  g_ln);
    cudaGetSymbolAddress((void**)&qkv, g_qkv);
    cudaGetSymbolAddress((void**)&o,   g_o);
    cudaGetSymbolAddress((void**)&h,   g_h);
    cudaGetSymbolAddress((void**)&a1,  g_a1);
    cudaGetSymbolAddress((void**)&btq, g_bt_qkv);
    cudaGetSymbolAddress((void**)&btp, g_bt_proj);
    cudaGetSymbolAddress((void**)&bt1, g_bt_fc1);
    cudaGetSymbolAddress((void**)&bt2, g_bt_fc2);
    cudaGetSymbolAddress((void**)&bm,  g_biasm);

    cudaFuncSetAttribute(gemm_hmma<0>, cudaFuncAttributeMaxDynamicSharedMemorySize, SMEM_BYTES);
    cudaFuncSetAttribute(gemm_hmma<1>, cudaFuncAttributeMaxDynamicSharedMemorySize, SMEM_BYTES);
    cudaFuncSetAttribute(gemm_hmma<2>, cudaFuncAttributeMaxDynamicSharedMemorySize, SMEM_BYTES);

    // Launch order arranged so profiled launch (global idx 2) is the QKV GEMM.
    // 0) weight prep for qkv
    prep_w<<<dim3(3 * C_DIM / 32, C_DIM / 32), 256>>>(qkvw, btq, C_DIM, 3 * C_DIM);
    // 1) LN1
    ln_kernel<<<M_TOK / 8, 256>>>(x, n1g, n1b, ln);
    // 2) qkv GEMM  <-- profiled
    gemm_hmma<0><<<dim3(3 * C_DIM / 128, M_TOK / 128), 128, SMEM_BYTES>>>(
        ln, btq, qkvb, nullptr, qkv, M_TOK, 3 * C_DIM, C_DIM);
    // 3) bias prep
    prep_bias<<<NHEADS, 256>>>(table, relidx, bm);
    // 4) attention
    attn_kernel<<<dim3(NHEADS, 2048), 256>>>(qkv, bm, o);
    // 5) proj weight prep
    prep_w<<<dim3(C_DIM / 32, C_DIM / 32), 256>>>(projw, btp, C_DIM, C_DIM);
    // 6) h = x + proj(o)
    gemm_hmma<1><<<dim3(C_DIM / 128, M_TOK / 128), 128, SMEM_BYTES>>>(
        o, btp, projb, x, h, M_TOK, C_DIM, C_DIM);
    // 7) LN2
    ln_kernel<<<M_TOK / 8, 256>>>(h, n2g, n2b, ln);
    // 8) fc1 weight prep
    prep_w<<<dim3(MLP_HID / 32, C_DIM / 32), 256>>>(fc1w, bt1, C_DIM, MLP_HID);
    // 9) a1 = gelu(fc1(ln))
    gemm_hmma<2><<<dim3(MLP_HID / 128, M_TOK / 128), 128, SMEM_BYTES>>>(
        ln, bt1, fc1b, nullptr, a1, M_TOK, MLP_HID, C_DIM);
    // 10) fc2 weight prep
    prep_w<<<dim3(C_DIM / 32, MLP_HID / 32), 256>>>(fc2w, bt2, MLP_HID, C_DIM);
    // 11) out = h + fc2(a1)
    gemm_hmma<1><<<dim3(C_DIM / 128, M_TOK / 128), 128, SMEM_BYTES>>>(
        a1, bt2, fc2b, h, out, M_TOK, C_DIM, MLP_HID);
}

// round 9
// speedup vs baseline: 1.0229x; 1.0229x over previous
#include <cuda_runtime.h>
#include <cuda_fp16.h>
#include <math.h>
#include <stdint.h>

// Problem constants
constexpr int BATCH   = 32;
constexpr int HDIM    = 56;
constexpr int C_DIM   = 384;
constexpr int NHEADS  = 12;
constexpr int HEADD   = 32;
constexpr int WS      = 7;
constexpr int SHIFT   = 3;
constexpr int NWIN    = 49;
constexpr int M_TOK   = BATCH * HDIM * HDIM;   // 100352
constexpr int MLP_HID = 4 * C_DIM;             // 1536
constexpr int NN      = NWIN * NWIN;           // 2401

constexpr int NSTAGE     = 3;
constexpr int STAGE_B    = 32768;              // A 16KB + B 16KB (fp16, k64)
constexpr int SMEM_BYTES = NSTAGE * STAGE_B;   // 96KB per CTA

// Scratch buffers (device globals: no allocation allowed)
__device__ __align__(256) __half g_ln [(size_t)M_TOK * C_DIM];
__device__ __align__(256) __half g_qkv[(size_t)M_TOK * 3 * C_DIM];
__device__ __align__(256) __half g_o  [(size_t)M_TOK * C_DIM];
__device__ __align__(256) float  g_h  [(size_t)M_TOK * C_DIM];
__device__ __align__(256) __half g_a1 [(size_t)M_TOK * MLP_HID];
// fp16 transposed weights [N][K]
__device__ __align__(256) __half g_bt_qkv [(size_t)3 * C_DIM * C_DIM];
__device__ __align__(256) __half g_bt_proj[(size_t)C_DIM * C_DIM];
__device__ __align__(256) __half g_bt_fc1 [(size_t)MLP_HID * C_DIM];
__device__ __align__(256) __half g_bt_fc2 [(size_t)C_DIM * MLP_HID];
// pre-gathered rel-bias [NHEADS][49*49] fp16
__device__ __align__(256) __half g_biasm[(size_t)NHEADS * NN];

// ---------------------------------------------------------------------------
// asm helpers (base-arch only: cp.async sm80, ldmatrix sm75, mma.sync sm80)
// ---------------------------------------------------------------------------
__device__ __forceinline__ uint32_t smem_u32(const void* p) {
    uint32_t a;
    asm("{ .reg .u64 t; cvta.to.shared.u64 t, %1; cvt.u32.u64 %0, t; }"
        : "=r"(a) : "l"(p));
    return a;
}
__device__ __forceinline__ void cp16(uint32_t dst, const void* src) {
    asm volatile("cp.async.cg.shared.global [%0], [%1], 16;"
                 :: "r"(dst), "l"(src) : "memory");
}
__device__ __forceinline__ void cp_commit() {
    asm volatile("cp.async.commit_group;" ::: "memory");
}
template <int N>
__device__ __forceinline__ void cp_wait() {
    asm volatile("cp.async.wait_group %0;" :: "n"(N) : "memory");
}
__device__ __forceinline__ void ldmx4(uint32_t& r0, uint32_t& r1,
                                      uint32_t& r2, uint32_t& r3, uint32_t addr) {
    asm volatile("ldmatrix.sync.aligned.m8n8.x4.shared.b16 {%0,%1,%2,%3}, [%4];"
                 : "=r"(r0), "=r"(r1), "=r"(r2), "=r"(r3) : "r"(addr));
}
__device__ __forceinline__ void mma16816(float* c, const uint32_t* a,
                                         const uint32_t* b) {
    asm volatile(
        "mma.sync.aligned.m16n8k16.row.col.f32.f16.f16.f32 "
        "{%0,%1,%2,%3}, {%4,%5,%6,%7}, {%8,%9}, {%0,%1,%2,%3};"
        : "+f"(c[0]), "+f"(c[1]), "+f"(c[2]), "+f"(c[3])
        : "r"(a[0]), "r"(a[1]), "r"(a[2]), "r"(a[3]), "r"(b[0]), "r"(b[1]));
}
// smem tile: [128 rows][64 fp16] = 128B rows (8x16B chunks), XOR-8 swizzle
__device__ __forceinline__ uint32_t sa_off(int row, int c4) {
    return (uint32_t)(row * 128 + ((c4 ^ (row & 7)) << 4));
}
__device__ __forceinline__ float gelu(float v) {
    return 0.5f * v * (1.0f + erff(v * 0.70710678118654752f));
}

// ---------------------------------------------------------------------------
// Weight prep: W[K][N] fp32 -> Wt[N][K] fp16, tiled transpose
// ---------------------------------------------------------------------------
__global__ __launch_bounds__(256) void prep_w(const float* __restrict__ W,
                                              __half* __restrict__ Wt,
                                              int K, int N) {
    __shared__ float t[32][33];
    int tx = threadIdx.x & 31, ty = threadIdx.x >> 5;
    int n0 = blockIdx.x * 32, k0 = blockIdx.y * 32;
    #pragma unroll
    for (int i = 0; i < 32; i += 8)
        t[ty + i][tx] = W[(size_t)(k0 + ty + i) * N + n0 + tx];
    __syncthreads();
    #pragma unroll
    for (int i = 0; i < 32; i += 8)
        Wt[(size_t)(n0 + ty + i) * K + k0 + tx] = __float2half_rn(t[tx][ty + i]);
}

// ---------------------------------------------------------------------------
// Bias prep: biasm[h][i*49+j] = table[relidx[i*49+j]*NHEADS + h] (fp16)
// ---------------------------------------------------------------------------
__global__ __launch_bounds__(256) void prep_bias(const float* __restrict__ table,
                                                 const int* __restrict__ relidx,
                                                 __half* __restrict__ bm) {
    int h = blockIdx.x;
    for (int e = threadIdx.x; e < NN; e += 256)
        bm[(size_t)h * NN + e] = __float2half_rn(table[relidx[e] * NHEADS + h]);
}

// ---------------------------------------------------------------------------
// fp16 HMMA GEMM (f32 accumulate): C[M,N] = A[M,K] @ Bt[N,K]^T (+bias/res/gelu)
// 128x128 CTA tile, 128 thr, 4 warps (2x2 -> 64x64 warp tile),
// K-chunk 64, 3-stage cp.async pipeline, 2 CTAs/SM.
// EPI: 0 = +bias -> half ; 1 = +bias+res -> float ; 2 = gelu(+bias) -> half
// ---------------------------------------------------------------------------
template <int EPI>
__global__ __launch_bounds__(128, 2)
void gemm_hmma(const __half* __restrict__ A, const __half* __restrict__ Bt,
               const float* __restrict__ bias, const float* __restrict__ R,
               void* __restrict__ out, int M, int N, int K) {
    extern __shared__ __align__(128) char smem[];
    uint32_t sbase = smem_u32(smem);

    int tid = threadIdx.x, warp = tid >> 5, lane = tid & 31;
    int wm = warp >> 1, wn = warp & 1;
    int m0 = blockIdx.y * 128, n0 = blockIdx.x * 128;
    int NC = K >> 6;

    float acc[4][8][4];
    #pragma unroll
    for (int i = 0; i < 4; i++)
        #pragma unroll
        for (int j = 0; j < 8; j++)
            #pragma unroll
            for (int e = 0; e < 4; e++) acc[i][j][e] = 0.0f;

    auto load_chunk = [&](int kc, int s) {
        uint32_t ast = sbase + s * STAGE_B;
        uint32_t bst = ast + 16384;
        #pragma unroll
        for (int t = 0; t < 8; t++) {
            int seg = tid + t * 128;
            int row = seg >> 3, q = seg & 7;
            cp16(ast + sa_off(row, q),
                 A + (size_t)(m0 + row) * K + kc * 64 + q * 8);
            cp16(bst + sa_off(row, q),
                 Bt + (size_t)(n0 + row) * K + kc * 64 + q * 8);
        }
    };

    #pragma unroll
    for (int c = 0; c < NSTAGE - 1; c++) { load_chunk(c, c); cp_commit(); }

    int s_cur = 0, s_nxt = NSTAGE - 1;
    for (int c = 0; c < NC; c++) {
        cp_wait<NSTAGE - 2>();
        __syncthreads();
        int cn = c + NSTAGE - 1;
        if (cn < NC) load_chunk(cn, s_nxt);
        cp_commit();
        if (++s_nxt == NSTAGE) s_nxt = 0;

        uint32_t ast = sbase + s_cur * STAGE_B;
        uint32_t bst = ast + 16384;
        if (++s_cur == NSTAGE) s_cur = 0;

        #pragma unroll
        for (int kk = 0; kk < 4; kk++) {
            uint32_t a[4][4], b[4][4];
            #pragma unroll
            for (int i = 0; i < 4; i++) {
                int row = wm * 64 + i * 16 + (lane & 15);
                int c4  = kk * 2 + (lane >> 4);
                ldmx4(a[i][0], a[i][1], a[i][2], a[i][3], ast + sa_off(row, c4));
            }
            #pragma unroll
            for (int jp = 0; jp < 4; jp++) {
                int row = wn * 64 + jp * 16 + (lane & 7) + ((lane >> 4) << 3);
                int c4  = kk * 2 + ((lane >> 3) & 1);
                ldmx4(b[jp][0], b[jp][1], b[jp][2], b[jp][3], bst + sa_off(row, c4));
            }
            #pragma unroll
            for (int i = 0; i < 4; i++)
                #pragma unroll
                for (int jp = 0; jp < 4; jp++) {
                    mma16816(acc[i][jp * 2 + 0], a[i], &b[jp][0]);
                    mma16816(acc[i][jp * 2 + 1], a[i], &b[jp][2]);
                }
        }
    }

    // register epilogue
    int rbase = m0 + wm * 64 + (lane >> 2);
    #pragma unroll
    for (int i = 0; i < 4; i++) {
        #pragma unroll
        for (int j = 0; j < 8; j++) {
            int col = n0 + wn * 64 + j * 8 + ((lane & 3) << 1);
            float b0 = bias[col], b1 = bias[col + 1];
            #pragma unroll
            for (int hm = 0; hm < 2; hm++) {
                int row = rbase + i * 16 + hm * 8;
                float v0 = acc[i][j][hm * 2 + 0] + b0;
                float v1 = acc[i][j][hm * 2 + 1] + b1;
                if (EPI == 1) {
                    const float2 r2 = *reinterpret_cast<const float2*>(
                        R + (size_t)row * N + col);
                    v0 += r2.x; v1 += r2.y;
                    *reinterpret_cast<float2*>((float*)out + (size_t)row * N + col)
                        = make_float2(v0, v1);
                } else {
                    if (EPI == 2) { v0 = gelu(v0); v1 = gelu(v1); }
                    *reinterpret_cast<__half2*>((__half*)out + (size_t)row * N + col)
                        = __floats2half2_rn(v0, v1);
                }
            }
        }
    }
}

// ---------------------------------------------------------------------------
// LayerNorm: one warp per token, fp32 in -> fp16 out
// ---------------------------------------------------------------------------
__global__ __launch_bounds__(256) void ln_kernel(const float* __restrict__ x,
                                                 const float* __restrict__ g,
                                                 const float* __restrict__ b,
                                                 __half* __restrict__ y) {
    int warp = threadIdx.x >> 5, lane = threadIdx.x & 31;
    int m = blockIdx.x * 8 + warp;
    const float4* xr = reinterpret_cast<const float4*>(x + (size_t)m * C_DIM);
    float4 v0 = xr[lane], v1 = xr[lane + 32], v2 = xr[lane + 64];

    float s  = v0.x + v0.y + v0.z + v0.w + v1.x + v1.y + v1.z + v1.w
             + v2.x + v2.y + v2.z + v2.w;
    float sq = v0.x*v0.x + v0.y*v0.y + v0.z*v0.z + v0.w*v0.w
             + v1.x*v1.x + v1.y*v1.y + v1.z*v1.z + v1.w*v1.w
             + v2.x*v2.x + v2.y*v2.y + v2.z*v2.z + v2.w*v2.w;
    #pragma unroll
    for (int o = 16; o; o >>= 1) {
        s  += __shfl_xor_sync(0xffffffffu, s,  o);
        sq += __shfl_xor_sync(0xffffffffu, sq, o);
    }
    float mean = s * (1.0f / 384.0f);
    float var  = sq * (1.0f / 384.0f) - mean * mean;
    float rstd = rsqrtf(var + 1e-5f);

    const float4* gr = reinterpret_cast<const float4*>(g);
    const float4* br = reinterpret_cast<const float4*>(b);
    __half2* yr = reinterpret_cast<__half2*>(y + (size_t)m * C_DIM);
    #pragma unroll
    for (int t = 0; t < 3; t++) {
        int p = lane + 32 * t;
        float4 xv = (t == 0) ? v0 : (t == 1) ? v1 : v2;
        float4 gv = gr[p], bv = br[p];
        yr[p * 2 + 0] = __floats2half2_rn((xv.x - mean) * rstd * gv.x + bv.x,
                                          (xv.y - mean) * rstd * gv.y + bv.y);
        yr[p * 2 + 1] = __floats2half2_rn((xv.z - mean) * rstd * gv.z + bv.z,
                                          (xv.w - mean) * rstd * gv.w + bv.w);
    }
}

// ---------------------------------------------------------------------------
// Windowed shifted attention: one block per (head, window); fp16 I/O.
// Q,K half2 smem (80B stride, conflict-free LDS.128), QK via HFMA2.
// Rel-bias from pre-gathered fp16 matrix (coalesced preload to smem).
// ---------------------------------------------------------------------------
__global__ __launch_bounds__(256) void attn_kernel(const __half* __restrict__ qkv,
                                                   const __half* __restrict__ biasm,
                                                   __half* __restrict__ o) {
    __shared__ __align__(16) __half2 q2[NWIN][40], k2[NWIN][40];
    __shared__ __align__(16) float vs[NWIN][36];
    __shared__ float ss[NWIN][52];
    __shared__ __align__(16) __half sb[NN + 16];
    __shared__ int   sidx[NWIN];

    int head = blockIdx.x;
    int w    = blockIdx.y;
    int tid  = threadIdx.x, warp = tid >> 5, lane = tid & 31;

    int b  = w >> 6;
    int wr = w & 63;
    int wi = wr >> 3, wj = wr & 7;

    if (tid < NWIN) {
        int i = tid / 7, j = tid - 7 * (tid / 7);
        int rr = wi * 7 + i + SHIFT; if (rr >= HDIM) rr -= HDIM;
        int cc = wj * 7 + j + SHIFT; if (cc >= HDIM) cc -= HDIM;
        sidx[tid] = b * (HDIM * HDIM) + rr * HDIM + cc;
    }
    // bias preload, coalesced
    {
        const __half* src = biasm + (size_t)head * NN;
        for (int e = tid; e < NN; e += 256) sb[e] = src[e];
    }
    __syncthreads();

    for (int idx = tid; idx < NWIN * 4; idx += 256) {
        int r = idx >> 2, c = idx & 3;
        const uint4* base = reinterpret_cast<const uint4*>(
            qkv + (size_t)sidx[r] * (3 * C_DIM) + head * HEADD);
        reinterpret_cast<uint4*>(&q2[r][0])[c] = base[c];
        reinterpret_cast<uint4*>(&k2[r][0])[c] = base[c + C_DIM / 8];
        uint4 vv = base[c + 2 * C_DIM / 8];
        const __half2* vh = reinterpret_cast<const __half2*>(&vv);
        float2 f0 = __half22float2(vh[0]), f1 = __half22float2(vh[1]);
        float2 f2 = __half22float2(vh[2]), f3 = __half22float2(vh[3]);
        float* vd = &vs[r][c * 8];
        vd[0] = f0.x; vd[1] = f0.y; vd[2] = f1.x; vd[3] = f1.y;
        vd[4] = f2.x; vd[5] = f2.y; vd[6] = f3.x; vd[7] = f3.y;
    }
    __syncthreads();

    const float scale = 0.17677669529663687f;
    for (int e = tid; e < NN; e += 256) {
        int i = e / NWIN, j = e - i * NWIN;
        const uint4* qq = reinterpret_cast<const uint4*>(&q2[i][0]);
        const uint4* kk = reinterpret_cast<const uint4*>(&k2[j][0]);
        __half2 a0 = __float2half2_rn(0.f), a1 = a0, a2 = a0, a3 = a0;
        #pragma unroll
        for (int t = 0; t < 4; t++) {
            uint4 qa = qq[t], kb = kk[t];
            const __half2* qh = reinterpret_cast<const __half2*>(&qa);
            const __half2* kh = reinterpret_cast<const __half2*>(&kb);
            a0 = __hfma2(qh[0], kh[0], a0);
            a1 = __hfma2(qh[1], kh[1], a1);
            a2 = __hfma2(qh[2], kh[2], a2);
            a3 = __hfma2(qh[3], kh[3], a3);
        }
        float2 f0 = __half22float2(a0), f1 = __half22float2(a1);
        float2 f2 = __half22float2(a2), f3 = __half22float2(a3);
        float s = (f0.x + f0.y) + (f1.x + f1.y) + (f2.x + f2.y) + (f3.x + f3.y);
        ss[i][j] = s * scale + __half2float(sb[e]);
    }
    __syncthreads();

    for (int i = warp; i < NWIN; i += 8) {
        float mx = -1e30f;
        for (int j = lane; j < NWIN; j += 32) mx = fmaxf(mx, ss[i][j]);
        #pragma unroll
        for (int off = 16; off; off >>= 1)
            mx = fmaxf(mx, __shfl_xor_sync(0xffffffffu, mx, off));
        float sum = 0.0f;
        for (int j = lane; j < NWIN; j += 32) {
            float p = __expf(ss[i][j] - mx);
            ss[i][j] = p;
            sum += p;
        }
        #pragma unroll
        for (int off = 16; off; off >>= 1)
            sum += __shfl_xor_sync(0xffffffffu, sum, off);
        float inv = 1.0f / sum;
        for (int j = lane; j < NWIN; j += 32) ss[i][j] *= inv;
    }
    __syncthreads();

    for (int e = tid; e < NWIN * 8; e += 256) {
        int i = e >> 3, dq = e & 7;
        float ax = 0.f, ay = 0.f, az = 0.f, aw = 0.f;
        #pragma unroll 7
        for (int j = 0; j < NWIN; j++) {
            float p = ss[i][j];
            float4 v = *reinterpret_cast<const float4*>(&vs[j][dq * 4]);
            ax += p * v.x; ay += p * v.y; az += p * v.z; aw += p * v.w;
        }
        __half2 h0 = __floats2half2_rn(ax, ay);
        __half2 h1 = __floats2half2_rn(az, aw);
        uint2 pk = make_uint2(*reinterpret_cast<uint32_t*>(&h0),
                              *reinterpret_cast<uint32_t*>(&h1));
        *reinterpret_cast<uint2*>(o + (size_t)sidx[i] * C_DIM + head * HEADD + dq * 4)
            = pk;
    }
}

// ---------------------------------------------------------------------------
extern "C" void kernel_launch(void* const* d_in, const int* in_sizes, int n_in,
                              void* d_out, int out_size) {
    const float* x      = (const float*)d_in[0];
    const float* n1g    = (const float*)d_in[1];
    const float* n1b    = (const float*)d_in[2];
    const float* qkvw   = (const float*)d_in[3];
    const float* qkvb   = (const float*)d_in[4];
    const float* projw  = (const float*)d_in[5];
    const float* projb  = (const float*)d_in[6];
    const float* table  = (const float*)d_in[7];
    const float* n2g    = (const float*)d_in[8];
    const float* n2b    = (const float*)d_in[9];
    const float* fc1w   = (const float*)d_in[10];
    const float* fc1b   = (const float*)d_in[11];
    const float* fc2w   = (const float*)d_in[12];
    const float* fc2b   = (const float*)d_in[13];
    const int*   relidx = (const int*)d_in[14];
    float* out = (float*)d_out;

    __half *ln, *qkv, *o, *a1, *btq, *btp, *bt1, *bt2, *bm;
    float *h;
    cudaGetSymbolAddress((void**)&ln,  g_ln);
    cudaGetSymbolAddress((void**)&qkv, g_qkv);
    cudaGetSymbolAddress((void**)&o,   g_o);
    cudaGetSymbolAddress((void**)&h,   g_h);
    cudaGetSymbolAddress((void**)&a1,  g_a1);
    cudaGetSymbolAddress((void**)&btq, g_bt_qkv);
    cudaGetSymbolAddress((void**)&btp, g_bt_proj);
    cudaGetSymbolAddress((void**)&bt1, g_bt_fc1);
    cudaGetSymbolAddress((void**)&bt2, g_bt_fc2);
    cudaGetSymbolAddress((void**)&bm,  g_biasm);

    cudaFuncSetAttribute(gemm_hmma<0>, cudaFuncAttributeMaxDynamicSharedMemorySize, SMEM_BYTES);
    cudaFuncSetAttribute(gemm_hmma<1>, cudaFuncAttributeMaxDynamicSharedMemorySize, SMEM_BYTES);
    cudaFuncSetAttribute(gemm_hmma<2>, cudaFuncAttributeMaxDynamicSharedMemorySize, SMEM_BYTES);

    // Launch order arranged so profiled launch (global idx 2) is the QKV GEMM.
    // 0) weight prep for qkv
    prep_w<<<dim3(3 * C_DIM / 32, C_DIM / 32), 256>>>(qkvw, btq, C_DIM, 3 * C_DIM);
    // 1) LN1
    ln_kernel<<<M_TOK / 8, 256>>>(x, n1g, n1b, ln);
    // 2) qkv GEMM  <-- profiled
    gemm_hmma<0><<<dim3(3 * C_DIM / 128, M_TOK / 128), 128, SMEM_BYTES>>>(
        ln, btq, qkvb, nullptr, qkv, M_TOK, 3 * C_DIM, C_DIM);
    // 3) bias prep
    prep_bias<<<NHEADS, 256>>>(table, relidx, bm);
    // 4) attention
    attn_kernel<<<dim3(NHEADS, 2048), 256>>>(qkv, bm, o);
    // 5) proj weight prep
    prep_w<<<dim3(C_DIM / 32, C_DIM / 32), 256>>>(projw, btp, C_DIM, C_DIM);
    // 6) h = x + proj(o)
    gemm_hmma<1><<<dim3(C_DIM / 128, M_TOK / 128), 128, SMEM_BYTES>>>(
        o, btp, projb, x, h, M_TOK, C_DIM, C_DIM);
    // 7) LN2
    ln_kernel<<<M_TOK / 8, 256>>>(h, n2g, n2b, ln);
    // 8) fc1 weight prep
    prep_w<<<dim3(MLP_HID / 32, C_DIM / 32), 256>>>(fc1w, bt1, C_DIM, MLP_HID);
    // 9) a1 = gelu(fc1(ln))
    gemm_hmma<2><<<dim3(MLP_HID / 128, M_TOK / 128), 128, SMEM_BYTES>>>(
        ln, bt1, fc1b, nullptr, a1, M_TOK, MLP_HID, C_DIM);
    // 10) fc2 weight prep
    prep_w<<<dim3(C_DIM / 32, MLP_HID / 32), 256>>>(fc2w, bt2, MLP_HID, C_DIM);
    // 11) out = h + fc2(a1)
    gemm_hmma<1><<<dim3(C_DIM / 128, M_TOK / 128), 128, SMEM_BYTES>>>(
        a1, bt2, fc2b, h, out, M_TOK, C_DIM, MLP_HID);
}

// round 10
// speedup vs baseline: 1.0504x; 1.0269x over previous
#include <cuda_runtime.h>
#include <cuda_fp16.h>
#include <math.h>
#include <stdint.h>

// Problem constants
constexpr int BATCH   = 32;
constexpr int HDIM    = 56;
constexpr int C_DIM   = 384;
constexpr int NHEADS  = 12;
constexpr int HEADD   = 32;
constexpr int WS      = 7;
constexpr int SHIFT   = 3;
constexpr int NWIN    = 49;
constexpr int M_TOK   = BATCH * HDIM * HDIM;   // 100352
constexpr int MLP_HID = 4 * C_DIM;             // 1536

constexpr int NSTAGE     = 3;
constexpr int STAGE_B    = 32768;              // A 16KB + B 16KB (fp16, k64)
constexpr int SMEM_BYTES = NSTAGE * STAGE_B;   // 96KB per CTA

// Scratch buffers (device globals: no allocation allowed)
__device__ __align__(256) __half g_ln [(size_t)M_TOK * C_DIM];
__device__ __align__(256) __half g_qkv[(size_t)M_TOK * 3 * C_DIM];
__device__ __align__(256) __half g_o  [(size_t)M_TOK * C_DIM];
__device__ __align__(256) __half g_h  [(size_t)M_TOK * C_DIM];   // fp16 residual
__device__ __align__(256) __half g_a1 [(size_t)M_TOK * MLP_HID];
// fp16 transposed weights [N][K]
__device__ __align__(256) __half g_bt_qkv [(size_t)3 * C_DIM * C_DIM];
__device__ __align__(256) __half g_bt_proj[(size_t)C_DIM * C_DIM];
__device__ __align__(256) __half g_bt_fc1 [(size_t)MLP_HID * C_DIM];
__device__ __align__(256) __half g_bt_fc2 [(size_t)C_DIM * MLP_HID];

// ---------------------------------------------------------------------------
// asm helpers (base-arch only: cp.async sm80, ldmatrix sm75, mma.sync sm80)
// ---------------------------------------------------------------------------
__device__ __forceinline__ uint32_t smem_u32(const void* p) {
    uint32_t a;
    asm("{ .reg .u64 t; cvta.to.shared.u64 t, %1; cvt.u32.u64 %0, t; }"
        : "=r"(a) : "l"(p));
    return a;
}
__device__ __forceinline__ void cp16(uint32_t dst, const void* src) {
    asm volatile("cp.async.cg.shared.global [%0], [%1], 16;"
                 :: "r"(dst), "l"(src) : "memory");
}
__device__ __forceinline__ void cp_commit() {
    asm volatile("cp.async.commit_group;" ::: "memory");
}
template <int N>
__device__ __forceinline__ void cp_wait() {
    asm volatile("cp.async.wait_group %0;" :: "n"(N) : "memory");
}
__device__ __forceinline__ void ldmx4(uint32_t& r0, uint32_t& r1,
                                      uint32_t& r2, uint32_t& r3, uint32_t addr) {
    asm volatile("ldmatrix.sync.aligned.m8n8.x4.shared.b16 {%0,%1,%2,%3}, [%4];"
                 : "=r"(r0), "=r"(r1), "=r"(r2), "=r"(r3) : "r"(addr));
}
__device__ __forceinline__ void mma16816(float* c, const uint32_t* a,
                                         const uint32_t* b) {
    asm volatile(
        "mma.sync.aligned.m16n8k16.row.col.f32.f16.f16.f32 "
        "{%0,%1,%2,%3}, {%4,%5,%6,%7}, {%8,%9}, {%0,%1,%2,%3};"
        : "+f"(c[0]), "+f"(c[1]), "+f"(c[2]), "+f"(c[3])
        : "r"(a[0]), "r"(a[1]), "r"(a[2]), "r"(a[3]), "r"(b[0]), "r"(b[1]));
}
// smem tile: [128 rows][64 fp16] = 128B rows (8x16B chunks), XOR-8 swizzle
__device__ __forceinline__ uint32_t sa_off(int row, int c4) {
    return (uint32_t)(row * 128 + ((c4 ^ (row & 7)) << 4));
}
__device__ __forceinline__ float gelu(float v) {
    return 0.5f * v * (1.0f + erff(v * 0.70710678118654752f));
}

// ---------------------------------------------------------------------------
// Weight prep, all 4 matrices in ONE launch. Linearized 32x32 tile grid:
//  [0,432)    qkv  K=384,  N=1152
//  [432,576)  proj K=384,  N=384
//  [576,1152) fc1  K=384,  N=1536
//  [1152,1728)fc2  K=1536, N=384
// ---------------------------------------------------------------------------
__global__ __launch_bounds__(256) void prep_all(
    const float* __restrict__ qkvw, const float* __restrict__ projw,
    const float* __restrict__ fc1w, const float* __restrict__ fc2w,
    __half* __restrict__ btq, __half* __restrict__ btp,
    __half* __restrict__ bt1, __half* __restrict__ bt2) {
    __shared__ float t[32][33];
    int bx = blockIdx.x;
    const float* W; __half* Wt; int K, N;
    if (bx < 432)       { W = qkvw;  Wt = btq; K = 384;  N = 1152; }
    else if (bx < 576)  { W = projw; Wt = btp; K = 384;  N = 384;  bx -= 432; }
    else if (bx < 1152) { W = fc1w;  Wt = bt1; K = 384;  N = 1536; bx -= 576; }
    else                { W = fc2w;  Wt = bt2; K = 1536; N = 384;  bx -= 1152; }
    int ntx = N >> 5;
    int n0 = (bx % ntx) << 5, k0 = (bx / ntx) << 5;
    int tx = threadIdx.x & 31, ty = threadIdx.x >> 5;
    #pragma unroll
    for (int i = 0; i < 32; i += 8)
        t[ty + i][tx] = W[(size_t)(k0 + ty + i) * N + n0 + tx];
    __syncthreads();
    #pragma unroll
    for (int i = 0; i < 32; i += 8)
        Wt[(size_t)(n0 + ty + i) * K + k0 + tx] = __float2half_rn(t[tx][ty + i]);
}

// ---------------------------------------------------------------------------
// fp16 HMMA GEMM (f32 accumulate): C[M,N] = A[M,K] @ Bt[N,K]^T (+bias/res/gelu)
// 128x128 CTA tile, 128 thr, 4 warps (2x2 -> 64x64 warp tile),
// K-chunk 64, 3-stage cp.async pipeline, 2 CTAs/SM.
// EPI: 0 = +bias -> half
//      1 = +bias + fp32 residual -> half   (proj: h = x + proj(o), h fp16)
//      2 = gelu(+bias) -> half
//      3 = +bias + fp16 residual -> float  (fc2: out = h + fc2(a1), out fp32)
// ---------------------------------------------------------------------------
template <int EPI>
__global__ __launch_bounds__(128, 2)
void gemm_hmma(const __half* __restrict__ A, const __half* __restrict__ Bt,
               const float* __restrict__ bias, const void* __restrict__ R,
               void* __restrict__ out, int M, int N, int K) {
    extern __shared__ __align__(128) char smem[];
    uint32_t sbase = smem_u32(smem);

    int tid = threadIdx.x, warp = tid >> 5, lane = tid & 31;
    int wm = warp >> 1, wn = warp & 1;
    int m0 = blockIdx.y * 128, n0 = blockIdx.x * 128;
    int NC = K >> 6;

    float acc[4][8][4];
    #pragma unroll
    for (int i = 0; i < 4; i++)
        #pragma unroll
        for (int j = 0; j < 8; j++)
            #pragma unroll
            for (int e = 0; e < 4; e++) acc[i][j][e] = 0.0f;

    auto load_chunk = [&](int kc, int s) {
        uint32_t ast = sbase + s * STAGE_B;
        uint32_t bst = ast + 16384;
        #pragma unroll
        for (int t = 0; t < 8; t++) {
            int seg = tid + t * 128;
            int row = seg >> 3, q = seg & 7;
            cp16(ast + sa_off(row, q),
                 A + (size_t)(m0 + row) * K + kc * 64 + q * 8);
            cp16(bst + sa_off(row, q),
                 Bt + (size_t)(n0 + row) * K + kc * 64 + q * 8);
        }
    };

    #pragma unroll
    for (int c = 0; c < NSTAGE - 1; c++) { load_chunk(c, c); cp_commit(); }

    int s_cur = 0, s_nxt = NSTAGE - 1;
    for (int c = 0; c < NC; c++) {
        cp_wait<NSTAGE - 2>();
        __syncthreads();
        int cn = c + NSTAGE - 1;
        if (cn < NC) load_chunk(cn, s_nxt);
        cp_commit();
        if (++s_nxt == NSTAGE) s_nxt = 0;

        uint32_t ast = sbase + s_cur * STAGE_B;
        uint32_t bst = ast + 16384;
        if (++s_cur == NSTAGE) s_cur = 0;

        #pragma unroll
        for (int kk = 0; kk < 4; kk++) {
            uint32_t a[4][4], b[4][4];
            #pragma unroll
            for (int i = 0; i < 4; i++) {
                int row = wm * 64 + i * 16 + (lane & 15);
                int c4  = kk * 2 + (lane >> 4);
                ldmx4(a[i][0], a[i][1], a[i][2], a[i][3], ast + sa_off(row, c4));
            }
            #pragma unroll
            for (int jp = 0; jp < 4; jp++) {
                int row = wn * 64 + jp * 16 + (lane & 7) + ((lane >> 4) << 3);
                int c4  = kk * 2 + ((lane >> 3) & 1);
                ldmx4(b[jp][0], b[jp][1], b[jp][2], b[jp][3], bst + sa_off(row, c4));
            }
            #pragma unroll
            for (int i = 0; i < 4; i++)
                #pragma unroll
                for (int jp = 0; jp < 4; jp++) {
                    mma16816(acc[i][jp * 2 + 0], a[i], &b[jp][0]);
                    mma16816(acc[i][jp * 2 + 1], a[i], &b[jp][2]);
                }
        }
    }

    // register epilogue
    int rbase = m0 + wm * 64 + (lane >> 2);
    #pragma unroll
    for (int i = 0; i < 4; i++) {
        #pragma unroll
        for (int j = 0; j < 8; j++) {
            int col = n0 + wn * 64 + j * 8 + ((lane & 3) << 1);
            float b0 = bias[col], b1 = bias[col + 1];
            #pragma unroll
            for (int hm = 0; hm < 2; hm++) {
                int row = rbase + i * 16 + hm * 8;
                float v0 = acc[i][j][hm * 2 + 0] + b0;
                float v1 = acc[i][j][hm * 2 + 1] + b1;
                if (EPI == 1) {          // + fp32 residual -> half
                    const float2 r2 = *reinterpret_cast<const float2*>(
                        (const float*)R + (size_t)row * N + col);
                    v0 += r2.x; v1 += r2.y;
                    *reinterpret_cast<__half2*>((__half*)out + (size_t)row * N + col)
                        = __floats2half2_rn(v0, v1);
                } else if (EPI == 3) {   // + fp16 residual -> float
                    const __half2 rh = *reinterpret_cast<const __half2*>(
                        (const __half*)R + (size_t)row * N + col);
                    float2 rf = __half22float2(rh);
                    v0 += rf.x; v1 += rf.y;
                    *reinterpret_cast<float2*>((float*)out + (size_t)row * N + col)
                        = make_float2(v0, v1);
                } else {
                    if (EPI == 2) { v0 = gelu(v0); v1 = gelu(v1); }
                    *reinterpret_cast<__half2*>((__half*)out + (size_t)row * N + col)
                        = __floats2half2_rn(v0, v1);
                }
            }
        }
    }
}

// ---------------------------------------------------------------------------
// LayerNorm (fp32 in -> fp16 out): one warp per token
// ---------------------------------------------------------------------------
__global__ __launch_bounds__(256) void ln_kernel(const float* __restrict__ x,
                                                 const float* __restrict__ g,
                                                 const float* __restrict__ b,
                                                 __half* __restrict__ y) {
    int warp = threadIdx.x >> 5, lane = threadIdx.x & 31;
    int m = blockIdx.x * 8 + warp;
    const float4* xr = reinterpret_cast<const float4*>(x + (size_t)m * C_DIM);
    float4 v0 = xr[lane], v1 = xr[lane + 32], v2 = xr[lane + 64];

    float s  = v0.x + v0.y + v0.z + v0.w + v1.x + v1.y + v1.z + v1.w
             + v2.x + v2.y + v2.z + v2.w;
    float sq = v0.x*v0.x + v0.y*v0.y + v0.z*v0.z + v0.w*v0.w
             + v1.x*v1.x + v1.y*v1.y + v1.z*v1.z + v1.w*v1.w
             + v2.x*v2.x + v2.y*v2.y + v2.z*v2.z + v2.w*v2.w;
    #pragma unroll
    for (int o = 16; o; o >>= 1) {
        s  += __shfl_xor_sync(0xffffffffu, s,  o);
        sq += __shfl_xor_sync(0xffffffffu, sq, o);
    }
    float mean = s * (1.0f / 384.0f);
    float var  = sq * (1.0f / 384.0f) - mean * mean;
    float rstd = rsqrtf(var + 1e-5f);

    const float4* gr = reinterpret_cast<const float4*>(g);
    const float4* br = reinterpret_cast<const float4*>(b);
    __half2* yr = reinterpret_cast<__half2*>(y + (size_t)m * C_DIM);
    #pragma unroll
    for (int t = 0; t < 3; t++) {
        int p = lane + 32 * t;
        float4 xv = (t == 0) ? v0 : (t == 1) ? v1 : v2;
        float4 gv = gr[p], bv = br[p];
        yr[p * 2 + 0] = __floats2half2_rn((xv.x - mean) * rstd * gv.x + bv.x,
                                          (xv.y - mean) * rstd * gv.y + bv.y);
        yr[p * 2 + 1] = __floats2half2_rn((xv.z - mean) * rstd * gv.z + bv.z,
                                          (xv.w - mean) * rstd * gv.w + bv.w);
    }
}

// ---------------------------------------------------------------------------
// LayerNorm (fp16 in -> fp16 out): one warp per token
// ---------------------------------------------------------------------------
__global__ __launch_bounds__(256) void ln16_kernel(const __half* __restrict__ x,
                                                   const float* __restrict__ g,
                                                   const float* __restrict__ b,
                                                   __half* __restrict__ y) {
    int warp = threadIdx.x >> 5, lane = threadIdx.x & 31;
    int m = blockIdx.x * 8 + warp;
    const uint2* xr = reinterpret_cast<const uint2*>(x + (size_t)m * C_DIM);
    uint2 u0 = xr[lane], u1 = xr[lane + 32], u2 = xr[lane + 64];

    float v[12];
    {
        const __half2* h0 = reinterpret_cast<const __half2*>(&u0);
        const __half2* h1 = reinterpret_cast<const __half2*>(&u1);
        const __half2* h2 = reinterpret_cast<const __half2*>(&u2);
        float2 f;
        f = __half22float2(h0[0]); v[0] = f.x; v[1] = f.y;
        f = __half22float2(h0[1]); v[2] = f.x; v[3] = f.y;
        f = __half22float2(h1[0]); v[4] = f.x; v[5] = f.y;
        f = __half22float2(h1[1]); v[6] = f.x; v[7] = f.y;
        f = __half22float2(h2[0]); v[8] = f.x; v[9] = f.y;
        f = __half22float2(h2[1]); v[10] = f.x; v[11] = f.y;
    }
    float s = 0.f, sq = 0.f;
    #pragma unroll
    for (int t = 0; t < 12; t++) { s += v[t]; sq += v[t] * v[t]; }
    #pragma unroll
    for (int o = 16; o; o >>= 1) {
        s  += __shfl_xor_sync(0xffffffffu, s,  o);
        sq += __shfl_xor_sync(0xffffffffu, sq, o);
    }
    float mean = s * (1.0f / 384.0f);
    float var  = sq * (1.0f / 384.0f) - mean * mean;
    float rstd = rsqrtf(var + 1e-5f);

    const float4* gr = reinterpret_cast<const float4*>(g);
    const float4* br = reinterpret_cast<const float4*>(b);
    __half2* yr = reinterpret_cast<__half2*>(y + (size_t)m * C_DIM);
    #pragma unroll
    for (int t = 0; t < 3; t++) {
        int p = lane + 32 * t;
        float4 gv = gr[p], bv = br[p];
        float w0 = (v[t*4+0] - mean) * rstd * gv.x + bv.x;
        float w1 = (v[t*4+1] - mean) * rstd * gv.y + bv.y;
        float w2 = (v[t*4+2] - mean) * rstd * gv.z + bv.z;
        float w3 = (v[t*4+3] - mean) * rstd * gv.w + bv.w;
        yr[p * 2 + 0] = __floats2half2_rn(w0, w1);
        yr[p * 2 + 1] = __floats2half2_rn(w2, w3);
    }
}

// ---------------------------------------------------------------------------
// Windowed shifted attention (round-7 version): one block per (head, window).
// Q,K half2 smem (80B stride, conflict-free LDS.128), QK via HFMA2.
// Rel-bias column in smem, indexed via relidx (L2-resident broadcast).
// ---------------------------------------------------------------------------
__global__ __launch_bounds__(256) void attn_kernel(const __half* __restrict__ qkv,
                                                   const float* __restrict__ table,
                                                   const int* __restrict__ relidx,
                                                   __half* __restrict__ o) {
    __shared__ __align__(16) __half2 q2[NWIN][40], k2[NWIN][40];
    __shared__ __align__(16) float vs[NWIN][36];
    __shared__ float ss[NWIN][52];
    __shared__ float sbias[(2 * WS - 1) * (2 * WS - 1)];
    __shared__ int   sidx[NWIN];

    int head = blockIdx.x;
    int w    = blockIdx.y;
    int tid  = threadIdx.x, warp = tid >> 5, lane = tid & 31;

    int b  = w >> 6;
    int wr = w & 63;
    int wi = wr >> 3, wj = wr & 7;

    if (tid < NWIN) {
        int i = tid / 7, j = tid - 7 * (tid / 7);
        int rr = wi * 7 + i + SHIFT; if (rr >= HDIM) rr -= HDIM;
        int cc = wj * 7 + j + SHIFT; if (cc >= HDIM) cc -= HDIM;
        sidx[tid] = b * (HDIM * HDIM) + rr * HDIM + cc;
    }
    if (tid < 169) sbias[tid] = table[tid * NHEADS + head];
    __syncthreads();

    for (int idx = tid; idx < NWIN * 4; idx += 256) {
        int r = idx >> 2, c = idx & 3;
        const uint4* base = reinterpret_cast<const uint4*>(
            qkv + (size_t)sidx[r] * (3 * C_DIM) + head * HEADD);
        reinterpret_cast<uint4*>(&q2[r][0])[c] = base[c];
        reinterpret_cast<uint4*>(&k2[r][0])[c] = base[c + C_DIM / 8];
        uint4 vv = base[c + 2 * C_DIM / 8];
        const __half2* vh = reinterpret_cast<const __half2*>(&vv);
        float2 f0 = __half22float2(vh[0]), f1 = __half22float2(vh[1]);
        float2 f2 = __half22float2(vh[2]), f3 = __half22float2(vh[3]);
        float* vd = &vs[r][c * 8];
        vd[0] = f0.x; vd[1] = f0.y; vd[2] = f1.x; vd[3] = f1.y;
        vd[4] = f2.x; vd[5] = f2.y; vd[6] = f3.x; vd[7] = f3.y;
    }
    __syncthreads();

    const float scale = 0.17677669529663687f;
    for (int e = tid; e < NWIN * NWIN; e += 256) {
        int i = e / NWIN, j = e - i * NWIN;
        const uint4* qq = reinterpret_cast<const uint4*>(&q2[i][0]);
        const uint4* kk = reinterpret_cast<const uint4*>(&k2[j][0]);
        __half2 a0 = __float2half2_rn(0.f), a1 = a0, a2 = a0, a3 = a0;
        #pragma unroll
        for (int t = 0; t < 4; t++) {
            uint4 qa = qq[t], kb = kk[t];
            const __half2* qh = reinterpret_cast<const __half2*>(&qa);
            const __half2* kh = reinterpret_cast<const __half2*>(&kb);
            a0 = __hfma2(qh[0], kh[0], a0);
            a1 = __hfma2(qh[1], kh[1], a1);
            a2 = __hfma2(qh[2], kh[2], a2);
            a3 = __hfma2(qh[3], kh[3], a3);
        }
        float2 f0 = __half22float2(a0), f1 = __half22float2(a1);
        float2 f2 = __half22float2(a2), f3 = __half22float2(a3);
        float s = (f0.x + f0.y) + (f1.x + f1.y) + (f2.x + f2.y) + (f3.x + f3.y);
        ss[i][j] = s * scale + sbias[relidx[e]];
    }
    __syncthreads();

    for (int i = warp; i < NWIN; i += 8) {
        float mx = -1e30f;
        for (int j = lane; j < NWIN; j += 32) mx = fmaxf(mx, ss[i][j]);
        #pragma unroll
        for (int off = 16; off; off >>= 1)
            mx = fmaxf(mx, __shfl_xor_sync(0xffffffffu, mx, off));
        float sum = 0.0f;
        for (int j = lane; j < NWIN; j += 32) {
            float p = __expf(ss[i][j] - mx);
            ss[i][j] = p;
            sum += p;
        }
        #pragma unroll
        for (int off = 16; off; off >>= 1)
            sum += __shfl_xor_sync(0xffffffffu, sum, off);
        float inv = 1.0f / sum;
        for (int j = lane; j < NWIN; j += 32) ss[i][j] *= inv;
    }
    __syncthreads();

    for (int e = tid; e < NWIN * 8; e += 256) {
        int i = e >> 3, dq = e & 7;
        float ax = 0.f, ay = 0.f, az = 0.f, aw = 0.f;
        #pragma unroll 7
        for (int j = 0; j < NWIN; j++) {
            float p = ss[i][j];
            float4 v = *reinterpret_cast<const float4*>(&vs[j][dq * 4]);
            ax += p * v.x; ay += p * v.y; az += p * v.z; aw += p * v.w;
        }
        __half2 h0 = __floats2half2_rn(ax, ay);
        __half2 h1 = __floats2half2_rn(az, aw);
        uint2 pk = make_uint2(*reinterpret_cast<uint32_t*>(&h0),
                              *reinterpret_cast<uint32_t*>(&h1));
        *reinterpret_cast<uint2*>(o + (size_t)sidx[i] * C_DIM + head * HEADD + dq * 4)
            = pk;
    }
}

// ---------------------------------------------------------------------------
extern "C" void kernel_launch(void* const* d_in, const int* in_sizes, int n_in,
                              void* d_out, int out_size) {
    const float* x      = (const float*)d_in[0];
    const float* n1g    = (const float*)d_in[1];
    const float* n1b    = (const float*)d_in[2];
    const float* qkvw   = (const float*)d_in[3];
    const float* qkvb   = (const float*)d_in[4];
    const float* projw  = (const float*)d_in[5];
    const float* projb  = (const float*)d_in[6];
    const float* table  = (const float*)d_in[7];
    const float* n2g    = (const float*)d_in[8];
    const float* n2b    = (const float*)d_in[9];
    const float* fc1w   = (const float*)d_in[10];
    const float* fc1b   = (const float*)d_in[11];
    const float* fc2w   = (const float*)d_in[12];
    const float* fc2b   = (const float*)d_in[13];
    const int*   relidx = (const int*)d_in[14];
    float* out = (float*)d_out;

    __half *ln, *qkv, *o, *h, *a1, *btq, *btp, *bt1, *bt2;
    cudaGetSymbolAddress((void**)&ln,  g_ln);
    cudaGetSymbolAddress((void**)&qkv, g_qkv);
    cudaGetSymbolAddress((void**)&o,   g_o);
    cudaGetSymbolAddress((void**)&h,   g_h);
    cudaGetSymbolAddress((void**)&a1,  g_a1);
    cudaGetSymbolAddress((void**)&btq, g_bt_qkv);
    cudaGetSymbolAddress((void**)&btp, g_bt_proj);
    cudaGetSymbolAddress((void**)&bt1, g_bt_fc1);
    cudaGetSymbolAddress((void**)&bt2, g_bt_fc2);

    cudaFuncSetAttribute(gemm_hmma<0>, cudaFuncAttributeMaxDynamicSharedMemorySize, SMEM_BYTES);
    cudaFuncSetAttribute(gemm_hmma<1>, cudaFuncAttributeMaxDynamicSharedMemorySize, SMEM_BYTES);
    cudaFuncSetAttribute(gemm_hmma<2>, cudaFuncAttributeMaxDynamicSharedMemorySize, SMEM_BYTES);
    cudaFuncSetAttribute(gemm_hmma<3>, cudaFuncAttributeMaxDynamicSharedMemorySize, SMEM_BYTES);

    // 0) all weight preps in one launch
    prep_all<<<1728, 256>>>(qkvw, projw, fc1w, fc2w, btq, btp, bt1, bt2);
    // 1) LN1: x (fp32) -> ln (fp16)
    ln_kernel<<<M_TOK / 8, 256>>>(x, n1g, n1b, ln);
    // 2) qkv = ln @ qkv_w + b   (fp16 out)
    gemm_hmma<0><<<dim3(3 * C_DIM / 128, M_TOK / 128), 128, SMEM_BYTES>>>(
        ln, btq, qkvb, nullptr, qkv, M_TOK, 3 * C_DIM, C_DIM);
    // 3) attention (shift folded into indices), fp16 out
    attn_kernel<<<dim3(NHEADS, 2048), 256>>>(qkv, table, relidx, o);
    // 4) h = x + proj(o)   (fp16 out, fp32 residual)
    gemm_hmma<1><<<dim3(C_DIM / 128, M_TOK / 128), 128, SMEM_BYTES>>>(
        o, btp, projb, x, h, M_TOK, C_DIM, C_DIM);
    // 5) LN2: h (fp16) -> ln (fp16)
    ln16_kernel<<<M_TOK / 8, 256>>>(h, n2g, n2b, ln);
    // 6) a1 = gelu(fc1(ln))  (fp16 out)
    gemm_hmma<2><<<dim3(MLP_HID / 128, M_TOK / 128), 128, SMEM_BYTES>>>(
        ln, bt1, fc1b, nullptr, a1, M_TOK, MLP_HID, C_DIM);
    // 7) out = h + fc2(a1)   (fp32 out, fp16 residual)
    gemm_hmma<3><<<dim3(C_DIM / 128, M_TOK / 128), 128, SMEM_BYTES>>>(
        a1, bt2, fc2b, h, out, M_TOK, C_DIM, MLP_HID);
}

// round 11
// speedup vs baseline: 1.2675x; 1.2067x over previous
#include <cuda_runtime.h>
#include <cuda_fp16.h>
#include <math.h>
#include <stdint.h>

// Problem constants
constexpr int BATCH   = 32;
constexpr int HDIM    = 56;
constexpr int C_DIM   = 384;
constexpr int NHEADS  = 12;
constexpr int HEADD   = 32;
constexpr int WS      = 7;
constexpr int SHIFT   = 3;
constexpr int NWIN    = 49;
constexpr int M_TOK   = BATCH * HDIM * HDIM;   // 100352
constexpr int MLP_HID = 4 * C_DIM;             // 1536

constexpr int NSTAGE     = 3;
constexpr int STAGE_B    = 32768;              // A 16KB + B 16KB (fp16, k64)
constexpr int SMEM_BYTES = NSTAGE * STAGE_B;   // 96KB per CTA

// Scratch buffers (device globals: no allocation allowed)
__device__ __align__(256) __half g_ln [(size_t)M_TOK * C_DIM];
__device__ __align__(256) __half g_qkv[(size_t)M_TOK * 3 * C_DIM];
__device__ __align__(256) __half g_o  [(size_t)M_TOK * C_DIM];
__device__ __align__(256) __half g_h  [(size_t)M_TOK * C_DIM];   // fp16 residual
__device__ __align__(256) __half g_a1 [(size_t)M_TOK * MLP_HID];
// fp16 transposed weights [N][K]
__device__ __align__(256) __half g_bt_qkv [(size_t)3 * C_DIM * C_DIM];
__device__ __align__(256) __half g_bt_proj[(size_t)C_DIM * C_DIM];
__device__ __align__(256) __half g_bt_fc1 [(size_t)MLP_HID * C_DIM];
__device__ __align__(256) __half g_bt_fc2 [(size_t)C_DIM * MLP_HID];

// ---------------------------------------------------------------------------
// asm helpers (base-arch only: cp.async sm80, ldmatrix sm75, mma.sync sm80)
// ---------------------------------------------------------------------------
__device__ __forceinline__ uint32_t smem_u32(const void* p) {
    uint32_t a;
    asm("{ .reg .u64 t; cvta.to.shared.u64 t, %1; cvt.u32.u64 %0, t; }"
        : "=r"(a) : "l"(p));
    return a;
}
__device__ __forceinline__ void cp16(uint32_t dst, const void* src) {
    asm volatile("cp.async.cg.shared.global [%0], [%1], 16;"
                 :: "r"(dst), "l"(src) : "memory");
}
__device__ __forceinline__ void cp_commit() {
    asm volatile("cp.async.commit_group;" ::: "memory");
}
template <int N>
__device__ __forceinline__ void cp_wait() {
    asm volatile("cp.async.wait_group %0;" :: "n"(N) : "memory");
}
__device__ __forceinline__ void ldmx4(uint32_t& r0, uint32_t& r1,
                                      uint32_t& r2, uint32_t& r3, uint32_t addr) {
    asm volatile("ldmatrix.sync.aligned.m8n8.x4.shared.b16 {%0,%1,%2,%3}, [%4];"
                 : "=r"(r0), "=r"(r1), "=r"(r2), "=r"(r3) : "r"(addr));
}
__device__ __forceinline__ void ldmx4t(uint32_t& r0, uint32_t& r1,
                                       uint32_t& r2, uint32_t& r3, uint32_t addr) {
    asm volatile("ldmatrix.sync.aligned.m8n8.x4.trans.shared.b16 {%0,%1,%2,%3}, [%4];"
                 : "=r"(r0), "=r"(r1), "=r"(r2), "=r"(r3) : "r"(addr));
}
__device__ __forceinline__ void mma16816(float* c, const uint32_t* a,
                                         const uint32_t* b) {
    asm volatile(
        "mma.sync.aligned.m16n8k16.row.col.f32.f16.f16.f32 "
        "{%0,%1,%2,%3}, {%4,%5,%6,%7}, {%8,%9}, {%0,%1,%2,%3};"
        : "+f"(c[0]), "+f"(c[1]), "+f"(c[2]), "+f"(c[3])
        : "r"(a[0]), "r"(a[1]), "r"(a[2]), "r"(a[3]), "r"(b[0]), "r"(b[1]));
}
// smem tile: [128 rows][64 fp16] = 128B rows (8x16B chunks), XOR-8 swizzle
__device__ __forceinline__ uint32_t sa_off(int row, int c4) {
    return (uint32_t)(row * 128 + ((c4 ^ (row & 7)) << 4));
}
__device__ __forceinline__ float gelu(float v) {
    return 0.5f * v * (1.0f + erff(v * 0.70710678118654752f));
}

// ---------------------------------------------------------------------------
// Weight prep, all 4 matrices in ONE launch (linearized 32x32 tile grid)
// ---------------------------------------------------------------------------
__global__ __launch_bounds__(256) void prep_all(
    const float* __restrict__ qkvw, const float* __restrict__ projw,
    const float* __restrict__ fc1w, const float* __restrict__ fc2w,
    __half* __restrict__ btq, __half* __restrict__ btp,
    __half* __restrict__ bt1, __half* __restrict__ bt2) {
    __shared__ float t[32][33];
    int bx = blockIdx.x;
    const float* W; __half* Wt; int K, N;
    if (bx < 432)       { W = qkvw;  Wt = btq; K = 384;  N = 1152; }
    else if (bx < 576)  { W = projw; Wt = btp; K = 384;  N = 384;  bx -= 432; }
    else if (bx < 1152) { W = fc1w;  Wt = bt1; K = 384;  N = 1536; bx -= 576; }
    else                { W = fc2w;  Wt = bt2; K = 1536; N = 384;  bx -= 1152; }
    int ntx = N >> 5;
    int n0 = (bx % ntx) << 5, k0 = (bx / ntx) << 5;
    int tx = threadIdx.x & 31, ty = threadIdx.x >> 5;
    #pragma unroll
    for (int i = 0; i < 32; i += 8)
        t[ty + i][tx] = W[(size_t)(k0 + ty + i) * N + n0 + tx];
    __syncthreads();
    #pragma unroll
    for (int i = 0; i < 32; i += 8)
        Wt[(size_t)(n0 + ty + i) * K + k0 + tx] = __float2half_rn(t[tx][ty + i]);
}

// ---------------------------------------------------------------------------
// fp16 HMMA GEMM (f32 accumulate) — unchanged from round 10
// EPI: 0 = +bias->half ; 1 = +bias+fp32res->half ; 2 = gelu->half ;
//      3 = +bias+fp16res->float
// ---------------------------------------------------------------------------
template <int EPI>
__global__ __launch_bounds__(128, 2)
void gemm_hmma(const __half* __restrict__ A, const __half* __restrict__ Bt,
               const float* __restrict__ bias, const void* __restrict__ R,
               void* __restrict__ out, int M, int N, int K) {
    extern __shared__ __align__(128) char smem[];
    uint32_t sbase = smem_u32(smem);

    int tid = threadIdx.x, warp = tid >> 5, lane = tid & 31;
    int wm = warp >> 1, wn = warp & 1;
    int m0 = blockIdx.y * 128, n0 = blockIdx.x * 128;
    int NC = K >> 6;

    float acc[4][8][4];
    #pragma unroll
    for (int i = 0; i < 4; i++)
        #pragma unroll
        for (int j = 0; j < 8; j++)
            #pragma unroll
            for (int e = 0; e < 4; e++) acc[i][j][e] = 0.0f;

    auto load_chunk = [&](int kc, int s) {
        uint32_t ast = sbase + s * STAGE_B;
        uint32_t bst = ast + 16384;
        #pragma unroll
        for (int t = 0; t < 8; t++) {
            int seg = tid + t * 128;
            int row = seg >> 3, q = seg & 7;
            cp16(ast + sa_off(row, q),
                 A + (size_t)(m0 + row) * K + kc * 64 + q * 8);
            cp16(bst + sa_off(row, q),
                 Bt + (size_t)(n0 + row) * K + kc * 64 + q * 8);
        }
    };

    #pragma unroll
    for (int c = 0; c < NSTAGE - 1; c++) { load_chunk(c, c); cp_commit(); }

    int s_cur = 0, s_nxt = NSTAGE - 1;
    for (int c = 0; c < NC; c++) {
        cp_wait<NSTAGE - 2>();
        __syncthreads();
        int cn = c + NSTAGE - 1;
        if (cn < NC) load_chunk(cn, s_nxt);
        cp_commit();
        if (++s_nxt == NSTAGE) s_nxt = 0;

        uint32_t ast = sbase + s_cur * STAGE_B;
        uint32_t bst = ast + 16384;
        if (++s_cur == NSTAGE) s_cur = 0;

        #pragma unroll
        for (int kk = 0; kk < 4; kk++) {
            uint32_t a[4][4], b[4][4];
            #pragma unroll
            for (int i = 0; i < 4; i++) {
                int row = wm * 64 + i * 16 + (lane & 15);
                int c4  = kk * 2 + (lane >> 4);
                ldmx4(a[i][0], a[i][1], a[i][2], a[i][3], ast + sa_off(row, c4));
            }
            #pragma unroll
            for (int jp = 0; jp < 4; jp++) {
                int row = wn * 64 + jp * 16 + (lane & 7) + ((lane >> 4) << 3);
                int c4  = kk * 2 + ((lane >> 3) & 1);
                ldmx4(b[jp][0], b[jp][1], b[jp][2], b[jp][3], bst + sa_off(row, c4));
            }
            #pragma unroll
            for (int i = 0; i < 4; i++)
                #pragma unroll
                for (int jp = 0; jp < 4; jp++) {
                    mma16816(acc[i][jp * 2 + 0], a[i], &b[jp][0]);
                    mma16816(acc[i][jp * 2 + 1], a[i], &b[jp][2]);
                }
        }
    }

    int rbase = m0 + wm * 64 + (lane >> 2);
    #pragma unroll
    for (int i = 0; i < 4; i++) {
        #pragma unroll
        for (int j = 0; j < 8; j++) {
            int col = n0 + wn * 64 + j * 8 + ((lane & 3) << 1);
            float b0 = bias[col], b1 = bias[col + 1];
            #pragma unroll
            for (int hm = 0; hm < 2; hm++) {
                int row = rbase + i * 16 + hm * 8;
                float v0 = acc[i][j][hm * 2 + 0] + b0;
                float v1 = acc[i][j][hm * 2 + 1] + b1;
                if (EPI == 1) {
                    const float2 r2 = *reinterpret_cast<const float2*>(
                        (const float*)R + (size_t)row * N + col);
                    v0 += r2.x; v1 += r2.y;
                    *reinterpret_cast<__half2*>((__half*)out + (size_t)row * N + col)
                        = __floats2half2_rn(v0, v1);
                } else if (EPI == 3) {
                    const __half2 rh = *reinterpret_cast<const __half2*>(
                        (const __half*)R + (size_t)row * N + col);
                    float2 rf = __half22float2(rh);
                    v0 += rf.x; v1 += rf.y;
                    *reinterpret_cast<float2*>((float*)out + (size_t)row * N + col)
                        = make_float2(v0, v1);
                } else {
                    if (EPI == 2) { v0 = gelu(v0); v1 = gelu(v1); }
                    *reinterpret_cast<__half2*>((__half*)out + (size_t)row * N + col)
                        = __floats2half2_rn(v0, v1);
                }
            }
        }
    }
}

// ---------------------------------------------------------------------------
// LayerNorm (fp32 in -> fp16 out)
// ---------------------------------------------------------------------------
__global__ __launch_bounds__(256) void ln_kernel(const float* __restrict__ x,
                                                 const float* __restrict__ g,
                                                 const float* __restrict__ b,
                                                 __half* __restrict__ y) {
    int warp = threadIdx.x >> 5, lane = threadIdx.x & 31;
    int m = blockIdx.x * 8 + warp;
    const float4* xr = reinterpret_cast<const float4*>(x + (size_t)m * C_DIM);
    float4 v0 = xr[lane], v1 = xr[lane + 32], v2 = xr[lane + 64];

    float s  = v0.x + v0.y + v0.z + v0.w + v1.x + v1.y + v1.z + v1.w
             + v2.x + v2.y + v2.z + v2.w;
    float sq = v0.x*v0.x + v0.y*v0.y + v0.z*v0.z + v0.w*v0.w
             + v1.x*v1.x + v1.y*v1.y + v1.z*v1.z + v1.w*v1.w
             + v2.x*v2.x + v2.y*v2.y + v2.z*v2.z + v2.w*v2.w;
    #pragma unroll
    for (int o = 16; o; o >>= 1) {
        s  += __shfl_xor_sync(0xffffffffu, s,  o);
        sq += __shfl_xor_sync(0xffffffffu, sq, o);
    }
    float mean = s * (1.0f / 384.0f);
    float var  = sq * (1.0f / 384.0f) - mean * mean;
    float rstd = rsqrtf(var + 1e-5f);

    const float4* gr = reinterpret_cast<const float4*>(g);
    const float4* br = reinterpret_cast<const float4*>(b);
    __half2* yr = reinterpret_cast<__half2*>(y + (size_t)m * C_DIM);
    #pragma unroll
    for (int t = 0; t < 3; t++) {
        int p = lane + 32 * t;
        float4 xv = (t == 0) ? v0 : (t == 1) ? v1 : v2;
        float4 gv = gr[p], bv = br[p];
        yr[p * 2 + 0] = __floats2half2_rn((xv.x - mean) * rstd * gv.x + bv.x,
                                          (xv.y - mean) * rstd * gv.y + bv.y);
        yr[p * 2 + 1] = __floats2half2_rn((xv.z - mean) * rstd * gv.z + bv.z,
                                          (xv.w - mean) * rstd * gv.w + bv.w);
    }
}

// ---------------------------------------------------------------------------
// LayerNorm (fp16 in -> fp16 out)
// ---------------------------------------------------------------------------
__global__ __launch_bounds__(256) void ln16_kernel(const __half* __restrict__ x,
                                                   const float* __restrict__ g,
                                                   const float* __restrict__ b,
                                                   __half* __restrict__ y) {
    int warp = threadIdx.x >> 5, lane = threadIdx.x & 31;
    int m = blockIdx.x * 8 + warp;
    const uint2* xr = reinterpret_cast<const uint2*>(x + (size_t)m * C_DIM);
    uint2 u0 = xr[lane], u1 = xr[lane + 32], u2 = xr[lane + 64];

    float v[12];
    {
        const __half2* h0 = reinterpret_cast<const __half2*>(&u0);
        const __half2* h1 = reinterpret_cast<const __half2*>(&u1);
        const __half2* h2 = reinterpret_cast<const __half2*>(&u2);
        float2 f;
        f = __half22float2(h0[0]); v[0] = f.x; v[1] = f.y;
        f = __half22float2(h0[1]); v[2] = f.x; v[3] = f.y;
        f = __half22float2(h1[0]); v[4] = f.x; v[5] = f.y;
        f = __half22float2(h1[1]); v[6] = f.x; v[7] = f.y;
        f = __half22float2(h2[0]); v[8] = f.x; v[9] = f.y;
        f = __half22float2(h2[1]); v[10] = f.x; v[11] = f.y;
    }
    float s = 0.f, sq = 0.f;
    #pragma unroll
    for (int t = 0; t < 12; t++) { s += v[t]; sq += v[t] * v[t]; }
    #pragma unroll
    for (int o = 16; o; o >>= 1) {
        s  += __shfl_xor_sync(0xffffffffu, s,  o);
        sq += __shfl_xor_sync(0xffffffffu, sq, o);
    }
    float mean = s * (1.0f / 384.0f);
    float var  = sq * (1.0f / 384.0f) - mean * mean;
    float rstd = rsqrtf(var + 1e-5f);

    const float4* gr = reinterpret_cast<const float4*>(g);
    const float4* br = reinterpret_cast<const float4*>(b);
    __half2* yr = reinterpret_cast<__half2*>(y + (size_t)m * C_DIM);
    #pragma unroll
    for (int t = 0; t < 3; t++) {
        int p = lane + 32 * t;
        float4 gv = gr[p], bv = br[p];
        float w0 = (v[t*4+0] - mean) * rstd * gv.x + bv.x;
        float w1 = (v[t*4+1] - mean) * rstd * gv.y + bv.y;
        float w2 = (v[t*4+2] - mean) * rstd * gv.z + bv.z;
        float w3 = (v[t*4+3] - mean) * rstd * gv.w + bv.w;
        yr[p * 2 + 0] = __floats2half2_rn(w0, w1);
        yr[p * 2 + 1] = __floats2half2_rn(w2, w3);
    }
}

// ---------------------------------------------------------------------------
// HMMA windowed attention: one block per (head, window), 256 thr / 8 warps.
// S[64x64] = Q@K^T via mma.sync (pad 49->64), scalar softmax (49x49, fp32,
// scale+bias fused), P fp16 -> O = P@V via mma.sync with ldmatrix.trans on V.
// ---------------------------------------------------------------------------
__global__ __launch_bounds__(256) void attn_kernel(const __half* __restrict__ qkv,
                                                   const float* __restrict__ table,
                                                   const int* __restrict__ relidx,
                                                   __half* __restrict__ o) {
    __shared__ __align__(16) __half qh[64 * 40], kh[64 * 40], vh[64 * 40];
    __shared__ __align__(16) __half ph[64 * 72];
    __shared__ __align__(16) float  ss[64 * 68];
    __shared__ float sbias[(2 * WS - 1) * (2 * WS - 1)];
    __shared__ int   sidx[NWIN];

    int head = blockIdx.x;
    int w    = blockIdx.y;
    int tid  = threadIdx.x, warp = tid >> 5, lane = tid & 31;

    int b  = w >> 6;
    int wr = w & 63;
    int wi = wr >> 3, wj = wr & 7;

    if (tid < NWIN) {
        int i = tid / 7, j = tid - 7 * (tid / 7);
        int rr = wi * 7 + i + SHIFT; if (rr >= HDIM) rr -= HDIM;
        int cc = wj * 7 + j + SHIFT; if (cc >= HDIM) cc -= HDIM;
        sidx[tid] = b * (HDIM * HDIM) + rr * HDIM + cc;
    }
    if (tid < 169) sbias[tid] = table[tid * NHEADS + head];
    // zero all of ph (pad safety for P@V) and V pad rows 49..63
    {
        uint4 z = make_uint4(0, 0, 0, 0);
        for (int i = tid; i < 576; i += 256)
            reinterpret_cast<uint4*>(ph)[i] = z;
        if (tid < 75) {
            int row = 49 + tid / 5, c = tid % 5;
            *reinterpret_cast<uint4*>(&vh[row * 40 + c * 8]) = z;
        }
    }
    __syncthreads();

    // gather Q,K,V rows (fp16, 4 x uint4 per row)
    for (int idx = tid; idx < NWIN * 4; idx += 256) {
        int r = idx >> 2, c = idx & 3;
        const uint4* base = reinterpret_cast<const uint4*>(
            qkv + (size_t)sidx[r] * (3 * C_DIM) + head * HEADD);
        *reinterpret_cast<uint4*>(&qh[r * 40 + c * 8]) = base[c];
        *reinterpret_cast<uint4*>(&kh[r * 40 + c * 8]) = base[c + C_DIM / 8];
        *reinterpret_cast<uint4*>(&vh[r * 40 + c * 8]) = base[c + 2 * C_DIM / 8];
    }
    __syncthreads();

    uint32_t qb = smem_u32(qh), kb = smem_u32(kh), vb_ = smem_u32(vh);
    uint32_t pb = smem_u32(ph);
    int wm = warp >> 1, wn = warp & 1;

    // ---- GEMM1: S = Q @ K^T  (each warp: 16x32 tile) ----
    {
        float acc1[4][4];
        #pragma unroll
        for (int t = 0; t < 4; t++)
            #pragma unroll
            for (int e = 0; e < 4; e++) acc1[t][e] = 0.0f;

        #pragma unroll
        for (int kf = 0; kf < 2; kf++) {
            uint32_t a[4], bfr[2][4];
            // A: Q rows wm*16..+16, k16 chunk kf
            ldmx4(a[0], a[1], a[2], a[3],
                  qb + (uint32_t)((wm * 16 + (lane & 15)) * 80
                                  + (lane >> 4) * 16 + kf * 32));
            #pragma unroll
            for (int jp = 0; jp < 2; jp++) {
                int nrow = wn * 32 + jp * 16 + (lane & 7) + ((lane >> 4) << 3);
                ldmx4(bfr[jp][0], bfr[jp][1], bfr[jp][2], bfr[jp][3],
                      kb + (uint32_t)(nrow * 80
                                      + ((lane >> 3) & 1) * 16 + kf * 32));
            }
            #pragma unroll
            for (int jp = 0; jp < 2; jp++) {
                mma16816(acc1[jp * 2 + 0], a, &bfr[jp][0]);
                mma16816(acc1[jp * 2 + 1], a, &bfr[jp][2]);
            }
        }
        // store S (fp32) to ss
        #pragma unroll
        for (int t = 0; t < 4; t++) {
            int col = wn * 32 + t * 8 + ((lane & 3) << 1);
            #pragma unroll
            for (int hm = 0; hm < 2; hm++) {
                int row = wm * 16 + (lane >> 2) + hm * 8;
                *reinterpret_cast<float2*>(&ss[row * 68 + col])
                    = make_float2(acc1[t][hm * 2], acc1[t][hm * 2 + 1]);
            }
        }
    }
    __syncthreads();

    // ---- softmax over real 49x49, scale+bias fused, write P fp16 ----
    const float scale = 0.17677669529663687f;
    for (int i = warp; i < NWIN; i += 8) {
        float mx = -1e30f;
        for (int j = lane; j < NWIN; j += 32) {
            float v = ss[i * 68 + j] * scale + sbias[relidx[i * NWIN + j]];
            ss[i * 68 + j] = v;
            mx = fmaxf(mx, v);
        }
        #pragma unroll
        for (int off = 16; off; off >>= 1)
            mx = fmaxf(mx, __shfl_xor_sync(0xffffffffu, mx, off));
        float sum = 0.0f;
        for (int j = lane; j < NWIN; j += 32) {
            float p = __expf(ss[i * 68 + j] - mx);
            ss[i * 68 + j] = p;
            sum += p;
        }
        #pragma unroll
        for (int off = 16; off; off >>= 1)
            sum += __shfl_xor_sync(0xffffffffu, sum, off);
        float inv = 1.0f / sum;
        for (int j = lane; j < NWIN; j += 32)
            ph[i * 72 + j] = __float2half_rn(ss[i * 68 + j] * inv);
    }
    __syncthreads();

    // ---- GEMM2: O = P @ V  (each warp: 16 rows x 16 headdim cols) ----
    {
        float acc2[2][4];
        #pragma unroll
        for (int t = 0; t < 2; t++)
            #pragma unroll
            for (int e = 0; e < 4; e++) acc2[t][e] = 0.0f;

        #pragma unroll
        for (int kf = 0; kf < 4; kf++) {
            uint32_t a2[4], vfr[4];
            // A: P rows wm*16..+16, k16 chunk kf (stride 72 halves = 144B)
            ldmx4(a2[0], a2[1], a2[2], a2[3],
                  pb + (uint32_t)((wm * 16 + (lane & 15)) * 144
                                  + (lane >> 4) * 16 + kf * 32));
            // B: V[k][n] via ldmatrix.trans (k = j rows, n = headdim)
            {
                int krow = kf * 16 + (lane & 7) + (((lane >> 3) & 1) << 3);
                int ncol = (lane >> 4) * 8 + wn * 16;
                ldmx4t(vfr[0], vfr[1], vfr[2], vfr[3],
                       vb_ + (uint32_t)(krow * 80 + ncol * 2));
            }
            mma16816(acc2[0], a2, &vfr[0]);
            mma16816(acc2[1], a2, &vfr[2]);
        }
        // epilogue: write rows < 49 straight to gmem (scatter via sidx)
        #pragma unroll
        for (int t = 0; t < 2; t++) {
            int col = wn * 16 + t * 8 + ((lane & 3) << 1);
            #pragma unroll
            for (int hm = 0; hm < 2; hm++) {
                int row = wm * 16 + (lane >> 2) + hm * 8;
                if (row < NWIN) {
                    __half2 hv = __floats2half2_rn(acc2[t][hm * 2],
                                                   acc2[t][hm * 2 + 1]);
                    *reinterpret_cast<__half2*>(
                        o + (size_t)sidx[row] * C_DIM + head * HEADD + col) = hv;
                }
            }
        }
    }
}

// ---------------------------------------------------------------------------
extern "C" void kernel_launch(void* const* d_in, const int* in_sizes, int n_in,
                              void* d_out, int out_size) {
    const float* x      = (const float*)d_in[0];
    const float* n1g    = (const float*)d_in[1];
    const float* n1b    = (const float*)d_in[2];
    const float* qkvw   = (const float*)d_in[3];
    const float* qkvb   = (const float*)d_in[4];
    const float* projw  = (const float*)d_in[5];
    const float* projb  = (const float*)d_in[6];
    const float* table  = (const float*)d_in[7];
    const float* n2g    = (const float*)d_in[8];
    const float* n2b    = (const float*)d_in[9];
    const float* fc1w   = (const float*)d_in[10];
    const float* fc1b   = (const float*)d_in[11];
    const float* fc2w   = (const float*)d_in[12];
    const float* fc2b   = (const float*)d_in[13];
    const int*   relidx = (const int*)d_in[14];
    float* out = (float*)d_out;

    __half *ln, *qkv, *o, *h, *a1, *btq, *btp, *bt1, *bt2;
    cudaGetSymbolAddress((void**)&ln,  g_ln);
    cudaGetSymbolAddress((void**)&qkv, g_qkv);
    cudaGetSymbolAddress((void**)&o,   g_o);
    cudaGetSymbolAddress((void**)&h,   g_h);
    cudaGetSymbolAddress((void**)&a1,  g_a1);
    cudaGetSymbolAddress((void**)&btq, g_bt_qkv);
    cudaGetSymbolAddress((void**)&btp, g_bt_proj);
    cudaGetSymbolAddress((void**)&bt1, g_bt_fc1);
    cudaGetSymbolAddress((void**)&bt2, g_bt_fc2);

    cudaFuncSetAttribute(gemm_hmma<0>, cudaFuncAttributeMaxDynamicSharedMemorySize, SMEM_BYTES);
    cudaFuncSetAttribute(gemm_hmma<1>, cudaFuncAttributeMaxDynamicSharedMemorySize, SMEM_BYTES);
    cudaFuncSetAttribute(gemm_hmma<2>, cudaFuncAttributeMaxDynamicSharedMemorySize, SMEM_BYTES);
    cudaFuncSetAttribute(gemm_hmma<3>, cudaFuncAttributeMaxDynamicSharedMemorySize, SMEM_BYTES);

    // 0) all weight preps in one launch
    prep_all<<<1728, 256>>>(qkvw, projw, fc1w, fc2w, btq, btp, bt1, bt2);
    // 1) LN1: x (fp32) -> ln (fp16)
    ln_kernel<<<M_TOK / 8, 256>>>(x, n1g, n1b, ln);
    // 2) qkv = ln @ qkv_w + b   (fp16 out)
    gemm_hmma<0><<<dim3(3 * C_DIM / 128, M_TOK / 128), 128, SMEM_BYTES>>>(
        ln, btq, qkvb, nullptr, qkv, M_TOK, 3 * C_DIM, C_DIM);
    // 3) HMMA attention (shift folded into indices), fp16 out
    attn_kernel<<<dim3(NHEADS, 2048), 256>>>(qkv, table, relidx, o);
    // 4) h = x + proj(o)   (fp16 out, fp32 residual)
    gemm_hmma<1><<<dim3(C_DIM / 128, M_TOK / 128), 128, SMEM_BYTES>>>(
        o, btp, projb, x, h, M_TOK, C_DIM, C_DIM);
    // 5) LN2: h (fp16) -> ln (fp16)
    ln16_kernel<<<M_TOK / 8, 256>>>(h, n2g, n2b, ln);
    // 6) a1 = gelu(fc1(ln))  (fp16 out)
    gemm_hmma<2><<<dim3(MLP_HID / 128, M_TOK / 128), 128, SMEM_BYTES>>>(
        ln, bt1, fc1b, nullptr, a1, M_TOK, MLP_HID, C_DIM);
    // 7) out = h + fc2(a1)   (fp32 out, fp16 residual)
    gemm_hmma<3><<<dim3(C_DIM / 128, M_TOK / 128), 128, SMEM_BYTES>>>(
        a1, bt2, fc2b, h, out, M_TOK, C_DIM, MLP_HID);
}

// round 12
// speedup vs baseline: 1.4393x; 1.1356x over previous
#include <cuda_runtime.h>
#include <cuda_fp16.h>
#include <math.h>
#include <stdint.h>

// Problem constants
constexpr int BATCH   = 32;
constexpr int HDIM    = 56;
constexpr int C_DIM   = 384;
constexpr int NHEADS  = 12;
constexpr int HEADD   = 32;
constexpr int WS      = 7;
constexpr int SHIFT   = 3;
constexpr int NWIN    = 49;
constexpr int M_TOK   = BATCH * HDIM * HDIM;   // 100352
constexpr int MLP_HID = 4 * C_DIM;             // 1536

constexpr int NSTAGE     = 3;
constexpr int STAGE_B    = 32768;              // A 16KB + B 16KB (fp16, k64)
constexpr int SMEM_BYTES = NSTAGE * STAGE_B;   // 96KB per CTA

// Scratch buffers (device globals: no allocation allowed)
__device__ __align__(256) __half g_ln [(size_t)M_TOK * C_DIM];
__device__ __align__(256) __half g_qkv[(size_t)M_TOK * 3 * C_DIM];
__device__ __align__(256) __half g_o  [(size_t)M_TOK * C_DIM];
__device__ __align__(256) __half g_h  [(size_t)M_TOK * C_DIM];   // fp16 residual
__device__ __align__(256) __half g_a1 [(size_t)M_TOK * MLP_HID];
// fp16 transposed weights [N][K]
__device__ __align__(256) __half g_bt_qkv [(size_t)3 * C_DIM * C_DIM];
__device__ __align__(256) __half g_bt_proj[(size_t)C_DIM * C_DIM];
__device__ __align__(256) __half g_bt_fc1 [(size_t)MLP_HID * C_DIM];
__device__ __align__(256) __half g_bt_fc2 [(size_t)C_DIM * MLP_HID];

// ---------------------------------------------------------------------------
// asm helpers (base-arch only: cp.async sm80, ldmatrix sm75, mma.sync sm80)
// ---------------------------------------------------------------------------
__device__ __forceinline__ uint32_t smem_u32(const void* p) {
    uint32_t a;
    asm("{ .reg .u64 t; cvta.to.shared.u64 t, %1; cvt.u32.u64 %0, t; }"
        : "=r"(a) : "l"(p));
    return a;
}
__device__ __forceinline__ void cp16(uint32_t dst, const void* src) {
    asm volatile("cp.async.cg.shared.global [%0], [%1], 16;"
                 :: "r"(dst), "l"(src) : "memory");
}
__device__ __forceinline__ void cp_commit() {
    asm volatile("cp.async.commit_group;" ::: "memory");
}
template <int N>
__device__ __forceinline__ void cp_wait() {
    asm volatile("cp.async.wait_group %0;" :: "n"(N) : "memory");
}
__device__ __forceinline__ void ldmx4(uint32_t& r0, uint32_t& r1,
                                      uint32_t& r2, uint32_t& r3, uint32_t addr) {
    asm volatile("ldmatrix.sync.aligned.m8n8.x4.shared.b16 {%0,%1,%2,%3}, [%4];"
                 : "=r"(r0), "=r"(r1), "=r"(r2), "=r"(r3) : "r"(addr));
}
__device__ __forceinline__ void ldmx4t(uint32_t& r0, uint32_t& r1,
                                       uint32_t& r2, uint32_t& r3, uint32_t addr) {
    asm volatile("ldmatrix.sync.aligned.m8n8.x4.trans.shared.b16 {%0,%1,%2,%3}, [%4];"
                 : "=r"(r0), "=r"(r1), "=r"(r2), "=r"(r3) : "r"(addr));
}
__device__ __forceinline__ void mma16816(float* c, const uint32_t* a,
                                         const uint32_t* b) {
    asm volatile(
        "mma.sync.aligned.m16n8k16.row.col.f32.f16.f16.f32 "
        "{%0,%1,%2,%3}, {%4,%5,%6,%7}, {%8,%9}, {%0,%1,%2,%3};"
        : "+f"(c[0]), "+f"(c[1]), "+f"(c[2]), "+f"(c[3])
        : "r"(a[0]), "r"(a[1]), "r"(a[2]), "r"(a[3]), "r"(b[0]), "r"(b[1]));
}
// smem tile: [128 rows][64 fp16] = 128B rows (8x16B chunks), XOR-8 swizzle
__device__ __forceinline__ uint32_t sa_off(int row, int c4) {
    return (uint32_t)(row * 128 + ((c4 ^ (row & 7)) << 4));
}
__device__ __forceinline__ float gelu(float v) {
    return 0.5f * v * (1.0f + erff(v * 0.70710678118654752f));
}

// ---------------------------------------------------------------------------
// Weight prep, all 4 matrices in ONE launch (linearized 32x32 tile grid)
// ---------------------------------------------------------------------------
__global__ __launch_bounds__(256) void prep_all(
    const float* __restrict__ qkvw, const float* __restrict__ projw,
    const float* __restrict__ fc1w, const float* __restrict__ fc2w,
    __half* __restrict__ btq, __half* __restrict__ btp,
    __half* __restrict__ bt1, __half* __restrict__ bt2) {
    __shared__ float t[32][33];
    int bx = blockIdx.x;
    const float* W; __half* Wt; int K, N;
    if (bx < 432)       { W = qkvw;  Wt = btq; K = 384;  N = 1152; }
    else if (bx < 576)  { W = projw; Wt = btp; K = 384;  N = 384;  bx -= 432; }
    else if (bx < 1152) { W = fc1w;  Wt = bt1; K = 384;  N = 1536; bx -= 576; }
    else                { W = fc2w;  Wt = bt2; K = 1536; N = 384;  bx -= 1152; }
    int ntx = N >> 5;
    int n0 = (bx % ntx) << 5, k0 = (bx / ntx) << 5;
    int tx = threadIdx.x & 31, ty = threadIdx.x >> 5;
    #pragma unroll
    for (int i = 0; i < 32; i += 8)
        t[ty + i][tx] = W[(size_t)(k0 + ty + i) * N + n0 + tx];
    __syncthreads();
    #pragma unroll
    for (int i = 0; i < 32; i += 8)
        Wt[(size_t)(n0 + ty + i) * K + k0 + tx] = __float2half_rn(t[tx][ty + i]);
}

// ---------------------------------------------------------------------------
// fp16 HMMA GEMM (f32 accumulate) — unchanged
// EPI: 0 = +bias->half ; 1 = +bias+fp32res->half ; 2 = gelu->half ;
//      3 = +bias+fp16res->float
// ---------------------------------------------------------------------------
template <int EPI>
__global__ __launch_bounds__(128, 2)
void gemm_hmma(const __half* __restrict__ A, const __half* __restrict__ Bt,
               const float* __restrict__ bias, const void* __restrict__ R,
               void* __restrict__ out, int M, int N, int K) {
    extern __shared__ __align__(128) char smem[];
    uint32_t sbase = smem_u32(smem);

    int tid = threadIdx.x, warp = tid >> 5, lane = tid & 31;
    int wm = warp >> 1, wn = warp & 1;
    int m0 = blockIdx.y * 128, n0 = blockIdx.x * 128;
    int NC = K >> 6;

    float acc[4][8][4];
    #pragma unroll
    for (int i = 0; i < 4; i++)
        #pragma unroll
        for (int j = 0; j < 8; j++)
            #pragma unroll
            for (int e = 0; e < 4; e++) acc[i][j][e] = 0.0f;

    auto load_chunk = [&](int kc, int s) {
        uint32_t ast = sbase + s * STAGE_B;
        uint32_t bst = ast + 16384;
        #pragma unroll
        for (int t = 0; t < 8; t++) {
            int seg = tid + t * 128;
            int row = seg >> 3, q = seg & 7;
            cp16(ast + sa_off(row, q),
                 A + (size_t)(m0 + row) * K + kc * 64 + q * 8);
            cp16(bst + sa_off(row, q),
                 Bt + (size_t)(n0 + row) * K + kc * 64 + q * 8);
        }
    };

    #pragma unroll
    for (int c = 0; c < NSTAGE - 1; c++) { load_chunk(c, c); cp_commit(); }

    int s_cur = 0, s_nxt = NSTAGE - 1;
    for (int c = 0; c < NC; c++) {
        cp_wait<NSTAGE - 2>();
        __syncthreads();
        int cn = c + NSTAGE - 1;
        if (cn < NC) load_chunk(cn, s_nxt);
        cp_commit();
        if (++s_nxt == NSTAGE) s_nxt = 0;

        uint32_t ast = sbase + s_cur * STAGE_B;
        uint32_t bst = ast + 16384;
        if (++s_cur == NSTAGE) s_cur = 0;

        #pragma unroll
        for (int kk = 0; kk < 4; kk++) {
            uint32_t a[4][4], b[4][4];
            #pragma unroll
            for (int i = 0; i < 4; i++) {
                int row = wm * 64 + i * 16 + (lane & 15);
                int c4  = kk * 2 + (lane >> 4);
                ldmx4(a[i][0], a[i][1], a[i][2], a[i][3], ast + sa_off(row, c4));
            }
            #pragma unroll
            for (int jp = 0; jp < 4; jp++) {
                int row = wn * 64 + jp * 16 + (lane & 7) + ((lane >> 4) << 3);
                int c4  = kk * 2 + ((lane >> 3) & 1);
                ldmx4(b[jp][0], b[jp][1], b[jp][2], b[jp][3], bst + sa_off(row, c4));
            }
            #pragma unroll
            for (int i = 0; i < 4; i++)
                #pragma unroll
                for (int jp = 0; jp < 4; jp++) {
                    mma16816(acc[i][jp * 2 + 0], a[i], &b[jp][0]);
                    mma16816(acc[i][jp * 2 + 1], a[i], &b[jp][2]);
                }
        }
    }

    int rbase = m0 + wm * 64 + (lane >> 2);
    #pragma unroll
    for (int i = 0; i < 4; i++) {
        #pragma unroll
        for (int j = 0; j < 8; j++) {
            int col = n0 + wn * 64 + j * 8 + ((lane & 3) << 1);
            float b0 = bias[col], b1 = bias[col + 1];
            #pragma unroll
            for (int hm = 0; hm < 2; hm++) {
                int row = rbase + i * 16 + hm * 8;
                float v0 = acc[i][j][hm * 2 + 0] + b0;
                float v1 = acc[i][j][hm * 2 + 1] + b1;
                if (EPI == 1) {
                    const float2 r2 = *reinterpret_cast<const float2*>(
                        (const float*)R + (size_t)row * N + col);
                    v0 += r2.x; v1 += r2.y;
                    *reinterpret_cast<__half2*>((__half*)out + (size_t)row * N + col)
                        = __floats2half2_rn(v0, v1);
                } else if (EPI == 3) {
                    const __half2 rh = *reinterpret_cast<const __half2*>(
                        (const __half*)R + (size_t)row * N + col);
                    float2 rf = __half22float2(rh);
                    v0 += rf.x; v1 += rf.y;
                    *reinterpret_cast<float2*>((float*)out + (size_t)row * N + col)
                        = make_float2(v0, v1);
                } else {
                    if (EPI == 2) { v0 = gelu(v0); v1 = gelu(v1); }
                    *reinterpret_cast<__half2*>((__half*)out + (size_t)row * N + col)
                        = __floats2half2_rn(v0, v1);
                }
            }
        }
    }
}

// ---------------------------------------------------------------------------
// LayerNorm (fp32 in -> fp16 out)
// ---------------------------------------------------------------------------
__global__ __launch_bounds__(256) void ln_kernel(const float* __restrict__ x,
                                                 const float* __restrict__ g,
                                                 const float* __restrict__ b,
                                                 __half* __restrict__ y) {
    int warp = threadIdx.x >> 5, lane = threadIdx.x & 31;
    int m = blockIdx.x * 8 + warp;
    const float4* xr = reinterpret_cast<const float4*>(x + (size_t)m * C_DIM);
    float4 v0 = xr[lane], v1 = xr[lane + 32], v2 = xr[lane + 64];

    float s  = v0.x + v0.y + v0.z + v0.w + v1.x + v1.y + v1.z + v1.w
             + v2.x + v2.y + v2.z + v2.w;
    float sq = v0.x*v0.x + v0.y*v0.y + v0.z*v0.z + v0.w*v0.w
             + v1.x*v1.x + v1.y*v1.y + v1.z*v1.z + v1.w*v1.w
             + v2.x*v2.x + v2.y*v2.y + v2.z*v2.z + v2.w*v2.w;
    #pragma unroll
    for (int o = 16; o; o >>= 1) {
        s  += __shfl_xor_sync(0xffffffffu, s,  o);
        sq += __shfl_xor_sync(0xffffffffu, sq, o);
    }
    float mean = s * (1.0f / 384.0f);
    float var  = sq * (1.0f / 384.0f) - mean * mean;
    float rstd = rsqrtf(var + 1e-5f);

    const float4* gr = reinterpret_cast<const float4*>(g);
    const float4* br = reinterpret_cast<const float4*>(b);
    __half2* yr = reinterpret_cast<__half2*>(y + (size_t)m * C_DIM);
    #pragma unroll
    for (int t = 0; t < 3; t++) {
        int p = lane + 32 * t;
        float4 xv = (t == 0) ? v0 : (t == 1) ? v1 : v2;
        float4 gv = gr[p], bv = br[p];
        yr[p * 2 + 0] = __floats2half2_rn((xv.x - mean) * rstd * gv.x + bv.x,
                                          (xv.y - mean) * rstd * gv.y + bv.y);
        yr[p * 2 + 1] = __floats2half2_rn((xv.z - mean) * rstd * gv.z + bv.z,
                                          (xv.w - mean) * rstd * gv.w + bv.w);
    }
}

// ---------------------------------------------------------------------------
// LayerNorm (fp16 in -> fp16 out)
// ---------------------------------------------------------------------------
__global__ __launch_bounds__(256) void ln16_kernel(const __half* __restrict__ x,
                                                   const float* __restrict__ g,
                                                   const float* __restrict__ b,
                                                   __half* __restrict__ y) {
    int warp = threadIdx.x >> 5, lane = threadIdx.x & 31;
    int m = blockIdx.x * 8 + warp;
    const uint2* xr = reinterpret_cast<const uint2*>(x + (size_t)m * C_DIM);
    uint2 u0 = xr[lane], u1 = xr[lane + 32], u2 = xr[lane + 64];

    float v[12];
    {
        const __half2* h0 = reinterpret_cast<const __half2*>(&u0);
        const __half2* h1 = reinterpret_cast<const __half2*>(&u1);
        const __half2* h2 = reinterpret_cast<const __half2*>(&u2);
        float2 f;
        f = __half22float2(h0[0]); v[0] = f.x; v[1] = f.y;
        f = __half22float2(h0[1]); v[2] = f.x; v[3] = f.y;
        f = __half22float2(h1[0]); v[4] = f.x; v[5] = f.y;
        f = __half22float2(h1[1]); v[6] = f.x; v[7] = f.y;
        f = __half22float2(h2[0]); v[8] = f.x; v[9] = f.y;
        f = __half22float2(h2[1]); v[10] = f.x; v[11] = f.y;
    }
    float s = 0.f, sq = 0.f;
    #pragma unroll
    for (int t = 0; t < 12; t++) { s += v[t]; sq += v[t] * v[t]; }
    #pragma unroll
    for (int o = 16; o; o >>= 1) {
        s  += __shfl_xor_sync(0xffffffffu, s,  o);
        sq += __shfl_xor_sync(0xffffffffu, sq, o);
    }
    float mean = s * (1.0f / 384.0f);
    float var  = sq * (1.0f / 384.0f) - mean * mean;
    float rstd = rsqrtf(var + 1e-5f);

    const float4* gr = reinterpret_cast<const float4*>(g);
    const float4* br = reinterpret_cast<const float4*>(b);
    __half2* yr = reinterpret_cast<__half2*>(y + (size_t)m * C_DIM);
    #pragma unroll
    for (int t = 0; t < 3; t++) {
        int p = lane + 32 * t;
        float4 gv = gr[p], bv = br[p];
        float w0 = (v[t*4+0] - mean) * rstd * gv.x + bv.x;
        float w1 = (v[t*4+1] - mean) * rstd * gv.y + bv.y;
        float w2 = (v[t*4+2] - mean) * rstd * gv.z + bv.z;
        float w3 = (v[t*4+3] - mean) * rstd * gv.w + bv.w;
        yr[p * 2 + 0] = __floats2half2_rn(w0, w1);
        yr[p * 2 + 1] = __floats2half2_rn(w2, w3);
    }
}

// ---------------------------------------------------------------------------
// HMMA windowed attention with register-resident softmax.
// S stays in mma accumulators; row max/sum via shfl + ONE smem (max,sum)
// exchange between the wn warp halves; P written once as fp16.
// ---------------------------------------------------------------------------
__global__ __launch_bounds__(256) void attn_kernel(const __half* __restrict__ qkv,
                                                   const float* __restrict__ table,
                                                   const int* __restrict__ relidx,
                                                   __half* __restrict__ o) {
    __shared__ __align__(16) __half qh[64 * 40], kh[64 * 40], vh[64 * 40];
    __shared__ __align__(16) __half ph[64 * 72];
    __shared__ float ex[64][2][2];      // [row][wn][{max,sum}]
    __shared__ float sbias[(2 * WS - 1) * (2 * WS - 1)];
    __shared__ int   sidx[NWIN];

    int head = blockIdx.x;
    int w    = blockIdx.y;
    int tid  = threadIdx.x, warp = tid >> 5, lane = tid & 31;

    int b  = w >> 6;
    int wr = w & 63;
    int wi = wr >> 3, wj = wr & 7;

    if (tid < NWIN) {
        int i = tid / 7, j = tid - 7 * (tid / 7);
        int rr = wi * 7 + i + SHIFT; if (rr >= HDIM) rr -= HDIM;
        int cc = wj * 7 + j + SHIFT; if (cc >= HDIM) cc -= HDIM;
        sidx[tid] = b * (HDIM * HDIM) + rr * HDIM + cc;
    }
    if (tid < 169) sbias[tid] = table[tid * NHEADS + head];
    // zero pad rows 49..63 of q/k/v (15 rows x 5 uint4 x 3 arrays = 225)
    if (tid < 225) {
        uint4 z = make_uint4(0, 0, 0, 0);
        int a = tid / 75;              // which array
        int t = tid % 75;
        int row = 49 + t / 5, c = t % 5;
        __half* dst = (a == 0) ? qh : (a == 1) ? kh : vh;
        *reinterpret_cast<uint4*>(&dst[row * 40 + c * 8]) = z;
    }
    __syncthreads();

    // gather Q,K,V rows (fp16, 4 x uint4 per row)
    for (int idx = tid; idx < NWIN * 4; idx += 256) {
        int r = idx >> 2, c = idx & 3;
        const uint4* base = reinterpret_cast<const uint4*>(
            qkv + (size_t)sidx[r] * (3 * C_DIM) + head * HEADD);
        *reinterpret_cast<uint4*>(&qh[r * 40 + c * 8]) = base[c];
        *reinterpret_cast<uint4*>(&kh[r * 40 + c * 8]) = base[c + C_DIM / 8];
        *reinterpret_cast<uint4*>(&vh[r * 40 + c * 8]) = base[c + 2 * C_DIM / 8];
    }
    __syncthreads();

    uint32_t qb = smem_u32(qh), kb = smem_u32(kh), vb_ = smem_u32(vh);
    uint32_t pb = smem_u32(ph);
    int wm = warp >> 1, wn = warp & 1;

    // ---- GEMM1: S = Q @ K^T  (each warp: 16x32 tile), stays in registers ----
    float acc1[4][4];
    #pragma unroll
    for (int t = 0; t < 4; t++)
        #pragma unroll
        for (int e = 0; e < 4; e++) acc1[t][e] = 0.0f;

    #pragma unroll
    for (int kf = 0; kf < 2; kf++) {
        uint32_t a[4], bfr[2][4];
        ldmx4(a[0], a[1], a[2], a[3],
              qb + (uint32_t)((wm * 16 + (lane & 15)) * 80
                              + (lane >> 4) * 16 + kf * 32));
        #pragma unroll
        for (int jp = 0; jp < 2; jp++) {
            int nrow = wn * 32 + jp * 16 + (lane & 7) + ((lane >> 4) << 3);
            ldmx4(bfr[jp][0], bfr[jp][1], bfr[jp][2], bfr[jp][3],
                  kb + (uint32_t)(nrow * 80 + ((lane >> 3) & 1) * 16 + kf * 32));
        }
        #pragma unroll
        for (int jp = 0; jp < 2; jp++) {
            mma16816(acc1[jp * 2 + 0], a, &bfr[jp][0]);
            mma16816(acc1[jp * 2 + 1], a, &bfr[jp][2]);
        }
    }

    // ---- register softmax ----
    const float scale = 0.17677669529663687f;
    int r0 = wm * 16 + (lane >> 2);
    float lm[2] = {-1e30f, -1e30f}, lsum[2];

    #pragma unroll
    for (int t = 0; t < 4; t++) {
        int cbase = wn * 32 + t * 8 + ((lane & 3) << 1);
        #pragma unroll
        for (int e = 0; e < 4; e++) {
            int hm = e >> 1;
            int c = cbase + (e & 1);
            int r = r0 + hm * 8;
            float v;
            if (c < NWIN) {
                int rr = (r < NWIN) ? r : 0;
                v = acc1[t][e] * scale + sbias[relidx[rr * NWIN + c]];
            } else v = -1e30f;
            acc1[t][e] = v;
            lm[hm] = fmaxf(lm[hm], v);
        }
    }
    #pragma unroll
    for (int off = 1; off <= 2; off <<= 1) {
        lm[0] = fmaxf(lm[0], __shfl_xor_sync(0xffffffffu, lm[0], off));
        lm[1] = fmaxf(lm[1], __shfl_xor_sync(0xffffffffu, lm[1], off));
    }
    lsum[0] = lsum[1] = 0.0f;
    #pragma unroll
    for (int t = 0; t < 4; t++)
        #pragma unroll
        for (int e = 0; e < 4; e++) {
            int hm = e >> 1;
            float p = __expf(acc1[t][e] - lm[hm]);
            acc1[t][e] = p;
            lsum[hm] += p;
        }
    #pragma unroll
    for (int off = 1; off <= 2; off <<= 1) {
        lsum[0] += __shfl_xor_sync(0xffffffffu, lsum[0], off);
        lsum[1] += __shfl_xor_sync(0xffffffffu, lsum[1], off);
    }
    // exchange (max,sum) between wn halves
    if ((lane & 3) == 0) {
        #pragma unroll
        for (int hm = 0; hm < 2; hm++) {
            int r = r0 + hm * 8;
            ex[r][wn][0] = lm[hm];
            ex[r][wn][1] = lsum[hm];
        }
    }
    __syncthreads();
    float fscale[2];
    #pragma unroll
    for (int hm = 0; hm < 2; hm++) {
        int r = r0 + hm * 8;
        float m0 = ex[r][0][0], s0 = ex[r][0][1];
        float m1 = ex[r][1][0], s1 = ex[r][1][1];
        float m = fmaxf(m0, m1);
        float stot = s0 * __expf(m0 - m) + s1 * __expf(m1 - m);
        fscale[hm] = __expf(lm[hm] - m) / stot;
    }
    // write P fp16 (covers the full 64x64, no zero-fill needed)
    #pragma unroll
    for (int t = 0; t < 4; t++) {
        int cbase = wn * 32 + t * 8 + ((lane & 3) << 1);
        #pragma unroll
        for (int hm = 0; hm < 2; hm++) {
            int r = r0 + hm * 8;
            __half2 hp = __floats2half2_rn(acc1[t][hm * 2] * fscale[hm],
                                           acc1[t][hm * 2 + 1] * fscale[hm]);
            *reinterpret_cast<__half2*>(&ph[r * 72 + cbase]) = hp;
        }
    }
    __syncthreads();

    // ---- GEMM2: O = P @ V  (each warp: 16 rows x 16 headdim cols) ----
    {
        float acc2[2][4];
        #pragma unroll
        for (int t = 0; t < 2; t++)
            #pragma unroll
            for (int e = 0; e < 4; e++) acc2[t][e] = 0.0f;

        #pragma unroll
        for (int kf = 0; kf < 4; kf++) {
            uint32_t a2[4], vfr[4];
            ldmx4(a2[0], a2[1], a2[2], a2[3],
                  pb + (uint32_t)((wm * 16 + (lane & 15)) * 144
                                  + (lane >> 4) * 16 + kf * 32));
            {
                int krow = kf * 16 + (lane & 7) + (((lane >> 3) & 1) << 3);
                int ncol = (lane >> 4) * 8 + wn * 16;
                ldmx4t(vfr[0], vfr[1], vfr[2], vfr[3],
                       vb_ + (uint32_t)(krow * 80 + ncol * 2));
            }
            mma16816(acc2[0], a2, &vfr[0]);
            mma16816(acc2[1], a2, &vfr[2]);
        }
        #pragma unroll
        for (int t = 0; t < 2; t++) {
            int col = wn * 16 + t * 8 + ((lane & 3) << 1);
            #pragma unroll
            for (int hm = 0; hm < 2; hm++) {
                int row = wm * 16 + (lane >> 2) + hm * 8;
                if (row < NWIN) {
                    __half2 hv = __floats2half2_rn(acc2[t][hm * 2],
                                                   acc2[t][hm * 2 + 1]);
                    *reinterpret_cast<__half2*>(
                        o + (size_t)sidx[row] * C_DIM + head * HEADD + col) = hv;
                }
            }
        }
    }
}

// ---------------------------------------------------------------------------
extern "C" void kernel_launch(void* const* d_in, const int* in_sizes, int n_in,
                              void* d_out, int out_size) {
    const float* x      = (const float*)d_in[0];
    const float* n1g    = (const float*)d_in[1];
    const float* n1b    = (const float*)d_in[2];
    const float* qkvw   = (const float*)d_in[3];
    const float* qkvb   = (const float*)d_in[4];
    const float* projw  = (const float*)d_in[5];
    const float* projb  = (const float*)d_in[6];
    const float* table  = (const float*)d_in[7];
    const float* n2g    = (const float*)d_in[8];
    const float* n2b    = (const float*)d_in[9];
    const float* fc1w   = (const float*)d_in[10];
    const float* fc1b   = (const float*)d_in[11];
    const float* fc2w   = (const float*)d_in[12];
    const float* fc2b   = (const float*)d_in[13];
    const int*   relidx = (const int*)d_in[14];
    float* out = (float*)d_out;

    __half *ln, *qkv, *o, *h, *a1, *btq, *btp, *bt1, *bt2;
    cudaGetSymbolAddress((void**)&ln,  g_ln);
    cudaGetSymbolAddress((void**)&qkv, g_qkv);
    cudaGetSymbolAddress((void**)&o,   g_o);
    cudaGetSymbolAddress((void**)&h,   g_h);
    cudaGetSymbolAddress((void**)&a1,  g_a1);
    cudaGetSymbolAddress((void**)&btq, g_bt_qkv);
    cudaGetSymbolAddress((void**)&btp, g_bt_proj);
    cudaGetSymbolAddress((void**)&bt1, g_bt_fc1);
    cudaGetSymbolAddress((void**)&bt2, g_bt_fc2);

    cudaFuncSetAttribute(gemm_hmma<0>, cudaFuncAttributeMaxDynamicSharedMemorySize, SMEM_BYTES);
    cudaFuncSetAttribute(gemm_hmma<1>, cudaFuncAttributeMaxDynamicSharedMemorySize, SMEM_BYTES);
    cudaFuncSetAttribute(gemm_hmma<2>, cudaFuncAttributeMaxDynamicSharedMemorySize, SMEM_BYTES);
    cudaFuncSetAttribute(gemm_hmma<3>, cudaFuncAttributeMaxDynamicSharedMemorySize, SMEM_BYTES);

    // 0) all weight preps in one launch
    prep_all<<<1728, 256>>>(qkvw, projw, fc1w, fc2w, btq, btp, bt1, bt2);
    // 1) LN1: x (fp32) -> ln (fp16)
    ln_kernel<<<M_TOK / 8, 256>>>(x, n1g, n1b, ln);
    // 2) qkv = ln @ qkv_w + b   (fp16 out)
    gemm_hmma<0><<<dim3(3 * C_DIM / 128, M_TOK / 128), 128, SMEM_BYTES>>>(
        ln, btq, qkvb, nullptr, qkv, M_TOK, 3 * C_DIM, C_DIM);
    // 3) HMMA attention (shift folded into indices), fp16 out
    attn_kernel<<<dim3(NHEADS, 2048), 256>>>(qkv, table, relidx, o);
    // 4) h = x + proj(o)   (fp16 out, fp32 residual)
    gemm_hmma<1><<<dim3(C_DIM / 128, M_TOK / 128), 128, SMEM_BYTES>>>(
        o, btp, projb, x, h, M_TOK, C_DIM, C_DIM);
    // 5) LN2: h (fp16) -> ln (fp16)
    ln16_kernel<<<M_TOK / 8, 256>>>(h, n2g, n2b, ln);
    // 6) a1 = gelu(fc1(ln))  (fp16 out)
    gemm_hmma<2><<<dim3(MLP_HID / 128, M_TOK / 128), 128, SMEM_BYTES>>>(
        ln, bt1, fc1b, nullptr, a1, M_TOK, MLP_HID, C_DIM);
    // 7) out = h + fc2(a1)   (fp32 out, fp16 residual)
    gemm_hmma<3><<<dim3(C_DIM / 128, M_TOK / 128), 128, SMEM_BYTES>>>(
        a1, bt2, fc2b, h, out, M_TOK, C_DIM, MLP_HID);
}

// round 13
// speedup vs baseline: 1.4417x; 1.0017x over previous
#include <cuda_runtime.h>
#include <cuda_fp16.h>
#include <math.h>
#include <stdint.h>

// Problem constants
constexpr int BATCH   = 32;
constexpr int HDIM    = 56;
constexpr int C_DIM   = 384;
constexpr int NHEADS  = 12;
constexpr int HEADD   = 32;
constexpr int WS      = 7;
constexpr int SHIFT   = 3;
constexpr int NWIN    = 49;
constexpr int M_TOK   = BATCH * HDIM * HDIM;   // 100352
constexpr int MLP_HID = 4 * C_DIM;             // 1536

constexpr int NSTAGE     = 3;
constexpr int STAGE_B    = 32768;              // A 16KB + B 16KB (fp16, k64)
constexpr int SMEM_BYTES = NSTAGE * STAGE_B;   // 96KB per CTA

// Scratch buffers (device globals: no allocation allowed)
__device__ __align__(256) __half g_ln [(size_t)M_TOK * C_DIM];
__device__ __align__(256) __half g_qkv[(size_t)M_TOK * 3 * C_DIM];
__device__ __align__(256) __half g_o  [(size_t)M_TOK * C_DIM];
__device__ __align__(256) __half g_h  [(size_t)M_TOK * C_DIM];   // fp16 residual
__device__ __align__(256) __half g_a1 [(size_t)M_TOK * MLP_HID];
// fp16 transposed weights [N][K]
__device__ __align__(256) __half g_bt_qkv [(size_t)3 * C_DIM * C_DIM];
__device__ __align__(256) __half g_bt_proj[(size_t)C_DIM * C_DIM];
__device__ __align__(256) __half g_bt_fc1 [(size_t)MLP_HID * C_DIM];
__device__ __align__(256) __half g_bt_fc2 [(size_t)C_DIM * MLP_HID];

// ---------------------------------------------------------------------------
// asm helpers (base-arch only: cp.async sm80, ldmatrix sm75, mma.sync sm80)
// ---------------------------------------------------------------------------
__device__ __forceinline__ uint32_t smem_u32(const void* p) {
    uint32_t a;
    asm("{ .reg .u64 t; cvta.to.shared.u64 t, %1; cvt.u32.u64 %0, t; }"
        : "=r"(a) : "l"(p));
    return a;
}
__device__ __forceinline__ void cp16(uint32_t dst, const void* src) {
    asm volatile("cp.async.cg.shared.global [%0], [%1], 16;"
                 :: "r"(dst), "l"(src) : "memory");
}
__device__ __forceinline__ void cp_commit() {
    asm volatile("cp.async.commit_group;" ::: "memory");
}
template <int N>
__device__ __forceinline__ void cp_wait() {
    asm volatile("cp.async.wait_group %0;" :: "n"(N) : "memory");
}
__device__ __forceinline__ void ldmx4(uint32_t& r0, uint32_t& r1,
                                      uint32_t& r2, uint32_t& r3, uint32_t addr) {
    asm volatile("ldmatrix.sync.aligned.m8n8.x4.shared.b16 {%0,%1,%2,%3}, [%4];"
                 : "=r"(r0), "=r"(r1), "=r"(r2), "=r"(r3) : "r"(addr));
}
__device__ __forceinline__ void ldmx4t(uint32_t& r0, uint32_t& r1,
                                       uint32_t& r2, uint32_t& r3, uint32_t addr) {
    asm volatile("ldmatrix.sync.aligned.m8n8.x4.trans.shared.b16 {%0,%1,%2,%3}, [%4];"
                 : "=r"(r0), "=r"(r1), "=r"(r2), "=r"(r3) : "r"(addr));
}
__device__ __forceinline__ void mma16816(float* c, const uint32_t* a,
                                         const uint32_t* b) {
    asm volatile(
        "mma.sync.aligned.m16n8k16.row.col.f32.f16.f16.f32 "
        "{%0,%1,%2,%3}, {%4,%5,%6,%7}, {%8,%9}, {%0,%1,%2,%3};"
        : "+f"(c[0]), "+f"(c[1]), "+f"(c[2]), "+f"(c[3])
        : "r"(a[0]), "r"(a[1]), "r"(a[2]), "r"(a[3]), "r"(b[0]), "r"(b[1]));
}
// smem tile: [128 rows][64 fp16] = 128B rows (8x16B chunks), XOR-8 swizzle
__device__ __forceinline__ uint32_t sa_off(int row, int c4) {
    return (uint32_t)(row * 128 + ((c4 ^ (row & 7)) << 4));
}
__device__ __forceinline__ float gelu(float v) {
    return 0.5f * v * (1.0f + erff(v * 0.70710678118654752f));
}

// ---------------------------------------------------------------------------
// Weight prep, all 4 matrices in ONE launch (linearized 32x32 tile grid)
// ---------------------------------------------------------------------------
__global__ __launch_bounds__(256) void prep_all(
    const float* __restrict__ qkvw, const float* __restrict__ projw,
    const float* __restrict__ fc1w, const float* __restrict__ fc2w,
    __half* __restrict__ btq, __half* __restrict__ btp,
    __half* __restrict__ bt1, __half* __restrict__ bt2) {
    __shared__ float t[32][33];
    int bx = blockIdx.x;
    const float* W; __half* Wt; int K, N;
    if (bx < 432)       { W = qkvw;  Wt = btq; K = 384;  N = 1152; }
    else if (bx < 576)  { W = projw; Wt = btp; K = 384;  N = 384;  bx -= 432; }
    else if (bx < 1152) { W = fc1w;  Wt = bt1; K = 384;  N = 1536; bx -= 576; }
    else                { W = fc2w;  Wt = bt2; K = 1536; N = 384;  bx -= 1152; }
    int ntx = N >> 5;
    int n0 = (bx % ntx) << 5, k0 = (bx / ntx) << 5;
    int tx = threadIdx.x & 31, ty = threadIdx.x >> 5;
    #pragma unroll
    for (int i = 0; i < 32; i += 8)
        t[ty + i][tx] = W[(size_t)(k0 + ty + i) * N + n0 + tx];
    __syncthreads();
    #pragma unroll
    for (int i = 0; i < 32; i += 8)
        Wt[(size_t)(n0 + ty + i) * K + k0 + tx] = __float2half_rn(t[tx][ty + i]);
}

// ---------------------------------------------------------------------------
// fp16 HMMA GEMM (f32 accumulate) — unchanged
// EPI: 0 = +bias->half ; 1 = +bias+fp32res->half ; 2 = gelu->half ;
//      3 = +bias+fp16res->float
// ---------------------------------------------------------------------------
template <int EPI>
__global__ __launch_bounds__(128, 2)
void gemm_hmma(const __half* __restrict__ A, const __half* __restrict__ Bt,
               const float* __restrict__ bias, const void* __restrict__ R,
               void* __restrict__ out, int M, int N, int K) {
    extern __shared__ __align__(128) char smem[];
    uint32_t sbase = smem_u32(smem);

    int tid = threadIdx.x, warp = tid >> 5, lane = tid & 31;
    int wm = warp >> 1, wn = warp & 1;
    int m0 = blockIdx.y * 128, n0 = blockIdx.x * 128;
    int NC = K >> 6;

    float acc[4][8][4];
    #pragma unroll
    for (int i = 0; i < 4; i++)
        #pragma unroll
        for (int j = 0; j < 8; j++)
            #pragma unroll
            for (int e = 0; e < 4; e++) acc[i][j][e] = 0.0f;

    auto load_chunk = [&](int kc, int s) {
        uint32_t ast = sbase + s * STAGE_B;
        uint32_t bst = ast + 16384;
        #pragma unroll
        for (int t = 0; t < 8; t++) {
            int seg = tid + t * 128;
            int row = seg >> 3, q = seg & 7;
            cp16(ast + sa_off(row, q),
                 A + (size_t)(m0 + row) * K + kc * 64 + q * 8);
            cp16(bst + sa_off(row, q),
                 Bt + (size_t)(n0 + row) * K + kc * 64 + q * 8);
        }
    };

    #pragma unroll
    for (int c = 0; c < NSTAGE - 1; c++) { load_chunk(c, c); cp_commit(); }

    int s_cur = 0, s_nxt = NSTAGE - 1;
    for (int c = 0; c < NC; c++) {
        cp_wait<NSTAGE - 2>();
        __syncthreads();
        int cn = c + NSTAGE - 1;
        if (cn < NC) load_chunk(cn, s_nxt);
        cp_commit();
        if (++s_nxt == NSTAGE) s_nxt = 0;

        uint32_t ast = sbase + s_cur * STAGE_B;
        uint32_t bst = ast + 16384;
        if (++s_cur == NSTAGE) s_cur = 0;

        #pragma unroll
        for (int kk = 0; kk < 4; kk++) {
            uint32_t a[4][4], b[4][4];
            #pragma unroll
            for (int i = 0; i < 4; i++) {
                int row = wm * 64 + i * 16 + (lane & 15);
                int c4  = kk * 2 + (lane >> 4);
                ldmx4(a[i][0], a[i][1], a[i][2], a[i][3], ast + sa_off(row, c4));
            }
            #pragma unroll
            for (int jp = 0; jp < 4; jp++) {
                int row = wn * 64 + jp * 16 + (lane & 7) + ((lane >> 4) << 3);
                int c4  = kk * 2 + ((lane >> 3) & 1);
                ldmx4(b[jp][0], b[jp][1], b[jp][2], b[jp][3], bst + sa_off(row, c4));
            }
            #pragma unroll
            for (int i = 0; i < 4; i++)
                #pragma unroll
                for (int jp = 0; jp < 4; jp++) {
                    mma16816(acc[i][jp * 2 + 0], a[i], &b[jp][0]);
                    mma16816(acc[i][jp * 2 + 1], a[i], &b[jp][2]);
                }
        }
    }

    int rbase = m0 + wm * 64 + (lane >> 2);
    #pragma unroll
    for (int i = 0; i < 4; i++) {
        #pragma unroll
        for (int j = 0; j < 8; j++) {
            int col = n0 + wn * 64 + j * 8 + ((lane & 3) << 1);
            float b0 = bias[col], b1 = bias[col + 1];
            #pragma unroll
            for (int hm = 0; hm < 2; hm++) {
                int row = rbase + i * 16 + hm * 8;
                float v0 = acc[i][j][hm * 2 + 0] + b0;
                float v1 = acc[i][j][hm * 2 + 1] + b1;
                if (EPI == 1) {
                    const float2 r2 = *reinterpret_cast<const float2*>(
                        (const float*)R + (size_t)row * N + col);
                    v0 += r2.x; v1 += r2.y;
                    *reinterpret_cast<__half2*>((__half*)out + (size_t)row * N + col)
                        = __floats2half2_rn(v0, v1);
                } else if (EPI == 3) {
                    const __half2 rh = *reinterpret_cast<const __half2*>(
                        (const __half*)R + (size_t)row * N + col);
                    float2 rf = __half22float2(rh);
                    v0 += rf.x; v1 += rf.y;
                    *reinterpret_cast<float2*>((float*)out + (size_t)row * N + col)
                        = make_float2(v0, v1);
                } else {
                    if (EPI == 2) { v0 = gelu(v0); v1 = gelu(v1); }
                    *reinterpret_cast<__half2*>((__half*)out + (size_t)row * N + col)
                        = __floats2half2_rn(v0, v1);
                }
            }
        }
    }
}

// ---------------------------------------------------------------------------
// LayerNorm (fp32 in -> fp16 out)
// ---------------------------------------------------------------------------
__global__ __launch_bounds__(256) void ln_kernel(const float* __restrict__ x,
                                                 const float* __restrict__ g,
                                                 const float* __restrict__ b,
                                                 __half* __restrict__ y) {
    int warp = threadIdx.x >> 5, lane = threadIdx.x & 31;
    int m = blockIdx.x * 8 + warp;
    const float4* xr = reinterpret_cast<const float4*>(x + (size_t)m * C_DIM);
    float4 v0 = xr[lane], v1 = xr[lane + 32], v2 = xr[lane + 64];

    float s  = v0.x + v0.y + v0.z + v0.w + v1.x + v1.y + v1.z + v1.w
             + v2.x + v2.y + v2.z + v2.w;
    float sq = v0.x*v0.x + v0.y*v0.y + v0.z*v0.z + v0.w*v0.w
             + v1.x*v1.x + v1.y*v1.y + v1.z*v1.z + v1.w*v1.w
             + v2.x*v2.x + v2.y*v2.y + v2.z*v2.z + v2.w*v2.w;
    #pragma unroll
    for (int o = 16; o; o >>= 1) {
        s  += __shfl_xor_sync(0xffffffffu, s,  o);
        sq += __shfl_xor_sync(0xffffffffu, sq, o);
    }
    float mean = s * (1.0f / 384.0f);
    float var  = sq * (1.0f / 384.0f) - mean * mean;
    float rstd = rsqrtf(var + 1e-5f);

    const float4* gr = reinterpret_cast<const float4*>(g);
    const float4* br = reinterpret_cast<const float4*>(b);
    __half2* yr = reinterpret_cast<__half2*>(y + (size_t)m * C_DIM);
    #pragma unroll
    for (int t = 0; t < 3; t++) {
        int p = lane + 32 * t;
        float4 xv = (t == 0) ? v0 : (t == 1) ? v1 : v2;
        float4 gv = gr[p], bv = br[p];
        yr[p * 2 + 0] = __floats2half2_rn((xv.x - mean) * rstd * gv.x + bv.x,
                                          (xv.y - mean) * rstd * gv.y + bv.y);
        yr[p * 2 + 1] = __floats2half2_rn((xv.z - mean) * rstd * gv.z + bv.z,
                                          (xv.w - mean) * rstd * gv.w + bv.w);
    }
}

// ---------------------------------------------------------------------------
// LayerNorm (fp16 in -> fp16 out)
// ---------------------------------------------------------------------------
__global__ __launch_bounds__(256) void ln16_kernel(const __half* __restrict__ x,
                                                   const float* __restrict__ g,
                                                   const float* __restrict__ b,
                                                   __half* __restrict__ y) {
    int warp = threadIdx.x >> 5, lane = threadIdx.x & 31;
    int m = blockIdx.x * 8 + warp;
    const uint2* xr = reinterpret_cast<const uint2*>(x + (size_t)m * C_DIM);
    uint2 u0 = xr[lane], u1 = xr[lane + 32], u2 = xr[lane + 64];

    float v[12];
    {
        const __half2* h0 = reinterpret_cast<const __half2*>(&u0);
        const __half2* h1 = reinterpret_cast<const __half2*>(&u1);
        const __half2* h2 = reinterpret_cast<const __half2*>(&u2);
        float2 f;
        f = __half22float2(h0[0]); v[0] = f.x; v[1] = f.y;
        f = __half22float2(h0[1]); v[2] = f.x; v[3] = f.y;
        f = __half22float2(h1[0]); v[4] = f.x; v[5] = f.y;
        f = __half22float2(h1[1]); v[6] = f.x; v[7] = f.y;
        f = __half22float2(h2[0]); v[8] = f.x; v[9] = f.y;
        f = __half22float2(h2[1]); v[10] = f.x; v[11] = f.y;
    }
    float s = 0.f, sq = 0.f;
    #pragma unroll
    for (int t = 0; t < 12; t++) { s += v[t]; sq += v[t] * v[t]; }
    #pragma unroll
    for (int o = 16; o; o >>= 1) {
        s  += __shfl_xor_sync(0xffffffffu, s,  o);
        sq += __shfl_xor_sync(0xffffffffu, sq, o);
    }
    float mean = s * (1.0f / 384.0f);
    float var  = sq * (1.0f / 384.0f) - mean * mean;
    float rstd = rsqrtf(var + 1e-5f);

    const float4* gr = reinterpret_cast<const float4*>(g);
    const float4* br = reinterpret_cast<const float4*>(b);
    __half2* yr = reinterpret_cast<__half2*>(y + (size_t)m * C_DIM);
    #pragma unroll
    for (int t = 0; t < 3; t++) {
        int p = lane + 32 * t;
        float4 gv = gr[p], bv = br[p];
        float w0 = (v[t*4+0] - mean) * rstd * gv.x + bv.x;
        float w1 = (v[t*4+1] - mean) * rstd * gv.y + bv.y;
        float w2 = (v[t*4+2] - mean) * rstd * gv.z + bv.z;
        float w3 = (v[t*4+3] - mean) * rstd * gv.w + bv.w;
        yr[p * 2 + 0] = __floats2half2_rn(w0, w1);
        yr[p * 2 + 1] = __floats2half2_rn(w2, w3);
    }
}

// ---------------------------------------------------------------------------
// HMMA windowed attention with register-resident softmax.
// S stays in mma accumulators; row max/sum via shfl + ONE smem (max,sum)
// exchange between the wn warp halves; P written once as fp16.
// ---------------------------------------------------------------------------
__global__ __launch_bounds__(256) void attn_kernel(const __half* __restrict__ qkv,
                                                   const float* __restrict__ table,
                                                   const int* __restrict__ relidx,
                                                   __half* __restrict__ o) {
    __shared__ __align__(16) __half qh[64 * 40], kh[64 * 40], vh[64 * 40];
    __shared__ __align__(16) __half ph[64 * 72];
    __shared__ float ex[64][2][2];      // [row][wn][{max,sum}]
    __shared__ float sbias[(2 * WS - 1) * (2 * WS - 1)];
    __shared__ int   sidx[NWIN];

    int head = blockIdx.x;
    int w    = blockIdx.y;
    int tid  = threadIdx.x, warp = tid >> 5, lane = tid & 31;

    int b  = w >> 6;
    int wr = w & 63;
    int wi = wr >> 3, wj = wr & 7;

    if (tid < NWIN) {
        int i = tid / 7, j = tid - 7 * (tid / 7);
        int rr = wi * 7 + i + SHIFT; if (rr >= HDIM) rr -= HDIM;
        int cc = wj * 7 + j + SHIFT; if (cc >= HDIM) cc -= HDIM;
        sidx[tid] = b * (HDIM * HDIM) + rr * HDIM + cc;
    }
    if (tid < 169) sbias[tid] = table[tid * NHEADS + head];
    // zero pad rows 49..63 of q/k/v (15 rows x 5 uint4 x 3 arrays = 225)
    if (tid < 225) {
        uint4 z = make_uint4(0, 0, 0, 0);
        int a = tid / 75;              // which array
        int t = tid % 75;
        int row = 49 + t / 5, c = t % 5;
        __half* dst = (a == 0) ? qh : (a == 1) ? kh : vh;
        *reinterpret_cast<uint4*>(&dst[row * 40 + c * 8]) = z;
    }
    __syncthreads();

    // gather Q,K,V rows (fp16, 4 x uint4 per row)
    for (int idx = tid; idx < NWIN * 4; idx += 256) {
        int r = idx >> 2, c = idx & 3;
        const uint4* base = reinterpret_cast<const uint4*>(
            qkv + (size_t)sidx[r] * (3 * C_DIM) + head * HEADD);
        *reinterpret_cast<uint4*>(&qh[r * 40 + c * 8]) = base[c];
        *reinterpret_cast<uint4*>(&kh[r * 40 + c * 8]) = base[c + C_DIM / 8];
        *reinterpret_cast<uint4*>(&vh[r * 40 + c * 8]) = base[c + 2 * C_DIM / 8];
    }
    __syncthreads();

    uint32_t qb = smem_u32(qh), kb = smem_u32(kh), vb_ = smem_u32(vh);
    uint32_t pb = smem_u32(ph);
    int wm = warp >> 1, wn = warp & 1;

    // ---- GEMM1: S = Q @ K^T  (each warp: 16x32 tile), stays in registers ----
    float acc1[4][4];
    #pragma unroll
    for (int t = 0; t < 4; t++)
        #pragma unroll
        for (int e = 0; e < 4; e++) acc1[t][e] = 0.0f;

    #pragma unroll
    for (int kf = 0; kf < 2; kf++) {
        uint32_t a[4], bfr[2][4];
        ldmx4(a[0], a[1], a[2], a[3],
              qb + (uint32_t)((wm * 16 + (lane & 15)) * 80
                              + (lane >> 4) * 16 + kf * 32));
        #pragma unroll
        for (int jp = 0; jp < 2; jp++) {
            int nrow = wn * 32 + jp * 16 + (lane & 7) + ((lane >> 4) << 3);
            ldmx4(bfr[jp][0], bfr[jp][1], bfr[jp][2], bfr[jp][3],
                  kb + (uint32_t)(nrow * 80 + ((lane >> 3) & 1) * 16 + kf * 32));
        }
        #pragma unroll
        for (int jp = 0; jp < 2; jp++) {
            mma16816(acc1[jp * 2 + 0], a, &bfr[jp][0]);
            mma16816(acc1[jp * 2 + 1], a, &bfr[jp][2]);
        }
    }

    // ---- register softmax ----
    const float scale = 0.17677669529663687f;
    int r0 = wm * 16 + (lane >> 2);
    float lm[2] = {-1e30f, -1e30f}, lsum[2];

    #pragma unroll
    for (int t = 0; t < 4; t++) {
        int cbase = wn * 32 + t * 8 + ((lane & 3) << 1);
        #pragma unroll
        for (int e = 0; e < 4; e++) {
            int hm = e >> 1;
            int c = cbase + (e & 1);
            int r = r0 + hm * 8;
            float v;
            if (c < NWIN) {
                int rr = (r < NWIN) ? r : 0;
                v = acc1[t][e] * scale + sbias[relidx[rr * NWIN + c]];
            } else v = -1e30f;
            acc1[t][e] = v;
            lm[hm] = fmaxf(lm[hm], v);
        }
    }
    #pragma unroll
    for (int off = 1; off <= 2; off <<= 1) {
        lm[0] = fmaxf(lm[0], __shfl_xor_sync(0xffffffffu, lm[0], off));
        lm[1] = fmaxf(lm[1], __shfl_xor_sync(0xffffffffu, lm[1], off));
    }
    lsum[0] = lsum[1] = 0.0f;
    #pragma unroll
    for (int t = 0; t < 4; t++)
        #pragma unroll
        for (int e = 0; e < 4; e++) {
            int hm = e >> 1;
            float p = __expf(acc1[t][e] - lm[hm]);
            acc1[t][e] = p;
            lsum[hm] += p;
        }
    #pragma unroll
    for (int off = 1; off <= 2; off <<= 1) {
        lsum[0] += __shfl_xor_sync(0xffffffffu, lsum[0], off);
        lsum[1] += __shfl_xor_sync(0xffffffffu, lsum[1], off);
    }
    // exchange (max,sum) between wn halves
    if ((lane & 3) == 0) {
        #pragma unroll
        for (int hm = 0; hm < 2; hm++) {
            int r = r0 + hm * 8;
            ex[r][wn][0] = lm[hm];
            ex[r][wn][1] = lsum[hm];
        }
    }
    __syncthreads();
    float fscale[2];
    #pragma unroll
    for (int hm = 0; hm < 2; hm++) {
        int r = r0 + hm * 8;
        float m0 = ex[r][0][0], s0 = ex[r][0][1];
        float m1 = ex[r][1][0], s1 = ex[r][1][1];
        float m = fmaxf(m0, m1);
        float stot = s0 * __expf(m0 - m) + s1 * __expf(m1 - m);
        fscale[hm] = __expf(lm[hm] - m) / stot;
    }
    // write P fp16 (covers the full 64x64, no zero-fill needed)
    #pragma unroll
    for (int t = 0; t < 4; t++) {
        int cbase = wn * 32 + t * 8 + ((lane & 3) << 1);
        #pragma unroll
        for (int hm = 0; hm < 2; hm++) {
            int r = r0 + hm * 8;
            __half2 hp = __floats2half2_rn(acc1[t][hm * 2] * fscale[hm],
                                           acc1[t][hm * 2 + 1] * fscale[hm]);
            *reinterpret_cast<__half2*>(&ph[r * 72 + cbase]) = hp;
        }
    }
    __syncthreads();

    // ---- GEMM2: O = P @ V  (each warp: 16 rows x 16 headdim cols) ----
    {
        float acc2[2][4];
        #pragma unroll
        for (int t = 0; t < 2; t++)
            #pragma unroll
            for (int e = 0; e < 4; e++) acc2[t][e] = 0.0f;

        #pragma unroll
        for (int kf = 0; kf < 4; kf++) {
            uint32_t a2[4], vfr[4];
            ldmx4(a2[0], a2[1], a2[2], a2[3],
                  pb + (uint32_t)((wm * 16 + (lane & 15)) * 144
                                  + (lane >> 4) * 16 + kf * 32));
            {
                int krow = kf * 16 + (lane & 7) + (((lane >> 3) & 1) << 3);
                int ncol = (lane >> 4) * 8 + wn * 16;
                ldmx4t(vfr[0], vfr[1], vfr[2], vfr[3],
                       vb_ + (uint32_t)(krow * 80 + ncol * 2));
            }
            mma16816(acc2[0], a2, &vfr[0]);
            mma16816(acc2[1], a2, &vfr[2]);
        }
        #pragma unroll
        for (int t = 0; t < 2; t++) {
            int col = wn * 16 + t * 8 + ((lane & 3) << 1);
            #pragma unroll
            for (int hm = 0; hm < 2; hm++) {
                int row = wm * 16 + (lane >> 2) + hm * 8;
                if (row < NWIN) {
                    __half2 hv = __floats2half2_rn(acc2[t][hm * 2],
                                                   acc2[t][hm * 2 + 1]);
                    *reinterpret_cast<__half2*>(
                        o + (size_t)sidx[row] * C_DIM + head * HEADD + col) = hv;
                }
            }
        }
    }
}

// ---------------------------------------------------------------------------
extern "C" void kernel_launch(void* const* d_in, const int* in_sizes, int n_in,
                              void* d_out, int out_size) {
    const float* x      = (const float*)d_in[0];
    const float* n1g    = (const float*)d_in[1];
    const float* n1b    = (const float*)d_in[2];
    const float* qkvw   = (const float*)d_in[3];
    const float* qkvb   = (const float*)d_in[4];
    const float* projw  = (const float*)d_in[5];
    const float* projb  = (const float*)d_in[6];
    const float* table  = (const float*)d_in[7];
    const float* n2g    = (const float*)d_in[8];
    const float* n2b    = (const float*)d_in[9];
    const float* fc1w   = (const float*)d_in[10];
    const float* fc1b   = (const float*)d_in[11];
    const float* fc2w   = (const float*)d_in[12];
    const float* fc2b   = (const float*)d_in[13];
    const int*   relidx = (const int*)d_in[14];
    float* out = (float*)d_out;

    __half *ln, *qkv, *o, *h, *a1, *btq, *btp, *bt1, *bt2;
    cudaGetSymbolAddress((void**)&ln,  g_ln);
    cudaGetSymbolAddress((void**)&qkv, g_qkv);
    cudaGetSymbolAddress((void**)&o,   g_o);
    cudaGetSymbolAddress((void**)&h,   g_h);
    cudaGetSymbolAddress((void**)&a1,  g_a1);
    cudaGetSymbolAddress((void**)&btq, g_bt_qkv);
    cudaGetSymbolAddress((void**)&btp, g_bt_proj);
    cudaGetSymbolAddress((void**)&bt1, g_bt_fc1);
    cudaGetSymbolAddress((void**)&bt2, g_bt_fc2);

    cudaFuncSetAttribute(gemm_hmma<0>, cudaFuncAttributeMaxDynamicSharedMemorySize, SMEM_BYTES);
    cudaFuncSetAttribute(gemm_hmma<1>, cudaFuncAttributeMaxDynamicSharedMemorySize, SMEM_BYTES);
    cudaFuncSetAttribute(gemm_hmma<2>, cudaFuncAttributeMaxDynamicSharedMemorySize, SMEM_BYTES);
    cudaFuncSetAttribute(gemm_hmma<3>, cudaFuncAttributeMaxDynamicSharedMemorySize, SMEM_BYTES);

    // 0) all weight preps in one launch
    prep_all<<<1728, 256>>>(qkvw, projw, fc1w, fc2w, btq, btp, bt1, bt2);
    // 1) LN1: x (fp32) -> ln (fp16)
    ln_kernel<<<M_TOK / 8, 256>>>(x, n1g, n1b, ln);
    // 2) qkv = ln @ qkv_w + b   (fp16 out)
    gemm_hmma<0><<<dim3(3 * C_DIM / 128, M_TOK / 128), 128, SMEM_BYTES>>>(
        ln, btq, qkvb, nullptr, qkv, M_TOK, 3 * C_DIM, C_DIM);
    // 3) HMMA attention (shift folded into indices), fp16 out
    attn_kernel<<<dim3(NHEADS, 2048), 256>>>(qkv, table, relidx, o);
    // 4) h = x + proj(o)   (fp16 out, fp32 residual)
    gemm_hmma<1><<<dim3(C_DIM / 128, M_TOK / 128), 128, SMEM_BYTES>>>(
        o, btp, projb, x, h, M_TOK, C_DIM, C_DIM);
    // 5) LN2: h (fp16) -> ln (fp16)
    ln16_kernel<<<M_TOK / 8, 256>>>(h, n2g, n2b, ln);
    // 6) a1 = gelu(fc1(ln))  (fp16 out)
    gemm_hmma<2><<<dim3(MLP_HID / 128, M_TOK / 128), 128, SMEM_BYTES>>>(
        ln, bt1, fc1b, nullptr, a1, M_TOK, MLP_HID, C_DIM);
    // 7) out = h + fc2(a1)   (fp32 out, fp16 residual)
    gemm_hmma<3><<<dim3(C_DIM / 128, M_TOK / 128), 128, SMEM_BYTES>>>(
        a1, bt2, fc2b, h, out, M_TOK, C_DIM, MLP_HID);
}

// round 14
// speedup vs baseline: 1.4419x; 1.0001x over previous
#include <cuda_runtime.h>
#include <cuda_fp16.h>
#include <math.h>
#include <stdint.h>

// Problem constants
constexpr int BATCH   = 32;
constexpr int HDIM    = 56;
constexpr int C_DIM   = 384;
constexpr int NHEADS  = 12;
constexpr int HEADD   = 32;
constexpr int WS      = 7;
constexpr int SHIFT   = 3;
constexpr int NWIN    = 49;
constexpr int M_TOK   = BATCH * HDIM * HDIM;   // 100352
constexpr int MLP_HID = 4 * C_DIM;             // 1536

constexpr int NSTAGE     = 3;
constexpr int STAGE_B    = 32768;              // A 16KB + B 16KB (fp16, k64)
constexpr int SMEM_BYTES = NSTAGE * STAGE_B;   // 96KB per CTA

// Scratch buffers (device globals: no allocation allowed)
__device__ __align__(256) __half g_ln [(size_t)M_TOK * C_DIM];
__device__ __align__(256) __half g_qkv[(size_t)M_TOK * 3 * C_DIM];
__device__ __align__(256) __half g_o  [(size_t)M_TOK * C_DIM];
__device__ __align__(256) __half g_h  [(size_t)M_TOK * C_DIM];   // fp16 residual
__device__ __align__(256) __half g_a1 [(size_t)M_TOK * MLP_HID];
// fp16 transposed weights [N][K]
__device__ __align__(256) __half g_bt_qkv [(size_t)3 * C_DIM * C_DIM];
__device__ __align__(256) __half g_bt_proj[(size_t)C_DIM * C_DIM];
__device__ __align__(256) __half g_bt_fc1 [(size_t)MLP_HID * C_DIM];
__device__ __align__(256) __half g_bt_fc2 [(size_t)C_DIM * MLP_HID];

// ---------------------------------------------------------------------------
// asm helpers (base-arch only: cp.async sm80, ldmatrix sm75, mma.sync sm80)
// ---------------------------------------------------------------------------
__device__ __forceinline__ uint32_t smem_u32(const void* p) {
    uint32_t a;
    asm("{ .reg .u64 t; cvta.to.shared.u64 t, %1; cvt.u32.u64 %0, t; }"
        : "=r"(a) : "l"(p));
    return a;
}
__device__ __forceinline__ void cp16(uint32_t dst, const void* src) {
    asm volatile("cp.async.cg.shared.global [%0], [%1], 16;"
                 :: "r"(dst), "l"(src) : "memory");
}
__device__ __forceinline__ void cp_commit() {
    asm volatile("cp.async.commit_group;" ::: "memory");
}
template <int N>
__device__ __forceinline__ void cp_wait() {
    asm volatile("cp.async.wait_group %0;" :: "n"(N) : "memory");
}
__device__ __forceinline__ void ldmx4(uint32_t& r0, uint32_t& r1,
                                      uint32_t& r2, uint32_t& r3, uint32_t addr) {
    asm volatile("ldmatrix.sync.aligned.m8n8.x4.shared.b16 {%0,%1,%2,%3}, [%4];"
                 : "=r"(r0), "=r"(r1), "=r"(r2), "=r"(r3) : "r"(addr));
}
__device__ __forceinline__ void ldmx4t(uint32_t& r0, uint32_t& r1,
                                       uint32_t& r2, uint32_t& r3, uint32_t addr) {
    asm volatile("ldmatrix.sync.aligned.m8n8.x4.trans.shared.b16 {%0,%1,%2,%3}, [%4];"
                 : "=r"(r0), "=r"(r1), "=r"(r2), "=r"(r3) : "r"(addr));
}
__device__ __forceinline__ void mma16816(float* c, const uint32_t* a,
                                         const uint32_t* b) {
    asm volatile(
        "mma.sync.aligned.m16n8k16.row.col.f32.f16.f16.f32 "
        "{%0,%1,%2,%3}, {%4,%5,%6,%7}, {%8,%9}, {%0,%1,%2,%3};"
        : "+f"(c[0]), "+f"(c[1]), "+f"(c[2]), "+f"(c[3])
        : "r"(a[0]), "r"(a[1]), "r"(a[2]), "r"(a[3]), "r"(b[0]), "r"(b[1]));
}
// smem tile: [128 rows][64 fp16] = 128B rows (8x16B chunks), XOR-8 swizzle
__device__ __forceinline__ uint32_t sa_off(int row, int c4) {
    return (uint32_t)(row * 128 + ((c4 ^ (row & 7)) << 4));
}
__device__ __forceinline__ float gelu(float v) {
    return 0.5f * v * (1.0f + erff(v * 0.70710678118654752f));
}

// ---------------------------------------------------------------------------
// Weight prep, all 4 matrices in ONE launch (linearized 32x32 tile grid)
// ---------------------------------------------------------------------------
__global__ __launch_bounds__(256) void prep_all(
    const float* __restrict__ qkvw, const float* __restrict__ projw,
    const float* __restrict__ fc1w, const float* __restrict__ fc2w,
    __half* __restrict__ btq, __half* __restrict__ btp,
    __half* __restrict__ bt1, __half* __restrict__ bt2) {
    __shared__ float t[32][33];
    int bx = blockIdx.x;
    const float* W; __half* Wt; int K, N;
    if (bx < 432)       { W = qkvw;  Wt = btq; K = 384;  N = 1152; }
    else if (bx < 576)  { W = projw; Wt = btp; K = 384;  N = 384;  bx -= 432; }
    else if (bx < 1152) { W = fc1w;  Wt = bt1; K = 384;  N = 1536; bx -= 576; }
    else                { W = fc2w;  Wt = bt2; K = 1536; N = 384;  bx -= 1152; }
    int ntx = N >> 5;
    int n0 = (bx % ntx) << 5, k0 = (bx / ntx) << 5;
    int tx = threadIdx.x & 31, ty = threadIdx.x >> 5;
    #pragma unroll
    for (int i = 0; i < 32; i += 8)
        t[ty + i][tx] = W[(size_t)(k0 + ty + i) * N + n0 + tx];
    __syncthreads();
    #pragma unroll
    for (int i = 0; i < 32; i += 8)
        Wt[(size_t)(n0 + ty + i) * K + k0 + tx] = __float2half_rn(t[tx][ty + i]);
}

// ---------------------------------------------------------------------------
// fp16 HMMA GEMM (f32 accumulate) — unchanged
// EPI: 0 = +bias->half ; 1 = +bias+fp32res->half ; 2 = gelu->half ;
//      3 = +bias+fp16res->float
// ---------------------------------------------------------------------------
template <int EPI>
__global__ __launch_bounds__(128, 2)
void gemm_hmma(const __half* __restrict__ A, const __half* __restrict__ Bt,
               const float* __restrict__ bias, const void* __restrict__ R,
               void* __restrict__ out, int M, int N, int K) {
    extern __shared__ __align__(128) char smem[];
    uint32_t sbase = smem_u32(smem);

    int tid = threadIdx.x, warp = tid >> 5, lane = tid & 31;
    int wm = warp >> 1, wn = warp & 1;
    int m0 = blockIdx.y * 128, n0 = blockIdx.x * 128;
    int NC = K >> 6;

    float acc[4][8][4];
    #pragma unroll
    for (int i = 0; i < 4; i++)
        #pragma unroll
        for (int j = 0; j < 8; j++)
            #pragma unroll
            for (int e = 0; e < 4; e++) acc[i][j][e] = 0.0f;

    auto load_chunk = [&](int kc, int s) {
        uint32_t ast = sbase + s * STAGE_B;
        uint32_t bst = ast + 16384;
        #pragma unroll
        for (int t = 0; t < 8; t++) {
            int seg = tid + t * 128;
            int row = seg >> 3, q = seg & 7;
            cp16(ast + sa_off(row, q),
                 A + (size_t)(m0 + row) * K + kc * 64 + q * 8);
            cp16(bst + sa_off(row, q),
                 Bt + (size_t)(n0 + row) * K + kc * 64 + q * 8);
        }
    };

    #pragma unroll
    for (int c = 0; c < NSTAGE - 1; c++) { load_chunk(c, c); cp_commit(); }

    int s_cur = 0, s_nxt = NSTAGE - 1;
    for (int c = 0; c < NC; c++) {
        cp_wait<NSTAGE - 2>();
        __syncthreads();
        int cn = c + NSTAGE - 1;
        if (cn < NC) load_chunk(cn, s_nxt);
        cp_commit();
        if (++s_nxt == NSTAGE) s_nxt = 0;

        uint32_t ast = sbase + s_cur * STAGE_B;
        uint32_t bst = ast + 16384;
        if (++s_cur == NSTAGE) s_cur = 0;

        #pragma unroll
        for (int kk = 0; kk < 4; kk++) {
            uint32_t a[4][4], b[4][4];
            #pragma unroll
            for (int i = 0; i < 4; i++) {
                int row = wm * 64 + i * 16 + (lane & 15);
                int c4  = kk * 2 + (lane >> 4);
                ldmx4(a[i][0], a[i][1], a[i][2], a[i][3], ast + sa_off(row, c4));
            }
            #pragma unroll
            for (int jp = 0; jp < 4; jp++) {
                int row = wn * 64 + jp * 16 + (lane & 7) + ((lane >> 4) << 3);
                int c4  = kk * 2 + ((lane >> 3) & 1);
                ldmx4(b[jp][0], b[jp][1], b[jp][2], b[jp][3], bst + sa_off(row, c4));
            }
            #pragma unroll
            for (int i = 0; i < 4; i++)
                #pragma unroll
                for (int jp = 0; jp < 4; jp++) {
                    mma16816(acc[i][jp * 2 + 0], a[i], &b[jp][0]);
                    mma16816(acc[i][jp * 2 + 1], a[i], &b[jp][2]);
                }
        }
    }

    int rbase = m0 + wm * 64 + (lane >> 2);
    #pragma unroll
    for (int i = 0; i < 4; i++) {
        #pragma unroll
        for (int j = 0; j < 8; j++) {
            int col = n0 + wn * 64 + j * 8 + ((lane & 3) << 1);
            float b0 = bias[col], b1 = bias[col + 1];
            #pragma unroll
            for (int hm = 0; hm < 2; hm++) {
                int row = rbase + i * 16 + hm * 8;
                float v0 = acc[i][j][hm * 2 + 0] + b0;
                float v1 = acc[i][j][hm * 2 + 1] + b1;
                if (EPI == 1) {
                    const float2 r2 = *reinterpret_cast<const float2*>(
                        (const float*)R + (size_t)row * N + col);
                    v0 += r2.x; v1 += r2.y;
                    *reinterpret_cast<__half2*>((__half*)out + (size_t)row * N + col)
                        = __floats2half2_rn(v0, v1);
                } else if (EPI == 3) {
                    const __half2 rh = *reinterpret_cast<const __half2*>(
                        (const __half*)R + (size_t)row * N + col);
                    float2 rf = __half22float2(rh);
                    v0 += rf.x; v1 += rf.y;
                    *reinterpret_cast<float2*>((float*)out + (size_t)row * N + col)
                        = make_float2(v0, v1);
                } else {
                    if (EPI == 2) { v0 = gelu(v0); v1 = gelu(v1); }
                    *reinterpret_cast<__half2*>((__half*)out + (size_t)row * N + col)
                        = __floats2half2_rn(v0, v1);
                }
            }
        }
    }
}

// ---------------------------------------------------------------------------
// LayerNorm (fp32 in -> fp16 out)
// ---------------------------------------------------------------------------
__global__ __launch_bounds__(256) void ln_kernel(const float* __restrict__ x,
                                                 const float* __restrict__ g,
                                                 const float* __restrict__ b,
                                                 __half* __restrict__ y) {
    int warp = threadIdx.x >> 5, lane = threadIdx.x & 31;
    int m = blockIdx.x * 8 + warp;
    const float4* xr = reinterpret_cast<const float4*>(x + (size_t)m * C_DIM);
    float4 v0 = xr[lane], v1 = xr[lane + 32], v2 = xr[lane + 64];

    float s  = v0.x + v0.y + v0.z + v0.w + v1.x + v1.y + v1.z + v1.w
             + v2.x + v2.y + v2.z + v2.w;
    float sq = v0.x*v0.x + v0.y*v0.y + v0.z*v0.z + v0.w*v0.w
             + v1.x*v1.x + v1.y*v1.y + v1.z*v1.z + v1.w*v1.w
             + v2.x*v2.x + v2.y*v2.y + v2.z*v2.z + v2.w*v2.w;
    #pragma unroll
    for (int o = 16; o; o >>= 1) {
        s  += __shfl_xor_sync(0xffffffffu, s,  o);
        sq += __shfl_xor_sync(0xffffffffu, sq, o);
    }
    float mean = s * (1.0f / 384.0f);
    float var  = sq * (1.0f / 384.0f) - mean * mean;
    float rstd = rsqrtf(var + 1e-5f);

    const float4* gr = reinterpret_cast<const float4*>(g);
    const float4* br = reinterpret_cast<const float4*>(b);
    __half2* yr = reinterpret_cast<__half2*>(y + (size_t)m * C_DIM);
    #pragma unroll
    for (int t = 0; t < 3; t++) {
        int p = lane + 32 * t;
        float4 xv = (t == 0) ? v0 : (t == 1) ? v1 : v2;
        float4 gv = gr[p], bv = br[p];
        yr[p * 2 + 0] = __floats2half2_rn((xv.x - mean) * rstd * gv.x + bv.x,
                                          (xv.y - mean) * rstd * gv.y + bv.y);
        yr[p * 2 + 1] = __floats2half2_rn((xv.z - mean) * rstd * gv.z + bv.z,
                                          (xv.w - mean) * rstd * gv.w + bv.w);
    }
}

// ---------------------------------------------------------------------------
// LayerNorm (fp16 in -> fp16 out)
// ---------------------------------------------------------------------------
__global__ __launch_bounds__(256) void ln16_kernel(const __half* __restrict__ x,
                                                   const float* __restrict__ g,
                                                   const float* __restrict__ b,
                                                   __half* __restrict__ y) {
    int warp = threadIdx.x >> 5, lane = threadIdx.x & 31;
    int m = blockIdx.x * 8 + warp;
    const uint2* xr = reinterpret_cast<const uint2*>(x + (size_t)m * C_DIM);
    uint2 u0 = xr[lane], u1 = xr[lane + 32], u2 = xr[lane + 64];

    float v[12];
    {
        const __half2* h0 = reinterpret_cast<const __half2*>(&u0);
        const __half2* h1 = reinterpret_cast<const __half2*>(&u1);
        const __half2* h2 = reinterpret_cast<const __half2*>(&u2);
        float2 f;
        f = __half22float2(h0[0]); v[0] = f.x; v[1] = f.y;
        f = __half22float2(h0[1]); v[2] = f.x; v[3] = f.y;
        f = __half22float2(h1[0]); v[4] = f.x; v[5] = f.y;
        f = __half22float2(h1[1]); v[6] = f.x; v[7] = f.y;
        f = __half22float2(h2[0]); v[8] = f.x; v[9] = f.y;
        f = __half22float2(h2[1]); v[10] = f.x; v[11] = f.y;
    }
    float s = 0.f, sq = 0.f;
    #pragma unroll
    for (int t = 0; t < 12; t++) { s += v[t]; sq += v[t] * v[t]; }
    #pragma unroll
    for (int o = 16; o; o >>= 1) {
        s  += __shfl_xor_sync(0xffffffffu, s,  o);
        sq += __shfl_xor_sync(0xffffffffu, sq, o);
    }
    float mean = s * (1.0f / 384.0f);
    float var  = sq * (1.0f / 384.0f) - mean * mean;
    float rstd = rsqrtf(var + 1e-5f);

    const float4* gr = reinterpret_cast<const float4*>(g);
    const float4* br = reinterpret_cast<const float4*>(b);
    __half2* yr = reinterpret_cast<__half2*>(y + (size_t)m * C_DIM);
    #pragma unroll
    for (int t = 0; t < 3; t++) {
        int p = lane + 32 * t;
        float4 gv = gr[p], bv = br[p];
        float w0 = (v[t*4+0] - mean) * rstd * gv.x + bv.x;
        float w1 = (v[t*4+1] - mean) * rstd * gv.y + bv.y;
        float w2 = (v[t*4+2] - mean) * rstd * gv.z + bv.z;
        float w3 = (v[t*4+3] - mean) * rstd * gv.w + bv.w;
        yr[p * 2 + 0] = __floats2half2_rn(w0, w1);
        yr[p * 2 + 1] = __floats2half2_rn(w2, w3);
    }
}

// ---------------------------------------------------------------------------
// HMMA windowed attention with register-resident softmax.
// S stays in mma accumulators; row max/sum via shfl + ONE smem (max,sum)
// exchange between the wn warp halves; P written once as fp16.
// ---------------------------------------------------------------------------
__global__ __launch_bounds__(256) void attn_kernel(const __half* __restrict__ qkv,
                                                   const float* __restrict__ table,
                                                   const int* __restrict__ relidx,
                                                   __half* __restrict__ o) {
    __shared__ __align__(16) __half qh[64 * 40], kh[64 * 40], vh[64 * 40];
    __shared__ __align__(16) __half ph[64 * 72];
    __shared__ float ex[64][2][2];      // [row][wn][{max,sum}]
    __shared__ float sbias[(2 * WS - 1) * (2 * WS - 1)];
    __shared__ int   sidx[NWIN];

    int head = blockIdx.x;
    int w    = blockIdx.y;
    int tid  = threadIdx.x, warp = tid >> 5, lane = tid & 31;

    int b  = w >> 6;
    int wr = w & 63;
    int wi = wr >> 3, wj = wr & 7;

    if (tid < NWIN) {
        int i = tid / 7, j = tid - 7 * (tid / 7);
        int rr = wi * 7 + i + SHIFT; if (rr >= HDIM) rr -= HDIM;
        int cc = wj * 7 + j + SHIFT; if (cc >= HDIM) cc -= HDIM;
        sidx[tid] = b * (HDIM * HDIM) + rr * HDIM + cc;
    }
    if (tid < 169) sbias[tid] = table[tid * NHEADS + head];
    // zero pad rows 49..63 of q/k/v (15 rows x 5 uint4 x 3 arrays = 225)
    if (tid < 225) {
        uint4 z = make_uint4(0, 0, 0, 0);
        int a = tid / 75;              // which array
        int t = tid % 75;
        int row = 49 + t / 5, c = t % 5;
        __half* dst = (a == 0) ? qh : (a == 1) ? kh : vh;
        *reinterpret_cast<uint4*>(&dst[row * 40 + c * 8]) = z;
    }
    __syncthreads();

    // gather Q,K,V rows (fp16, 4 x uint4 per row)
    for (int idx = tid; idx < NWIN * 4; idx += 256) {
        int r = idx >> 2, c = idx & 3;
        const uint4* base = reinterpret_cast<const uint4*>(
            qkv + (size_t)sidx[r] * (3 * C_DIM) + head * HEADD);
        *reinterpret_cast<uint4*>(&qh[r * 40 + c * 8]) = base[c];
        *reinterpret_cast<uint4*>(&kh[r * 40 + c * 8]) = base[c + C_DIM / 8];
        *reinterpret_cast<uint4*>(&vh[r * 40 + c * 8]) = base[c + 2 * C_DIM / 8];
    }
    __syncthreads();

    uint32_t qb = smem_u32(qh), kb = smem_u32(kh), vb_ = smem_u32(vh);
    uint32_t pb = smem_u32(ph);
    int wm = warp >> 1, wn = warp & 1;

    // ---- GEMM1: S = Q @ K^T  (each warp: 16x32 tile), stays in registers ----
    float acc1[4][4];
    #pragma unroll
    for (int t = 0; t < 4; t++)
        #pragma unroll
        for (int e = 0; e < 4; e++) acc1[t][e] = 0.0f;

    #pragma unroll
    for (int kf = 0; kf < 2; kf++) {
        uint32_t a[4], bfr[2][4];
        ldmx4(a[0], a[1], a[2], a[3],
              qb + (uint32_t)((wm * 16 + (lane & 15)) * 80
                              + (lane >> 4) * 16 + kf * 32));
        #pragma unroll
        for (int jp = 0; jp < 2; jp++) {
            int nrow = wn * 32 + jp * 16 + (lane & 7) + ((lane >> 4) << 3);
            ldmx4(bfr[jp][0], bfr[jp][1], bfr[jp][2], bfr[jp][3],
                  kb + (uint32_t)(nrow * 80 + ((lane >> 3) & 1) * 16 + kf * 32));
        }
        #pragma unroll
        for (int jp = 0; jp < 2; jp++) {
            mma16816(acc1[jp * 2 + 0], a, &bfr[jp][0]);
            mma16816(acc1[jp * 2 + 1], a, &bfr[jp][2]);
        }
    }

    // ---- register softmax ----
    const float scale = 0.17677669529663687f;
    int r0 = wm * 16 + (lane >> 2);
    float lm[2] = {-1e30f, -1e30f}, lsum[2];

    #pragma unroll
    for (int t = 0; t < 4; t++) {
        int cbase = wn * 32 + t * 8 + ((lane & 3) << 1);
        #pragma unroll
        for (int e = 0; e < 4; e++) {
            int hm = e >> 1;
            int c = cbase + (e & 1);
            int r = r0 + hm * 8;
            float v;
            if (c < NWIN) {
                int rr = (r < NWIN) ? r : 0;
                v = acc1[t][e] * scale + sbias[relidx[rr * NWIN + c]];
            } else v = -1e30f;
            acc1[t][e] = v;
            lm[hm] = fmaxf(lm[hm], v);
        }
    }
    #pragma unroll
    for (int off = 1; off <= 2; off <<= 1) {
        lm[0] = fmaxf(lm[0], __shfl_xor_sync(0xffffffffu, lm[0], off));
        lm[1] = fmaxf(lm[1], __shfl_xor_sync(0xffffffffu, lm[1], off));
    }
    lsum[0] = lsum[1] = 0.0f;
    #pragma unroll
    for (int t = 0; t < 4; t++)
        #pragma unroll
        for (int e = 0; e < 4; e++) {
            int hm = e >> 1;
            float p = __expf(acc1[t][e] - lm[hm]);
            acc1[t][e] = p;
            lsum[hm] += p;
        }
    #pragma unroll
    for (int off = 1; off <= 2; off <<= 1) {
        lsum[0] += __shfl_xor_sync(0xffffffffu, lsum[0], off);
        lsum[1] += __shfl_xor_sync(0xffffffffu, lsum[1], off);
    }
    // exchange (max,sum) between wn halves
    if ((lane & 3) == 0) {
        #pragma unroll
        for (int hm = 0; hm < 2; hm++) {
            int r = r0 + hm * 8;
            ex[r][wn][0] = lm[hm];
            ex[r][wn][1] = lsum[hm];
        }
    }
    __syncthreads();
    float fscale[2];
    #pragma unroll
    for (int hm = 0; hm < 2; hm++) {
        int r = r0 + hm * 8;
        float m0 = ex[r][0][0], s0 = ex[r][0][1];
        float m1 = ex[r][1][0], s1 = ex[r][1][1];
        float m = fmaxf(m0, m1);
        float stot = s0 * __expf(m0 - m) + s1 * __expf(m1 - m);
        fscale[hm] = __expf(lm[hm] - m) / stot;
    }
    // write P fp16 (covers the full 64x64, no zero-fill needed)
    #pragma unroll
    for (int t = 0; t < 4; t++) {
        int cbase = wn * 32 + t * 8 + ((lane & 3) << 1);
        #pragma unroll
        for (int hm = 0; hm < 2; hm++) {
            int r = r0 + hm * 8;
            __half2 hp = __floats2half2_rn(acc1[t][hm * 2] * fscale[hm],
                                           acc1[t][hm * 2 + 1] * fscale[hm]);
            *reinterpret_cast<__half2*>(&ph[r * 72 + cbase]) = hp;
        }
    }
    __syncthreads();

    // ---- GEMM2: O = P @ V  (each warp: 16 rows x 16 headdim cols) ----
    {
        float acc2[2][4];
        #pragma unroll
        for (int t = 0; t < 2; t++)
            #pragma unroll
            for (int e = 0; e < 4; e++) acc2[t][e] = 0.0f;

        #pragma unroll
        for (int kf = 0; kf < 4; kf++) {
            uint32_t a2[4], vfr[4];
            ldmx4(a2[0], a2[1], a2[2], a2[3],
                  pb + (uint32_t)((wm * 16 + (lane & 15)) * 144
                                  + (lane >> 4) * 16 + kf * 32));
            {
                int krow = kf * 16 + (lane & 7) + (((lane >> 3) & 1) << 3);
                int ncol = (lane >> 4) * 8 + wn * 16;
                ldmx4t(vfr[0], vfr[1], vfr[2], vfr[3],
                       vb_ + (uint32_t)(krow * 80 + ncol * 2));
            }
            mma16816(acc2[0], a2, &vfr[0]);
            mma16816(acc2[1], a2, &vfr[2]);
        }
        #pragma unroll
        for (int t = 0; t < 2; t++) {
            int col = wn * 16 + t * 8 + ((lane & 3) << 1);
            #pragma unroll
            for (int hm = 0; hm < 2; hm++) {
                int row = wm * 16 + (lane >> 2) + hm * 8;
                if (row < NWIN) {
                    __half2 hv = __floats2half2_rn(acc2[t][hm * 2],
                                                   acc2[t][hm * 2 + 1]);
                    *reinterpret_cast<__half2*>(
                        o + (size_t)sidx[row] * C_DIM + head * HEADD + col) = hv;
                }
            }
        }
    }
}

// ---------------------------------------------------------------------------
extern "C" void kernel_launch(void* const* d_in, const int* in_sizes, int n_in,
                              void* d_out, int out_size) {
    const float* x      = (const float*)d_in[0];
    const float* n1g    = (const float*)d_in[1];
    const float* n1b    = (const float*)d_in[2];
    const float* qkvw   = (const float*)d_in[3];
    const float* qkvb   = (const float*)d_in[4];
    const float* projw  = (const float*)d_in[5];
    const float* projb  = (const float*)d_in[6];
    const float* table  = (const float*)d_in[7];
    const float* n2g    = (const float*)d_in[8];
    const float* n2b    = (const float*)d_in[9];
    const float* fc1w   = (const float*)d_in[10];
    const float* fc1b   = (const float*)d_in[11];
    const float* fc2w   = (const float*)d_in[12];
    const float* fc2b   = (const float*)d_in[13];
    const int*   relidx = (const int*)d_in[14];
    float* out = (float*)d_out;

    __half *ln, *qkv, *o, *h, *a1, *btq, *btp, *bt1, *bt2;
    cudaGetSymbolAddress((void**)&ln,  g_ln);
    cudaGetSymbolAddress((void**)&qkv, g_qkv);
    cudaGetSymbolAddress((void**)&o,   g_o);
    cudaGetSymbolAddress((void**)&h,   g_h);
    cudaGetSymbolAddress((void**)&a1,  g_a1);
    cudaGetSymbolAddress((void**)&btq, g_bt_qkv);
    cudaGetSymbolAddress((void**)&btp, g_bt_proj);
    cudaGetSymbolAddress((void**)&bt1, g_bt_fc1);
    cudaGetSymbolAddress((void**)&bt2, g_bt_fc2);

    cudaFuncSetAttribute(gemm_hmma<0>, cudaFuncAttributeMaxDynamicSharedMemorySize, SMEM_BYTES);
    cudaFuncSetAttribute(gemm_hmma<1>, cudaFuncAttributeMaxDynamicSharedMemorySize, SMEM_BYTES);
    cudaFuncSetAttribute(gemm_hmma<2>, cudaFuncAttributeMaxDynamicSharedMemorySize, SMEM_BYTES);
    cudaFuncSetAttribute(gemm_hmma<3>, cudaFuncAttributeMaxDynamicSharedMemorySize, SMEM_BYTES);

    // 0) all weight preps in one launch
    prep_all<<<1728, 256>>>(qkvw, projw, fc1w, fc2w, btq, btp, bt1, bt2);
    // 1) LN1: x (fp32) -> ln (fp16)
    ln_kernel<<<M_TOK / 8, 256>>>(x, n1g, n1b, ln);
    // 2) qkv = ln @ qkv_w + b   (fp16 out)
    gemm_hmma<0><<<dim3(3 * C_DIM / 128, M_TOK / 128), 128, SMEM_BYTES>>>(
        ln, btq, qkvb, nullptr, qkv, M_TOK, 3 * C_DIM, C_DIM);
    // 3) HMMA attention (shift folded into indices), fp16 out
    attn_kernel<<<dim3(NHEADS, 2048), 256>>>(qkv, table, relidx, o);
    // 4) h = x + proj(o)   (fp16 out, fp32 residual)
    gemm_hmma<1><<<dim3(C_DIM / 128, M_TOK / 128), 128, SMEM_BYTES>>>(
        o, btp, projb, x, h, M_TOK, C_DIM, C_DIM);
    // 5) LN2: h (fp16) -> ln (fp16)
    ln16_kernel<<<M_TOK / 8, 256>>>(h, n2g, n2b, ln);
    // 6) a1 = gelu(fc1(ln))  (fp16 out)
    gemm_hmma<2><<<dim3(MLP_HID / 128, M_TOK / 128), 128, SMEM_BYTES>>>(
        ln, bt1, fc1b, nullptr, a1, M_TOK, MLP_HID, C_DIM);
    // 7) out = h + fc2(a1)   (fp32 out, fp16 residual)
    gemm_hmma<3><<<dim3(C_DIM / 128, M_TOK / 128), 128, SMEM_BYTES>>>(
        a1, bt2, fc2b, h, out, M_TOK, C_DIM, MLP_HID);
}

// round 15
// speedup vs baseline: 1.4431x; 1.0008x over previous
#include <cuda_runtime.h>
#include <cuda_fp16.h>
#include <math.h>
#include <stdint.h>

// Problem constants
constexpr int BATCH   = 32;
constexpr int HDIM    = 56;
constexpr int C_DIM   = 384;
constexpr int NHEADS  = 12;
constexpr int HEADD   = 32;
constexpr int WS      = 7;
constexpr int SHIFT   = 3;
constexpr int NWIN    = 49;
constexpr int M_TOK   = BATCH * HDIM * HDIM;   // 100352
constexpr int MLP_HID = 4 * C_DIM;             // 1536

constexpr int NSTAGE     = 3;
constexpr int STAGE_B    = 32768;              // A 16KB + B 16KB (fp16, k64)
constexpr int SMEM_BYTES = NSTAGE * STAGE_B;   // 96KB per CTA

// Scratch buffers (device globals: no allocation allowed)
__device__ __align__(256) __half g_ln [(size_t)M_TOK * C_DIM];
__device__ __align__(256) __half g_qkv[(size_t)M_TOK * 3 * C_DIM];
__device__ __align__(256) __half g_o  [(size_t)M_TOK * C_DIM];
__device__ __align__(256) __half g_h  [(size_t)M_TOK * C_DIM];   // fp16 residual
__device__ __align__(256) __half g_a1 [(size_t)M_TOK * MLP_HID];
// fp16 transposed weights [N][K]
__device__ __align__(256) __half g_bt_qkv [(size_t)3 * C_DIM * C_DIM];
__device__ __align__(256) __half g_bt_proj[(size_t)C_DIM * C_DIM];
__device__ __align__(256) __half g_bt_fc1 [(size_t)MLP_HID * C_DIM];
__device__ __align__(256) __half g_bt_fc2 [(size_t)C_DIM * MLP_HID];

// ---------------------------------------------------------------------------
// asm helpers (base-arch only: cp.async sm80, ldmatrix sm75, mma.sync sm80)
// ---------------------------------------------------------------------------
__device__ __forceinline__ uint32_t smem_u32(const void* p) {
    uint32_t a;
    asm("{ .reg .u64 t; cvta.to.shared.u64 t, %1; cvt.u32.u64 %0, t; }"
        : "=r"(a) : "l"(p));
    return a;
}
__device__ __forceinline__ void cp16(uint32_t dst, const void* src) {
    asm volatile("cp.async.cg.shared.global [%0], [%1], 16;"
                 :: "r"(dst), "l"(src) : "memory");
}
__device__ __forceinline__ void cp_commit() {
    asm volatile("cp.async.commit_group;" ::: "memory");
}
template <int N>
__device__ __forceinline__ void cp_wait() {
    asm volatile("cp.async.wait_group %0;" :: "n"(N) : "memory");
}
__device__ __forceinline__ void ldmx4(uint32_t& r0, uint32_t& r1,
                                      uint32_t& r2, uint32_t& r3, uint32_t addr) {
    asm volatile("ldmatrix.sync.aligned.m8n8.x4.shared.b16 {%0,%1,%2,%3}, [%4];"
                 : "=r"(r0), "=r"(r1), "=r"(r2), "=r"(r3) : "r"(addr));
}
__device__ __forceinline__ void ldmx4t(uint32_t& r0, uint32_t& r1,
                                       uint32_t& r2, uint32_t& r3, uint32_t addr) {
    asm volatile("ldmatrix.sync.aligned.m8n8.x4.trans.shared.b16 {%0,%1,%2,%3}, [%4];"
                 : "=r"(r0), "=r"(r1), "=r"(r2), "=r"(r3) : "r"(addr));
}
__device__ __forceinline__ void mma16816(float* c, const uint32_t* a,
                                         const uint32_t* b) {
    asm volatile(
        "mma.sync.aligned.m16n8k16.row.col.f32.f16.f16.f32 "
        "{%0,%1,%2,%3}, {%4,%5,%6,%7}, {%8,%9}, {%0,%1,%2,%3};"
        : "+f"(c[0]), "+f"(c[1]), "+f"(c[2]), "+f"(c[3])
        : "r"(a[0]), "r"(a[1]), "r"(a[2]), "r"(a[3]), "r"(b[0]), "r"(b[1]));
}
// smem tile: [128 rows][64 fp16] = 128B rows (8x16B chunks), XOR-8 swizzle
__device__ __forceinline__ uint32_t sa_off(int row, int c4) {
    return (uint32_t)(row * 128 + ((c4 ^ (row & 7)) << 4));
}
__device__ __forceinline__ float gelu(float v) {
    return 0.5f * v * (1.0f + erff(v * 0.70710678118654752f));
}

// ---------------------------------------------------------------------------
// Weight prep, all 4 matrices in ONE launch (linearized 32x32 tile grid)
// ---------------------------------------------------------------------------
__global__ __launch_bounds__(256) void prep_all(
    const float* __restrict__ qkvw, const float* __restrict__ projw,
    const float* __restrict__ fc1w, const float* __restrict__ fc2w,
    __half* __restrict__ btq, __half* __restrict__ btp,
    __half* __restrict__ bt1, __half* __restrict__ bt2) {
    __shared__ float t[32][33];
    int bx = blockIdx.x;
    const float* W; __half* Wt; int K, N;
    if (bx < 432)       { W = qkvw;  Wt = btq; K = 384;  N = 1152; }
    else if (bx < 576)  { W = projw; Wt = btp; K = 384;  N = 384;  bx -= 432; }
    else if (bx < 1152) { W = fc1w;  Wt = bt1; K = 384;  N = 1536; bx -= 576; }
    else                { W = fc2w;  Wt = bt2; K = 1536; N = 384;  bx -= 1152; }
    int ntx = N >> 5;
    int n0 = (bx % ntx) << 5, k0 = (bx / ntx) << 5;
    int tx = threadIdx.x & 31, ty = threadIdx.x >> 5;
    #pragma unroll
    for (int i = 0; i < 32; i += 8)
        t[ty + i][tx] = W[(size_t)(k0 + ty + i) * N + n0 + tx];
    __syncthreads();
    #pragma unroll
    for (int i = 0; i < 32; i += 8)
        Wt[(size_t)(n0 + ty + i) * K + k0 + tx] = __float2half_rn(t[tx][ty + i]);
}

// ---------------------------------------------------------------------------
// fp16 HMMA GEMM (f32 accumulate) — unchanged
// EPI: 0 = +bias->half ; 1 = +bias+fp32res->half ; 2 = gelu->half ;
//      3 = +bias+fp16res->float
// ---------------------------------------------------------------------------
template <int EPI>
__global__ __launch_bounds__(128, 2)
void gemm_hmma(const __half* __restrict__ A, const __half* __restrict__ Bt,
               const float* __restrict__ bias, const void* __restrict__ R,
               void* __restrict__ out, int M, int N, int K) {
    extern __shared__ __align__(128) char smem[];
    uint32_t sbase = smem_u32(smem);

    int tid = threadIdx.x, warp = tid >> 5, lane = tid & 31;
    int wm = warp >> 1, wn = warp & 1;
    int m0 = blockIdx.y * 128, n0 = blockIdx.x * 128;
    int NC = K >> 6;

    float acc[4][8][4];
    #pragma unroll
    for (int i = 0; i < 4; i++)
        #pragma unroll
        for (int j = 0; j < 8; j++)
            #pragma unroll
            for (int e = 0; e < 4; e++) acc[i][j][e] = 0.0f;

    auto load_chunk = [&](int kc, int s) {
        uint32_t ast = sbase + s * STAGE_B;
        uint32_t bst = ast + 16384;
        #pragma unroll
        for (int t = 0; t < 8; t++) {
            int seg = tid + t * 128;
            int row = seg >> 3, q = seg & 7;
            cp16(ast + sa_off(row, q),
                 A + (size_t)(m0 + row) * K + kc * 64 + q * 8);
            cp16(bst + sa_off(row, q),
                 Bt + (size_t)(n0 + row) * K + kc * 64 + q * 8);
        }
    };

    #pragma unroll
    for (int c = 0; c < NSTAGE - 1; c++) { load_chunk(c, c); cp_commit(); }

    int s_cur = 0, s_nxt = NSTAGE - 1;
    for (int c = 0; c < NC; c++) {
        cp_wait<NSTAGE - 2>();
        __syncthreads();
        int cn = c + NSTAGE - 1;
        if (cn < NC) load_chunk(cn, s_nxt);
        cp_commit();
        if (++s_nxt == NSTAGE) s_nxt = 0;

        uint32_t ast = sbase + s_cur * STAGE_B;
        uint32_t bst = ast + 16384;
        if (++s_cur == NSTAGE) s_cur = 0;

        #pragma unroll
        for (int kk = 0; kk < 4; kk++) {
            uint32_t a[4][4], b[4][4];
            #pragma unroll
            for (int i = 0; i < 4; i++) {
                int row = wm * 64 + i * 16 + (lane & 15);
                int c4  = kk * 2 + (lane >> 4);
                ldmx4(a[i][0], a[i][1], a[i][2], a[i][3], ast + sa_off(row, c4));
            }
            #pragma unroll
            for (int jp = 0; jp < 4; jp++) {
                int row = wn * 64 + jp * 16 + (lane & 7) + ((lane >> 4) << 3);
                int c4  = kk * 2 + ((lane >> 3) & 1);
                ldmx4(b[jp][0], b[jp][1], b[jp][2], b[jp][3], bst + sa_off(row, c4));
            }
            #pragma unroll
            for (int i = 0; i < 4; i++)
                #pragma unroll
                for (int jp = 0; jp < 4; jp++) {
                    mma16816(acc[i][jp * 2 + 0], a[i], &b[jp][0]);
                    mma16816(acc[i][jp * 2 + 1], a[i], &b[jp][2]);
                }
        }
    }

    int rbase = m0 + wm * 64 + (lane >> 2);
    #pragma unroll
    for (int i = 0; i < 4; i++) {
        #pragma unroll
        for (int j = 0; j < 8; j++) {
            int col = n0 + wn * 64 + j * 8 + ((lane & 3) << 1);
            float b0 = bias[col], b1 = bias[col + 1];
            #pragma unroll
            for (int hm = 0; hm < 2; hm++) {
                int row = rbase + i * 16 + hm * 8;
                float v0 = acc[i][j][hm * 2 + 0] + b0;
                float v1 = acc[i][j][hm * 2 + 1] + b1;
                if (EPI == 1) {
                    const float2 r2 = *reinterpret_cast<const float2*>(
                        (const float*)R + (size_t)row * N + col);
                    v0 += r2.x; v1 += r2.y;
                    *reinterpret_cast<__half2*>((__half*)out + (size_t)row * N + col)
                        = __floats2half2_rn(v0, v1);
                } else if (EPI == 3) {
                    const __half2 rh = *reinterpret_cast<const __half2*>(
                        (const __half*)R + (size_t)row * N + col);
                    float2 rf = __half22float2(rh);
                    v0 += rf.x; v1 += rf.y;
                    *reinterpret_cast<float2*>((float*)out + (size_t)row * N + col)
                        = make_float2(v0, v1);
                } else {
                    if (EPI == 2) { v0 = gelu(v0); v1 = gelu(v1); }
                    *reinterpret_cast<__half2*>((__half*)out + (size_t)row * N + col)
                        = __floats2half2_rn(v0, v1);
                }
            }
        }
    }
}

// ---------------------------------------------------------------------------
// LayerNorm (fp32 in -> fp16 out)
// ---------------------------------------------------------------------------
__global__ __launch_bounds__(256) void ln_kernel(const float* __restrict__ x,
                                                 const float* __restrict__ g,
                                                 const float* __restrict__ b,
                                                 __half* __restrict__ y) {
    int warp = threadIdx.x >> 5, lane = threadIdx.x & 31;
    int m = blockIdx.x * 8 + warp;
    const float4* xr = reinterpret_cast<const float4*>(x + (size_t)m * C_DIM);
    float4 v0 = xr[lane], v1 = xr[lane + 32], v2 = xr[lane + 64];

    float s  = v0.x + v0.y + v0.z + v0.w + v1.x + v1.y + v1.z + v1.w
             + v2.x + v2.y + v2.z + v2.w;
    float sq = v0.x*v0.x + v0.y*v0.y + v0.z*v0.z + v0.w*v0.w
             + v1.x*v1.x + v1.y*v1.y + v1.z*v1.z + v1.w*v1.w
             + v2.x*v2.x + v2.y*v2.y + v2.z*v2.z + v2.w*v2.w;
    #pragma unroll
    for (int o = 16; o; o >>= 1) {
        s  += __shfl_xor_sync(0xffffffffu, s,  o);
        sq += __shfl_xor_sync(0xffffffffu, sq, o);
    }
    float mean = s * (1.0f / 384.0f);
    float var  = sq * (1.0f / 384.0f) - mean * mean;
    float rstd = rsqrtf(var + 1e-5f);

    const float4* gr = reinterpret_cast<const float4*>(g);
    const float4* br = reinterpret_cast<const float4*>(b);
    __half2* yr = reinterpret_cast<__half2*>(y + (size_t)m * C_DIM);
    #pragma unroll
    for (int t = 0; t < 3; t++) {
        int p = lane + 32 * t;
        float4 xv = (t == 0) ? v0 : (t == 1) ? v1 : v2;
        float4 gv = gr[p], bv = br[p];
        yr[p * 2 + 0] = __floats2half2_rn((xv.x - mean) * rstd * gv.x + bv.x,
                                          (xv.y - mean) * rstd * gv.y + bv.y);
        yr[p * 2 + 1] = __floats2half2_rn((xv.z - mean) * rstd * gv.z + bv.z,
                                          (xv.w - mean) * rstd * gv.w + bv.w);
    }
}

// ---------------------------------------------------------------------------
// LayerNorm (fp16 in -> fp16 out)
// ---------------------------------------------------------------------------
__global__ __launch_bounds__(256) void ln16_kernel(const __half* __restrict__ x,
                                                   const float* __restrict__ g,
                                                   const float* __restrict__ b,
                                                   __half* __restrict__ y) {
    int warp = threadIdx.x >> 5, lane = threadIdx.x & 31;
    int m = blockIdx.x * 8 + warp;
    const uint2* xr = reinterpret_cast<const uint2*>(x + (size_t)m * C_DIM);
    uint2 u0 = xr[lane], u1 = xr[lane + 32], u2 = xr[lane + 64];

    float v[12];
    {
        const __half2* h0 = reinterpret_cast<const __half2*>(&u0);
        const __half2* h1 = reinterpret_cast<const __half2*>(&u1);
        const __half2* h2 = reinterpret_cast<const __half2*>(&u2);
        float2 f;
        f = __half22float2(h0[0]); v[0] = f.x; v[1] = f.y;
        f = __half22float2(h0[1]); v[2] = f.x; v[3] = f.y;
        f = __half22float2(h1[0]); v[4] = f.x; v[5] = f.y;
        f = __half22float2(h1[1]); v[6] = f.x; v[7] = f.y;
        f = __half22float2(h2[0]); v[8] = f.x; v[9] = f.y;
        f = __half22float2(h2[1]); v[10] = f.x; v[11] = f.y;
    }
    float s = 0.f, sq = 0.f;
    #pragma unroll
    for (int t = 0; t < 12; t++) { s += v[t]; sq += v[t] * v[t]; }
    #pragma unroll
    for (int o = 16; o; o >>= 1) {
        s  += __shfl_xor_sync(0xffffffffu, s,  o);
        sq += __shfl_xor_sync(0xffffffffu, sq, o);
    }
    float mean = s * (1.0f / 384.0f);
    float var  = sq * (1.0f / 384.0f) - mean * mean;
    float rstd = rsqrtf(var + 1e-5f);

    const float4* gr = reinterpret_cast<const float4*>(g);
    const float4* br = reinterpret_cast<const float4*>(b);
    __half2* yr = reinterpret_cast<__half2*>(y + (size_t)m * C_DIM);
    #pragma unroll
    for (int t = 0; t < 3; t++) {
        int p = lane + 32 * t;
        float4 gv = gr[p], bv = br[p];
        float w0 = (v[t*4+0] - mean) * rstd * gv.x + bv.x;
        float w1 = (v[t*4+1] - mean) * rstd * gv.y + bv.y;
        float w2 = (v[t*4+2] - mean) * rstd * gv.z + bv.z;
        float w3 = (v[t*4+3] - mean) * rstd * gv.w + bv.w;
        yr[p * 2 + 0] = __floats2half2_rn(w0, w1);
        yr[p * 2 + 1] = __floats2half2_rn(w2, w3);
    }
}

// ---------------------------------------------------------------------------
// HMMA windowed attention with register-resident softmax.
// S stays in mma accumulators; row max/sum via shfl + ONE smem (max,sum)
// exchange between the wn warp halves; P written once as fp16.
// ---------------------------------------------------------------------------
__global__ __launch_bounds__(256) void attn_kernel(const __half* __restrict__ qkv,
                                                   const float* __restrict__ table,
                                                   const int* __restrict__ relidx,
                                                   __half* __restrict__ o) {
    __shared__ __align__(16) __half qh[64 * 40], kh[64 * 40], vh[64 * 40];
    __shared__ __align__(16) __half ph[64 * 72];
    __shared__ float ex[64][2][2];      // [row][wn][{max,sum}]
    __shared__ float sbias[(2 * WS - 1) * (2 * WS - 1)];
    __shared__ int   sidx[NWIN];

    int head = blockIdx.x;
    int w    = blockIdx.y;
    int tid  = threadIdx.x, warp = tid >> 5, lane = tid & 31;

    int b  = w >> 6;
    int wr = w & 63;
    int wi = wr >> 3, wj = wr & 7;

    if (tid < NWIN) {
        int i = tid / 7, j = tid - 7 * (tid / 7);
        int rr = wi * 7 + i + SHIFT; if (rr >= HDIM) rr -= HDIM;
        int cc = wj * 7 + j + SHIFT; if (cc >= HDIM) cc -= HDIM;
        sidx[tid] = b * (HDIM * HDIM) + rr * HDIM + cc;
    }
    if (tid < 169) sbias[tid] = table[tid * NHEADS + head];
    // zero pad rows 49..63 of q/k/v (15 rows x 5 uint4 x 3 arrays = 225)
    if (tid < 225) {
        uint4 z = make_uint4(0, 0, 0, 0);
        int a = tid / 75;              // which array
        int t = tid % 75;
        int row = 49 + t / 5, c = t % 5;
        __half* dst = (a == 0) ? qh : (a == 1) ? kh : vh;
        *reinterpret_cast<uint4*>(&dst[row * 40 + c * 8]) = z;
    }
    __syncthreads();

    // gather Q,K,V rows (fp16, 4 x uint4 per row)
    for (int idx = tid; idx < NWIN * 4; idx += 256) {
        int r = idx >> 2, c = idx & 3;
        const uint4* base = reinterpret_cast<const uint4*>(
            qkv + (size_t)sidx[r] * (3 * C_DIM) + head * HEADD);
        *reinterpret_cast<uint4*>(&qh[r * 40 + c * 8]) = base[c];
        *reinterpret_cast<uint4*>(&kh[r * 40 + c * 8]) = base[c + C_DIM / 8];
        *reinterpret_cast<uint4*>(&vh[r * 40 + c * 8]) = base[c + 2 * C_DIM / 8];
    }
    __syncthreads();

    uint32_t qb = smem_u32(qh), kb = smem_u32(kh), vb_ = smem_u32(vh);
    uint32_t pb = smem_u32(ph);
    int wm = warp >> 1, wn = warp & 1;

    // ---- GEMM1: S = Q @ K^T  (each warp: 16x32 tile), stays in registers ----
    float acc1[4][4];
    #pragma unroll
    for (int t = 0; t < 4; t++)
        #pragma unroll
        for (int e = 0; e < 4; e++) acc1[t][e] = 0.0f;

    #pragma unroll
    for (int kf = 0; kf < 2; kf++) {
        uint32_t a[4], bfr[2][4];
        ldmx4(a[0], a[1], a[2], a[3],
              qb + (uint32_t)((wm * 16 + (lane & 15)) * 80
                              + (lane >> 4) * 16 + kf * 32));
        #pragma unroll
        for (int jp = 0; jp < 2; jp++) {
            int nrow = wn * 32 + jp * 16 + (lane & 7) + ((lane >> 4) << 3);
            ldmx4(bfr[jp][0], bfr[jp][1], bfr[jp][2], bfr[jp][3],
                  kb + (uint32_t)(nrow * 80 + ((lane >> 3) & 1) * 16 + kf * 32));
        }
        #pragma unroll
        for (int jp = 0; jp < 2; jp++) {
            mma16816(acc1[jp * 2 + 0], a, &bfr[jp][0]);
            mma16816(acc1[jp * 2 + 1], a, &bfr[jp][2]);
        }
    }

    // ---- register softmax ----
    const float scale = 0.17677669529663687f;
    int r0 = wm * 16 + (lane >> 2);
    float lm[2] = {-1e30f, -1e30f}, lsum[2];

    #pragma unroll
    for (int t = 0; t < 4; t++) {
        int cbase = wn * 32 + t * 8 + ((lane & 3) << 1);
        #pragma unroll
        for (int e = 0; e < 4; e++) {
            int hm = e >> 1;
            int c = cbase + (e & 1);
            int r = r0 + hm * 8;
            float v;
            if (c < NWIN) {
                int rr = (r < NWIN) ? r : 0;
                v = acc1[t][e] * scale + sbias[relidx[rr * NWIN + c]];
            } else v = -1e30f;
            acc1[t][e] = v;
            lm[hm] = fmaxf(lm[hm], v);
        }
    }
    #pragma unroll
    for (int off = 1; off <= 2; off <<= 1) {
        lm[0] = fmaxf(lm[0], __shfl_xor_sync(0xffffffffu, lm[0], off));
        lm[1] = fmaxf(lm[1], __shfl_xor_sync(0xffffffffu, lm[1], off));
    }
    lsum[0] = lsum[1] = 0.0f;
    #pragma unroll
    for (int t = 0; t < 4; t++)
        #pragma unroll
        for (int e = 0; e < 4; e++) {
            int hm = e >> 1;
            float p = __expf(acc1[t][e] - lm[hm]);
            acc1[t][e] = p;
            lsum[hm] += p;
        }
    #pragma unroll
    for (int off = 1; off <= 2; off <<= 1) {
        lsum[0] += __shfl_xor_sync(0xffffffffu, lsum[0], off);
        lsum[1] += __shfl_xor_sync(0xffffffffu, lsum[1], off);
    }
    // exchange (max,sum) between wn halves
    if ((lane & 3) == 0) {
        #pragma unroll
        for (int hm = 0; hm < 2; hm++) {
            int r = r0 + hm * 8;
            ex[r][wn][0] = lm[hm];
            ex[r][wn][1] = lsum[hm];
        }
    }
    __syncthreads();
    float fscale[2];
    #pragma unroll
    for (int hm = 0; hm < 2; hm++) {
        int r = r0 + hm * 8;
        float m0 = ex[r][0][0], s0 = ex[r][0][1];
        float m1 = ex[r][1][0], s1 = ex[r][1][1];
        float m = fmaxf(m0, m1);
        float stot = s0 * __expf(m0 - m) + s1 * __expf(m1 - m);
        fscale[hm] = __expf(lm[hm] - m) / stot;
    }
    // write P fp16 (covers the full 64x64, no zero-fill needed)
    #pragma unroll
    for (int t = 0; t < 4; t++) {
        int cbase = wn * 32 + t * 8 + ((lane & 3) << 1);
        #pragma unroll
        for (int hm = 0; hm < 2; hm++) {
            int r = r0 + hm * 8;
            __half2 hp = __floats2half2_rn(acc1[t][hm * 2] * fscale[hm],
                                           acc1[t][hm * 2 + 1] * fscale[hm]);
            *reinterpret_cast<__half2*>(&ph[r * 72 + cbase]) = hp;
        }
    }
    __syncthreads();

    // ---- GEMM2: O = P @ V  (each warp: 16 rows x 16 headdim cols) ----
    {
        float acc2[2][4];
        #pragma unroll
        for (int t = 0; t < 2; t++)
            #pragma unroll
            for (int e = 0; e < 4; e++) acc2[t][e] = 0.0f;

        #pragma unroll
        for (int kf = 0; kf < 4; kf++) {
            uint32_t a2[4], vfr[4];
            ldmx4(a2[0], a2[1], a2[2], a2[3],
                  pb + (uint32_t)((wm * 16 + (lane & 15)) * 144
                                  + (lane >> 4) * 16 + kf * 32));
            {
                int krow = kf * 16 + (lane & 7) + (((lane >> 3) & 1) << 3);
                int ncol = (lane >> 4) * 8 + wn * 16;
                ldmx4t(vfr[0], vfr[1], vfr[2], vfr[3],
                       vb_ + (uint32_t)(krow * 80 + ncol * 2));
            }
            mma16816(acc2[0], a2, &vfr[0]);
            mma16816(acc2[1], a2, &vfr[2]);
        }
        #pragma unroll
        for (int t = 0; t < 2; t++) {
            int col = wn * 16 + t * 8 + ((lane & 3) << 1);
            #pragma unroll
            for (int hm = 0; hm < 2; hm++) {
                int row = wm * 16 + (lane >> 2) + hm * 8;
                if (row < NWIN) {
                    __half2 hv = __floats2half2_rn(acc2[t][hm * 2],
                                                   acc2[t][hm * 2 + 1]);
                    *reinterpret_cast<__half2*>(
                        o + (size_t)sidx[row] * C_DIM + head * HEADD + col) = hv;
                }
            }
        }
    }
}

// ---------------------------------------------------------------------------
extern "C" void kernel_launch(void* const* d_in, const int* in_sizes, int n_in,
                              void* d_out, int out_size) {
    const float* x      = (const float*)d_in[0];
    const float* n1g    = (const float*)d_in[1];
    const float* n1b    = (const float*)d_in[2];
    const float* qkvw   = (const float*)d_in[3];
    const float* qkvb   = (const float*)d_in[4];
    const float* projw  = (const float*)d_in[5];
    const float* projb  = (const float*)d_in[6];
    const float* table  = (const float*)d_in[7];
    const float* n2g    = (const float*)d_in[8];
    const float* n2b    = (const float*)d_in[9];
    const float* fc1w   = (const float*)d_in[10];
    const float* fc1b   = (const float*)d_in[11];
    const float* fc2w   = (const float*)d_in[12];
    const float* fc2b   = (const float*)d_in[13];
    const int*   relidx = (const int*)d_in[14];
    float* out = (float*)d_out;

    __half *ln, *qkv, *o, *h, *a1, *btq, *btp, *bt1, *bt2;
    cudaGetSymbolAddress((void**)&ln,  g_ln);
    cudaGetSymbolAddress((void**)&qkv, g_qkv);
    cudaGetSymbolAddress((void**)&o,   g_o);
    cudaGetSymbolAddress((void**)&h,   g_h);
    cudaGetSymbolAddress((void**)&a1,  g_a1);
    cudaGetSymbolAddress((void**)&btq, g_bt_qkv);
    cudaGetSymbolAddress((void**)&btp, g_bt_proj);
    cudaGetSymbolAddress((void**)&bt1, g_bt_fc1);
    cudaGetSymbolAddress((void**)&bt2, g_bt_fc2);

    cudaFuncSetAttribute(gemm_hmma<0>, cudaFuncAttributeMaxDynamicSharedMemorySize, SMEM_BYTES);
    cudaFuncSetAttribute(gemm_hmma<1>, cudaFuncAttributeMaxDynamicSharedMemorySize, SMEM_BYTES);
    cudaFuncSetAttribute(gemm_hmma<2>, cudaFuncAttributeMaxDynamicSharedMemorySize, SMEM_BYTES);
    cudaFuncSetAttribute(gemm_hmma<3>, cudaFuncAttributeMaxDynamicSharedMemorySize, SMEM_BYTES);

    // 0) all weight preps in one launch
    prep_all<<<1728, 256>>>(qkvw, projw, fc1w, fc2w, btq, btp, bt1, bt2);
    // 1) LN1: x (fp32) -> ln (fp16)
    ln_kernel<<<M_TOK / 8, 256>>>(x, n1g, n1b, ln);
    // 2) qkv = ln @ qkv_w + b   (fp16 out)
    gemm_hmma<0><<<dim3(3 * C_DIM / 128, M_TOK / 128), 128, SMEM_BYTES>>>(
        ln, btq, qkvb, nullptr, qkv, M_TOK, 3 * C_DIM, C_DIM);
    // 3) HMMA attention (shift folded into indices), fp16 out
    attn_kernel<<<dim3(NHEADS, 2048), 256>>>(qkv, table, relidx, o);
    // 4) h = x + proj(o)   (fp16 out, fp32 residual)
    gemm_hmma<1><<<dim3(C_DIM / 128, M_TOK / 128), 128, SMEM_BYTES>>>(
        o, btp, projb, x, h, M_TOK, C_DIM, C_DIM);
    // 5) LN2: h (fp16) -> ln (fp16)
    ln16_kernel<<<M_TOK / 8, 256>>>(h, n2g, n2b, ln);
    // 6) a1 = gelu(fc1(ln))  (fp16 out)
    gemm_hmma<2><<<dim3(MLP_HID / 128, M_TOK / 128), 128, SMEM_BYTES>>>(
        ln, bt1, fc1b, nullptr, a1, M_TOK, MLP_HID, C_DIM);
    // 7) out = h + fc2(a1)   (fp32 out, fp16 residual)
    gemm_hmma<3><<<dim3(C_DIM / 128, M_TOK / 128), 128, SMEM_BYTES>>>(
        a1, bt2, fc2b, h, out, M_TOK, C_DIM, MLP_HID);
}